// round 5
// baseline (speedup 1.0000x reference)
#include <cuda_runtime.h>
#include <cuda_bf16.h>
#include <math.h>
#include <cstdint>

// ---------------- problem constants ----------------
#define Bb 2
#define Tt 2048
#define Dd 2560
#define Hh 8
#define Gg 4
#define HD 256
#define NQ (Hh*HD)     // 2048
#define NKV (Gg*HD)    // 1024
#define MROWS (Bb*Tt)  // 4096
#define QK_SCALE 0.0625f
#define WINDOW 1024

// ---------------- scratch (static device globals; no allocation) -----------
__device__ float g_q[(size_t)MROWS * NQ];
__device__ float g_k[(size_t)MROWS * NKV];
__device__ float g_v[(size_t)MROWS * NKV];
__device__ float g_ao[(size_t)MROWS * NQ];

// split-precision bf16 operands (16B-aligned for cp.async)
__device__ __align__(256) __nv_bfloat16 g_xhi[(size_t)MROWS * Dd];
__device__ __align__(256) __nv_bfloat16 g_xlo[(size_t)MROWS * Dd];
__device__ __align__(256) __nv_bfloat16 g_aohi[(size_t)MROWS * NQ];
__device__ __align__(256) __nv_bfloat16 g_aolo[(size_t)MROWS * NQ];
__device__ __align__(256) __nv_bfloat16 g_wqhi[(size_t)NQ * Dd];   // [N,K]
__device__ __align__(256) __nv_bfloat16 g_wqlo[(size_t)NQ * Dd];
__device__ __align__(256) __nv_bfloat16 g_wkhi[(size_t)NKV * Dd];
__device__ __align__(256) __nv_bfloat16 g_wklo[(size_t)NKV * Dd];
__device__ __align__(256) __nv_bfloat16 g_wvhi[(size_t)NKV * Dd];
__device__ __align__(256) __nv_bfloat16 g_wvlo[(size_t)NKV * Dd];
__device__ __align__(256) __nv_bfloat16 g_wohi[(size_t)Dd * NQ];
__device__ __align__(256) __nv_bfloat16 g_wolo[(size_t)Dd * NQ];

// ---------------- helpers ----------------------------------------------------
__device__ __forceinline__ uint32_t smem_u32(const void* p) {
    uint32_t a;
    asm("{ .reg .u64 t; cvta.to.shared.u64 t, %1; cvt.u32.u64 %0, t; }"
        : "=r"(a) : "l"(p));
    return a;
}
__device__ __forceinline__ void cp_async16(uint32_t saddr, const void* gaddr) {
    asm volatile("cp.async.cg.shared.global [%0], [%1], 16;"
                 :: "r"(saddr), "l"(gaddr) : "memory");
}
__device__ __forceinline__ void ldmat4(uint32_t* r, uint32_t addr) {
    asm volatile("ldmatrix.sync.aligned.m8n8.x4.shared.b16 {%0,%1,%2,%3}, [%4];"
                 : "=r"(r[0]), "=r"(r[1]), "=r"(r[2]), "=r"(r[3]) : "r"(addr));
}
__device__ __forceinline__ void mma_bf16(float* c, const uint32_t* a, const uint32_t* b) {
    asm volatile(
        "mma.sync.aligned.m16n8k16.row.col.f32.bf16.bf16.f32 "
        "{%0,%1,%2,%3}, {%4,%5,%6,%7}, {%8,%9}, {%0,%1,%2,%3};"
        : "+f"(c[0]), "+f"(c[1]), "+f"(c[2]), "+f"(c[3])
        : "r"(a[0]), "r"(a[1]), "r"(a[2]), "r"(a[3]), "r"(b[0]), "r"(b[1]));
}

// ---------------- split kernels ---------------------------------------------
__global__ __launch_bounds__(256) void split_rows_kernel(
    const float4* __restrict__ in, __nv_bfloat16* __restrict__ hi,
    __nv_bfloat16* __restrict__ lo, int n4)
{
    int i = blockIdx.x * 256 + threadIdx.x;
    if (i >= n4) return;
    float4 v = in[i];
    __nv_bfloat16 h0 = __float2bfloat16_rn(v.x);
    __nv_bfloat16 h1 = __float2bfloat16_rn(v.y);
    __nv_bfloat16 h2 = __float2bfloat16_rn(v.z);
    __nv_bfloat16 h3 = __float2bfloat16_rn(v.w);
    __nv_bfloat16 l0 = __float2bfloat16_rn(v.x - __bfloat162float(h0));
    __nv_bfloat16 l1 = __float2bfloat16_rn(v.y - __bfloat162float(h1));
    __nv_bfloat16 l2 = __float2bfloat16_rn(v.z - __bfloat162float(h2));
    __nv_bfloat16 l3 = __float2bfloat16_rn(v.w - __bfloat162float(h3));
    __nv_bfloat162* hp = (__nv_bfloat162*)(hi + (size_t)i * 4);
    __nv_bfloat162* lp = (__nv_bfloat162*)(lo + (size_t)i * 4);
    hp[0] = __nv_bfloat162(h0, h1); hp[1] = __nv_bfloat162(h2, h3);
    lp[0] = __nv_bfloat162(l0, l1); lp[1] = __nv_bfloat162(l2, l3);
}

// in [K,N] fp32 -> out hi/lo [N,K] bf16
__global__ __launch_bounds__(256) void split_transpose_kernel(
    const float* __restrict__ in, __nv_bfloat16* __restrict__ hi,
    __nv_bfloat16* __restrict__ lo, int K, int N)
{
    __shared__ float t[32][33];
    int n0 = blockIdx.x * 32, k0 = blockIdx.y * 32;
    int tx = threadIdx.x & 31, ty = threadIdx.x >> 5;  // 32 x 8
#pragma unroll
    for (int i = 0; i < 32; i += 8)
        t[ty + i][tx] = in[(size_t)(k0 + ty + i) * N + n0 + tx];
    __syncthreads();
#pragma unroll
    for (int i = 0; i < 32; i += 8) {
        float a = t[tx][ty + i];
        __nv_bfloat16 h = __float2bfloat16_rn(a);
        __nv_bfloat16 l = __float2bfloat16_rn(a - __bfloat162float(h));
        size_t o = (size_t)(n0 + ty + i) * K + k0 + tx;
        hi[o] = h; lo[o] = l;
    }
}

// ---------------- mma.sync split-bf16 GEMM -----------------------------------
// C[M,N] = A[M,K] @ B[N,K]^T with A = Ahi+Alo, B = Bhi+Blo (bf16x3 scheme).
// CTA tile 256x128, BK=32, 3-stage cp.async pipeline, 8 warps (4m x 2n),
// warp tile 64x64.
#define GP 80                 // smem row pitch in BYTES — conflict-free ldmatrix
#define ATILE (256 * GP)      // 20480 B per 256x32 bf16 tile
#define BTILE (128 * GP)      // 10240 B per 128x32 bf16 tile
#define STGB (2 * ATILE + 2 * BTILE)   // 61440 per stage
#define NSTG 3

__global__ __launch_bounds__(256, 1) void mma_gemm_kernel(
    const __nv_bfloat16* __restrict__ Ahi, const __nv_bfloat16* __restrict__ Alo,
    const __nv_bfloat16* __restrict__ Bhi, const __nv_bfloat16* __restrict__ Blo,
    float* __restrict__ C, int M, int N, int K)
{
    extern __shared__ char smem[];
    uint32_t sb = smem_u32(smem);
    int tid = threadIdx.x, lane = tid & 31, wid = tid >> 5;
    int wm = wid & 3, wn = wid >> 2;          // 4 x 2 warp grid
    int row0 = blockIdx.y * 256, col0 = blockIdx.x * 128;

    const __nv_bfloat16* a_hi = Ahi + (size_t)row0 * K;
    const __nv_bfloat16* a_lo = Alo + (size_t)row0 * K;
    const __nv_bfloat16* b_hi = Bhi + (size_t)col0 * K;
    const __nv_bfloat16* b_lo = Blo + (size_t)col0 * K;

    const int NC = K >> 5;

    float acc[4][8][4];
#pragma unroll
    for (int mt = 0; mt < 4; mt++)
#pragma unroll
        for (int nt = 0; nt < 8; nt++)
#pragma unroll
            for (int i = 0; i < 4; i++) acc[mt][nt][i] = 0.f;

    // ldmatrix per-lane offsets
    int grp = lane >> 3, lr = lane & 7;
    uint32_t aoff = (uint32_t)(((grp & 1) * 8 + lr) * GP + (grp >> 1) * 16);
    uint32_t boff = (uint32_t)(((grp >> 1) * 8 + lr) * GP + (grp & 1) * 16);

    // per-thread copy coords
    int rA = tid >> 2, cA = tid & 3;          // A: 4 iters of 64 rows
    int rB = tid >> 2, cB = tid & 3;          // B: 2 iters of 64 rows

    auto load_stage = [&](int c) {
        uint32_t st = sb + (uint32_t)(c % NSTG) * STGB;
        int kb = c * 32;
#pragma unroll
        for (int i = 0; i < 4; i++) {
            int row = rA + i * 64;
            uint32_t so = (uint32_t)(row * GP + cA * 16);
            const __nv_bfloat16* gh = a_hi + (size_t)row * K + kb + cA * 8;
            const __nv_bfloat16* gl = a_lo + (size_t)row * K + kb + cA * 8;
            cp_async16(st + so, gh);
            cp_async16(st + ATILE + so, gl);
        }
#pragma unroll
        for (int i = 0; i < 2; i++) {
            int row = rB + i * 64;
            uint32_t so = (uint32_t)(row * GP + cB * 16);
            const __nv_bfloat16* gh = b_hi + (size_t)row * K + kb + cB * 8;
            const __nv_bfloat16* gl = b_lo + (size_t)row * K + kb + cB * 8;
            cp_async16(st + 2 * ATILE + so, gh);
            cp_async16(st + 2 * ATILE + BTILE + so, gl);
        }
        asm volatile("cp.async.commit_group;" ::: "memory");
    };

    load_stage(0);
    load_stage(1);

    for (int c = 0; c < NC; c++) {
        if (c + 2 < NC) {
            load_stage(c + 2);
            asm volatile("cp.async.wait_group 2;" ::: "memory");
        } else if (c + 1 < NC) {
            asm volatile("cp.async.wait_group 1;" ::: "memory");
        } else {
            asm volatile("cp.async.wait_group 0;" ::: "memory");
        }
        __syncthreads();

        uint32_t st = sb + (uint32_t)(c % NSTG) * STGB;
        uint32_t A0 = st, A1 = st + ATILE;
        uint32_t B0 = st + 2 * ATILE, B1 = B0 + BTILE;

#pragma unroll
        for (int kk = 0; kk < 2; kk++) {
            uint32_t kbyte = (uint32_t)kk * 32;
            uint32_t ah[4][4], al[4][4];
#pragma unroll
            for (int mt = 0; mt < 4; mt++) {
                uint32_t rb = (uint32_t)((wm * 64 + mt * 16) * GP) + aoff + kbyte;
                ldmat4(ah[mt], A0 + rb);
                ldmat4(al[mt], A1 + rb);
            }
#pragma unroll
            for (int nh = 0; nh < 2; nh++) {
                uint32_t bh[4][2], bl[4][2];
#pragma unroll
                for (int nt2 = 0; nt2 < 2; nt2++) {
                    uint32_t rb = (uint32_t)((wn * 64 + nh * 32 + nt2 * 16) * GP)
                                + boff + kbyte;
                    uint32_t r[4];
                    ldmat4(r, B0 + rb);
                    bh[nt2 * 2][0] = r[0]; bh[nt2 * 2][1] = r[1];
                    bh[nt2 * 2 + 1][0] = r[2]; bh[nt2 * 2 + 1][1] = r[3];
                    ldmat4(r, B1 + rb);
                    bl[nt2 * 2][0] = r[0]; bl[nt2 * 2][1] = r[1];
                    bl[nt2 * 2 + 1][0] = r[2]; bl[nt2 * 2 + 1][1] = r[3];
                }
#pragma unroll
                for (int mt = 0; mt < 4; mt++)
#pragma unroll
                    for (int nt = 0; nt < 4; nt++) {
                        float* a = acc[mt][nh * 4 + nt];
                        mma_bf16(a, ah[mt], bh[nt]);
                        mma_bf16(a, ah[mt], bl[nt]);
                        mma_bf16(a, al[mt], bh[nt]);
                    }
            }
        }
        __syncthreads();
    }

    // epilogue
#pragma unroll
    for (int mt = 0; mt < 4; mt++) {
        int rg0 = row0 + wm * 64 + mt * 16 + (lane >> 2);
#pragma unroll
        for (int nt = 0; nt < 8; nt++) {
            int cg = col0 + wn * 64 + nt * 8 + (lane & 3) * 2;
            *(float2*)(C + (size_t)rg0 * N + cg) =
                make_float2(acc[mt][nt][0], acc[mt][nt][1]);
            *(float2*)(C + (size_t)(rg0 + 8) * N + cg) =
                make_float2(acc[mt][nt][2], acc[mt][nt][3]);
        }
    }
}

// ---------------- Gemma RMSNorm over contiguous 256-float rows -------------
__global__ __launch_bounds__(256) void rmsnorm_kernel(
    float* __restrict__ buf, const float* __restrict__ scale)
{
    int row = blockIdx.x;
    int d = threadIdx.x;
    float* p = buf + (size_t)row * HD;
    float x = p[d];
    float v = x * x;
#pragma unroll
    for (int o = 16; o > 0; o >>= 1) v += __shfl_xor_sync(0xffffffffu, v, o);
    __shared__ float ws[8];
    __shared__ float stot;
    if ((d & 31) == 0) ws[d >> 5] = v;
    __syncthreads();
    if (d == 0) {
        float s = 0.f;
#pragma unroll
        for (int i = 0; i < 8; i++) s += ws[i];
        stot = s;
    }
    __syncthreads();
    float r = rsqrtf(stot * (1.f / HD) + 1e-6f);
    p[d] = x * r * (1.f + scale[d]);
}

// ---------------- sliding-window flash attention (fp32) --------------------
#define AQT 32
#define QPAD 257   // Q/K pitch (scalar access)
#define VPAD 260   // V pitch: 16B-aligned rows for LDS.128
#define SPAD 33

__global__ __launch_bounds__(256) void attn_kernel()
{
    extern __shared__ float sm[];
    float* Qs = sm;                     // [32][257]
    float* Ks = Qs + AQT * QPAD;        // [32][257]
    float* Vs = Ks + AQT * QPAD;        // [32][260]
    float* Ss = Vs + AQT * VPAD;        // [32][33]
    float* lrow = Ss + AQT * SPAD;
    float* arow = lrow + AQT;

    int tid = threadIdx.x;
    int qt = blockIdx.x;
    int h  = blockIdx.y;
    int b  = blockIdx.z;
    int t0 = qt * AQT;
    int kvh = h & (Gg - 1);

    for (int idx = tid; idx < AQT * HD; idx += 256) {
        int qi = idx >> 8, d = idx & 255;
        Qs[qi * QPAD + d] =
            g_q[((size_t)(b * Tt + t0 + qi)) * NQ + h * HD + d] * QK_SCALE;
    }

    int qi_o = tid >> 3;   // output query row
    int dseg = tid & 7;    // owns d = dseg*4 + 32*j (float4 chunks)
    float4 o4[8];
#pragma unroll
    for (int j = 0; j < 8; j++) o4[j] = make_float4(0.f, 0.f, 0.f, 0.f);

    float mreg = -1e30f, lreg = 0.f;

    int kb0 = max(0, t0 - (WINDOW - 1)) >> 5;
    int kb1 = (t0 + AQT - 1) >> 5;

    for (int kb = kb0; kb <= kb1; kb++) {
        int s0 = kb * AQT;
        __syncthreads();

        for (int idx = tid; idx < AQT * HD; idx += 256) {
            int ki = idx >> 8, d = idx & 255;
            Ks[ki * QPAD + d] =
                g_k[((size_t)(b * Tt + s0 + ki)) * NKV + kvh * HD + d];
        }
        for (int idx = tid; idx < AQT * (HD / 4); idx += 256) {
            int ki = idx >> 6, dc = idx & 63;
            float4 vv = *(const float4*)(
                g_v + ((size_t)(b * Tt + s0 + ki)) * NKV + kvh * HD + dc * 4);
            *(float4*)(Vs + ki * VPAD + dc * 4) = vv;
        }
        __syncthreads();

        // scores: 2x2 micro-tile per thread
        int q2 = (tid >> 4) << 1;
        int k2 = (tid & 15) << 1;
        float s00 = 0.f, s01 = 0.f, s10 = 0.f, s11 = 0.f;
        const float* q0p = Qs + q2 * QPAD;
        const float* q1p = q0p + QPAD;
        const float* k0p = Ks + k2 * QPAD;
        const float* k1p = k0p + QPAD;
#pragma unroll 4
        for (int d = 0; d < HD; d++) {
            float q0v = q0p[d], q1v = q1p[d];
            float k0v = k0p[d], k1v = k1p[d];
            s00 += q0v * k0v; s01 += q0v * k1v;
            s10 += q1v * k0v; s11 += q1v * k1v;
        }
        {
            int tq0 = t0 + q2, tq1 = tq0 + 1;
            int kk0 = s0 + k2, kk1 = kk0 + 1;
            Ss[q2 * SPAD + k2]           = (kk0 > tq0 || kk0 < tq0 - (WINDOW - 1)) ? -1e30f : s00;
            Ss[q2 * SPAD + k2 + 1]       = (kk1 > tq0 || kk1 < tq0 - (WINDOW - 1)) ? -1e30f : s01;
            Ss[(q2 + 1) * SPAD + k2]     = (kk0 > tq1 || kk0 < tq1 - (WINDOW - 1)) ? -1e30f : s10;
            Ss[(q2 + 1) * SPAD + k2 + 1] = (kk1 > tq1 || kk1 < tq1 - (WINDOW - 1)) ? -1e30f : s11;
        }
        __syncthreads();

        // online softmax (one thread per query row)
        if (tid < 32) {
            float* srow = Ss + tid * SPAD;
            float mnew = mreg;
#pragma unroll
            for (int j = 0; j < 32; j++) mnew = fmaxf(mnew, srow[j]);
            float alpha = __expf(mreg - mnew);
            float sum = 0.f;
#pragma unroll
            for (int j = 0; j < 32; j++) {
                float s = srow[j];
                float p = __expf(s - mnew);
                if (s < -1e29f) p = 0.f;
                srow[j] = p;
                sum += p;
            }
            lreg = lreg * alpha + sum;
            mreg = mnew;
            arow[tid] = alpha;
            lrow[tid] = lreg;
        }
        __syncthreads();

        // O = O*alpha + P @ V  (vectorized over d)
        float al = arow[qi_o];
#pragma unroll
        for (int j = 0; j < 8; j++) {
            o4[j].x *= al; o4[j].y *= al; o4[j].z *= al; o4[j].w *= al;
        }
        const float* prow = Ss + qi_o * SPAD;
#pragma unroll 4
        for (int k = 0; k < 32; k++) {
            float p = prow[k];
            const float4* vrow = (const float4*)(Vs + k * VPAD) + dseg;
#pragma unroll
            for (int j = 0; j < 8; j++) {
                float4 vv = vrow[j * 8];
                o4[j].x += p * vv.x; o4[j].y += p * vv.y;
                o4[j].z += p * vv.z; o4[j].w += p * vv.w;
            }
        }
    }
    __syncthreads();

    float invl = 1.f / lrow[qi_o];
    float* op = g_ao + ((size_t)(b * Tt + t0 + qi_o)) * NQ + h * HD + dseg * 4;
#pragma unroll
    for (int j = 0; j < 8; j++) {
        float4 v = make_float4(o4[j].x * invl, o4[j].y * invl,
                               o4[j].z * invl, o4[j].w * invl);
        *(float4*)(op + j * 32) = v;
    }
}

// ---------------- launch ----------------------------------------------------
extern "C" void kernel_launch(void* const* d_in, const int* in_sizes, int n_in,
                              void* d_out, int out_size)
{
    const float* x   = (const float*)d_in[0];
    const float* Wq  = (const float*)d_in[1];
    const float* Wk  = (const float*)d_in[2];
    const float* Wv  = (const float*)d_in[3];
    const float* Wo  = (const float*)d_in[4];
    const float* qsc = (const float*)d_in[5];
    const float* ksc = (const float*)d_in[6];
    float* out = (float*)d_out;

    void *pq, *pk, *pv, *pao;
    void *pxh, *pxl, *paoh, *paol;
    void *pwqh, *pwql, *pwkh, *pwkl, *pwvh, *pwvl, *pwoh, *pwol;
    cudaGetSymbolAddress(&pq, g_q);   cudaGetSymbolAddress(&pk, g_k);
    cudaGetSymbolAddress(&pv, g_v);   cudaGetSymbolAddress(&pao, g_ao);
    cudaGetSymbolAddress(&pxh, g_xhi);  cudaGetSymbolAddress(&pxl, g_xlo);
    cudaGetSymbolAddress(&paoh, g_aohi); cudaGetSymbolAddress(&paol, g_aolo);
    cudaGetSymbolAddress(&pwqh, g_wqhi); cudaGetSymbolAddress(&pwql, g_wqlo);
    cudaGetSymbolAddress(&pwkh, g_wkhi); cudaGetSymbolAddress(&pwkl, g_wklo);
    cudaGetSymbolAddress(&pwvh, g_wvhi); cudaGetSymbolAddress(&pwvl, g_wvlo);
    cudaGetSymbolAddress(&pwoh, g_wohi); cudaGetSymbolAddress(&pwol, g_wolo);

    float* dq  = (float*)pq;  float* dk = (float*)pk;
    float* dv  = (float*)pv;  float* dao = (float*)pao;
    __nv_bfloat16* xh = (__nv_bfloat16*)pxh;  __nv_bfloat16* xl = (__nv_bfloat16*)pxl;
    __nv_bfloat16* aoh = (__nv_bfloat16*)paoh; __nv_bfloat16* aol = (__nv_bfloat16*)paol;
    __nv_bfloat16* wqh = (__nv_bfloat16*)pwqh; __nv_bfloat16* wql = (__nv_bfloat16*)pwql;
    __nv_bfloat16* wkh = (__nv_bfloat16*)pwkh; __nv_bfloat16* wkl = (__nv_bfloat16*)pwkl;
    __nv_bfloat16* wvh = (__nv_bfloat16*)pwvh; __nv_bfloat16* wvl = (__nv_bfloat16*)pwvl;
    __nv_bfloat16* woh = (__nv_bfloat16*)pwoh; __nv_bfloat16* wol = (__nv_bfloat16*)pwol;

    size_t gemm_smem = (size_t)NSTG * STGB;  // 184320
    cudaFuncSetAttribute(mma_gemm_kernel,
                         cudaFuncAttributeMaxDynamicSharedMemorySize, (int)gemm_smem);

    // ---- splits for Q/K/V projections ----
    {
        int n4 = (MROWS * Dd) / 4;
        split_rows_kernel<<<(n4 + 255) / 256, 256>>>((const float4*)x, xh, xl, n4);
        split_transpose_kernel<<<dim3(NQ / 32, Dd / 32), 256>>>(Wq, wqh, wql, Dd, NQ);
        split_transpose_kernel<<<dim3(NKV / 32, Dd / 32), 256>>>(Wk, wkh, wkl, Dd, NKV);
        split_transpose_kernel<<<dim3(NKV / 32, Dd / 32), 256>>>(Wv, wvh, wvl, Dd, NKV);
    }

    // ---- projections (tensor cores) ----
    {
        dim3 blk(256);
        mma_gemm_kernel<<<dim3(NQ / 128,  MROWS / 256), blk, gemm_smem>>>(
            xh, xl, wqh, wql, dq, MROWS, NQ, Dd);
        mma_gemm_kernel<<<dim3(NKV / 128, MROWS / 256), blk, gemm_smem>>>(
            xh, xl, wkh, wkl, dk, MROWS, NKV, Dd);
        mma_gemm_kernel<<<dim3(NKV / 128, MROWS / 256), blk, gemm_smem>>>(
            xh, xl, wvh, wvl, dv, MROWS, NKV, Dd);
    }

    // ---- qk-norm ----
    rmsnorm_kernel<<<MROWS * Hh, 256>>>(dq, qsc);
    rmsnorm_kernel<<<MROWS * Gg, 256>>>(dk, ksc);

    // ---- attention ----
    {
        size_t smem = (size_t)(2 * AQT * QPAD + AQT * VPAD + AQT * SPAD + 2 * AQT)
                      * sizeof(float);
        cudaFuncSetAttribute(attn_kernel,
                             cudaFuncAttributeMaxDynamicSharedMemorySize, (int)smem);
        dim3 grid(Tt / AQT, Hh, Bb);
        attn_kernel<<<grid, 256, smem>>>();
    }

    // ---- output projection ----
    {
        int n4 = (MROWS * NQ) / 4;
        split_rows_kernel<<<(n4 + 255) / 256, 256>>>((const float4*)dao, aoh, aol, n4);
        split_transpose_kernel<<<dim3(Dd / 32, NQ / 32), 256>>>(Wo, woh, wol, NQ, Dd);
        mma_gemm_kernel<<<dim3(Dd / 128, MROWS / 256), 256, gemm_smem>>>(
            aoh, aol, woh, wol, out, MROWS, Dd, NQ);
    }
}

// round 6
// speedup vs baseline: 1.1701x; 1.1701x over previous
#include <cuda_runtime.h>
#include <cuda_fp16.h>
#include <math.h>
#include <cstdint>

// ---------------- problem constants ----------------
#define Bb 2
#define Tt 2048
#define Dd 2560
#define Hh 8
#define Gg 4
#define HD 256
#define NQ (Hh*HD)     // 2048
#define NKV (Gg*HD)    // 1024
#define MROWS (Bb*Tt)  // 4096
#define QK_SCALE 0.0625f
#define WINDOW 1024

// ---------------- scratch (static device globals; no allocation) -----------
__device__ float g_q[(size_t)MROWS * NQ];
__device__ float g_k[(size_t)MROWS * NKV];
__device__ float g_v[(size_t)MROWS * NKV];
__device__ float g_ao[(size_t)MROWS * NQ];

// fp16 operands (16B-aligned for cp.async)
__device__ __align__(256) __half g_xh[(size_t)MROWS * Dd];      // A for QKV proj
__device__ __align__(256) __half g_aoh[(size_t)MROWS * NQ];     // A for O proj
__device__ __align__(256) __half g_wqhi[(size_t)NQ * Dd];       // [N,K] hi
__device__ __align__(256) __half g_wqlo[(size_t)NQ * Dd];       // [N,K] lo
__device__ __align__(256) __half g_wkhi[(size_t)NKV * Dd];
__device__ __align__(256) __half g_wklo[(size_t)NKV * Dd];
__device__ __align__(256) __half g_wvhi[(size_t)NKV * Dd];
__device__ __align__(256) __half g_wvlo[(size_t)NKV * Dd];
__device__ __align__(256) __half g_wohi[(size_t)Dd * NQ];
__device__ __align__(256) __half g_wolo[(size_t)Dd * NQ];

// ---------------- helpers ----------------------------------------------------
__device__ __forceinline__ uint32_t smem_u32(const void* p) {
    uint32_t a;
    asm("{ .reg .u64 t; cvta.to.shared.u64 t, %1; cvt.u32.u64 %0, t; }"
        : "=r"(a) : "l"(p));
    return a;
}
__device__ __forceinline__ void cp_async16(uint32_t saddr, const void* gaddr) {
    asm volatile("cp.async.cg.shared.global [%0], [%1], 16;"
                 :: "r"(saddr), "l"(gaddr) : "memory");
}
__device__ __forceinline__ void ldmat4(uint32_t* r, uint32_t addr) {
    asm volatile("ldmatrix.sync.aligned.m8n8.x4.shared.b16 {%0,%1,%2,%3}, [%4];"
                 : "=r"(r[0]), "=r"(r[1]), "=r"(r[2]), "=r"(r[3]) : "r"(addr));
}
__device__ __forceinline__ void mma_f16(float* c, const uint32_t* a, const uint32_t* b) {
    asm volatile(
        "mma.sync.aligned.m16n8k16.row.col.f32.f16.f16.f32 "
        "{%0,%1,%2,%3}, {%4,%5,%6,%7}, {%8,%9}, {%0,%1,%2,%3};"
        : "+f"(c[0]), "+f"(c[1]), "+f"(c[2]), "+f"(c[3])
        : "r"(a[0]), "r"(a[1]), "r"(a[2]), "r"(a[3]), "r"(b[0]), "r"(b[1]));
}

// ---------------- split kernels ---------------------------------------------
// fp32 -> single fp16 (row-major, same layout)
__global__ __launch_bounds__(256) void tohalf_kernel(
    const float4* __restrict__ in, __half* __restrict__ out, int n4)
{
    int i = blockIdx.x * 256 + threadIdx.x;
    if (i >= n4) return;
    float4 v = in[i];
    __half2* op = (__half2*)(out + (size_t)i * 4);
    op[0] = __half2(__float2half_rn(v.x), __float2half_rn(v.y));
    op[1] = __half2(__float2half_rn(v.z), __float2half_rn(v.w));
}

// in [K,N] fp32 -> out hi/lo [N,K] fp16
__global__ __launch_bounds__(256) void split_transpose_kernel(
    const float* __restrict__ in, __half* __restrict__ hi,
    __half* __restrict__ lo, int K, int N)
{
    __shared__ float t[32][33];
    int n0 = blockIdx.x * 32, k0 = blockIdx.y * 32;
    int tx = threadIdx.x & 31, ty = threadIdx.x >> 5;  // 32 x 8
#pragma unroll
    for (int i = 0; i < 32; i += 8)
        t[ty + i][tx] = in[(size_t)(k0 + ty + i) * N + n0 + tx];
    __syncthreads();
#pragma unroll
    for (int i = 0; i < 32; i += 8) {
        float a = t[tx][ty + i];
        __half h = __float2half_rn(a);
        __half l = __float2half_rn(a - __half2float(h));
        size_t o = (size_t)(n0 + ty + i) * K + k0 + tx;
        hi[o] = h; lo[o] = l;
    }
}

// ---------------- mma.sync fp16 2-pass GEMM ----------------------------------
// C[M,N] = A[M,K] @ (Bhi[N,K] + Blo[N,K])^T, A single fp16, fp32 accum.
// CTA tile 128x128, BK=32, double-buffered cp.async, 8 warps (4m x 2n),
// 2 CTAs / SM.
#define GP 80                 // smem row pitch in BYTES — conflict-free ldmatrix
#define TILEB (128 * GP)      // 10240 B per 128x32 fp16 tile
#define STAGEB (3 * TILEB)    // A, Bhi, Blo = 30720

__global__ __launch_bounds__(256, 2) void mma_gemm_kernel(
    const __half* __restrict__ A,
    const __half* __restrict__ Bhi, const __half* __restrict__ Blo,
    float* __restrict__ C, int M, int N, int K)
{
    extern __shared__ char smem[];
    uint32_t sb = smem_u32(smem);
    int tid = threadIdx.x, lane = tid & 31, wid = tid >> 5;
    int wm = wid & 3, wn = wid >> 2;          // 4 x 2 warp grid
    int row0 = blockIdx.y * 128, col0 = blockIdx.x * 128;

    const __half* gsrc[3] = {
        A + (size_t)row0 * K,
        Bhi + (size_t)col0 * K, Blo + (size_t)col0 * K };

    const int NC = K >> 5;

    // per-thread copy coords: 512 16B-chunks per tile, 2 per thread
    int r_ld0 = tid >> 2, c16_0 = tid & 3;
    int r_ld1 = (tid + 256) >> 2, c16_1 = (tid + 256) & 3;

    float acc[2][8][4];
#pragma unroll
    for (int mt = 0; mt < 2; mt++)
#pragma unroll
        for (int nt = 0; nt < 8; nt++)
#pragma unroll
            for (int i = 0; i < 4; i++) acc[mt][nt][i] = 0.f;

    // ldmatrix per-lane offsets
    int grp = lane >> 3, lr = lane & 7;
    uint32_t aoff = (uint32_t)(((grp & 1) * 8 + lr) * GP + (grp >> 1) * 16);
    uint32_t boff = (uint32_t)(((grp >> 1) * 8 + lr) * GP + (grp & 1) * 16);

    auto load_stage = [&](int c) {
        uint32_t st = sb + (uint32_t)(c & 1) * STAGEB;
        int kb = c * 32;
#pragma unroll
        for (int tile = 0; tile < 3; tile++) {
            const __half* g = gsrc[tile];
            uint32_t tb = st + (uint32_t)tile * TILEB;
            cp_async16(tb + (uint32_t)(r_ld0 * GP + c16_0 * 16),
                       g + (size_t)r_ld0 * K + kb + c16_0 * 8);
            cp_async16(tb + (uint32_t)(r_ld1 * GP + c16_1 * 16),
                       g + (size_t)r_ld1 * K + kb + c16_1 * 8);
        }
        asm volatile("cp.async.commit_group;" ::: "memory");
    };

    load_stage(0);

    for (int c = 0; c < NC; c++) {
        if (c + 1 < NC) {
            load_stage(c + 1);
            asm volatile("cp.async.wait_group 1;" ::: "memory");
        } else {
            asm volatile("cp.async.wait_group 0;" ::: "memory");
        }
        __syncthreads();

        uint32_t st = sb + (uint32_t)(c & 1) * STAGEB;
        uint32_t A0 = st, B0 = st + TILEB, B1 = st + 2 * TILEB;

#pragma unroll
        for (int kk = 0; kk < 2; kk++) {
            uint32_t kbyte = (uint32_t)kk * 32;
            uint32_t ah[2][4];
#pragma unroll
            for (int mt = 0; mt < 2; mt++) {
                uint32_t rb = (uint32_t)((wm * 32 + mt * 16) * GP) + aoff + kbyte;
                ldmat4(ah[mt], A0 + rb);
            }
#pragma unroll
            for (int nh = 0; nh < 2; nh++) {
                uint32_t bh[4][2], bl[4][2];
#pragma unroll
                for (int nt2 = 0; nt2 < 2; nt2++) {
                    uint32_t rb = (uint32_t)((wn * 64 + nh * 32 + nt2 * 16) * GP)
                                + boff + kbyte;
                    uint32_t r[4];
                    ldmat4(r, B0 + rb);
                    bh[nt2 * 2][0] = r[0]; bh[nt2 * 2][1] = r[1];
                    bh[nt2 * 2 + 1][0] = r[2]; bh[nt2 * 2 + 1][1] = r[3];
                    ldmat4(r, B1 + rb);
                    bl[nt2 * 2][0] = r[0]; bl[nt2 * 2][1] = r[1];
                    bl[nt2 * 2 + 1][0] = r[2]; bl[nt2 * 2 + 1][1] = r[3];
                }
#pragma unroll
                for (int mt = 0; mt < 2; mt++)
#pragma unroll
                    for (int nt = 0; nt < 4; nt++) {
                        float* a = acc[mt][nh * 4 + nt];
                        mma_f16(a, ah[mt], bh[nt]);
                        mma_f16(a, ah[mt], bl[nt]);
                    }
            }
        }
        __syncthreads();
    }

    // epilogue
#pragma unroll
    for (int mt = 0; mt < 2; mt++) {
        int rg0 = row0 + wm * 32 + mt * 16 + (lane >> 2);
#pragma unroll
        for (int nt = 0; nt < 8; nt++) {
            int cg = col0 + wn * 64 + nt * 8 + (lane & 3) * 2;
            *(float2*)(C + (size_t)rg0 * N + cg) =
                make_float2(acc[mt][nt][0], acc[mt][nt][1]);
            *(float2*)(C + (size_t)(rg0 + 8) * N + cg) =
                make_float2(acc[mt][nt][2], acc[mt][nt][3]);
        }
    }
}

// ---------------- Gemma RMSNorm over contiguous 256-float rows -------------
__global__ __launch_bounds__(256) void rmsnorm_kernel(
    float* __restrict__ buf, const float* __restrict__ scale)
{
    int row = blockIdx.x;
    int d = threadIdx.x;
    float* p = buf + (size_t)row * HD;
    float x = p[d];
    float v = x * x;
#pragma unroll
    for (int o = 16; o > 0; o >>= 1) v += __shfl_xor_sync(0xffffffffu, v, o);
    __shared__ float ws[8];
    __shared__ float stot;
    if ((d & 31) == 0) ws[d >> 5] = v;
    __syncthreads();
    if (d == 0) {
        float s = 0.f;
#pragma unroll
        for (int i = 0; i < 8; i++) s += ws[i];
        stot = s;
    }
    __syncthreads();
    float r = rsqrtf(stot * (1.f / HD) + 1e-6f);
    p[d] = x * r * (1.f + scale[d]);
}

// ---------------- sliding-window flash attention (fp32) --------------------
#define AQT 32
#define QPAD 257   // Q/K pitch (scalar access)
#define VPAD 260   // V pitch: 16B-aligned rows for LDS.128
#define SPAD 33

__global__ __launch_bounds__(256) void attn_kernel()
{
    extern __shared__ float sm[];
    float* Qs = sm;                     // [32][257]
    float* Ks = Qs + AQT * QPAD;        // [32][257]
    float* Vs = Ks + AQT * QPAD;        // [32][260]
    float* Ss = Vs + AQT * VPAD;        // [32][33]
    float* lrow = Ss + AQT * SPAD;
    float* arow = lrow + AQT;

    int tid = threadIdx.x;
    int qt = blockIdx.x;
    int h  = blockIdx.y;
    int b  = blockIdx.z;
    int t0 = qt * AQT;
    int kvh = h & (Gg - 1);

    for (int idx = tid; idx < AQT * HD; idx += 256) {
        int qi = idx >> 8, d = idx & 255;
        Qs[qi * QPAD + d] =
            g_q[((size_t)(b * Tt + t0 + qi)) * NQ + h * HD + d] * QK_SCALE;
    }

    int qi_o = tid >> 3;   // output query row
    int dseg = tid & 7;    // owns d = dseg*4 + 32*j (float4 chunks)
    float4 o4[8];
#pragma unroll
    for (int j = 0; j < 8; j++) o4[j] = make_float4(0.f, 0.f, 0.f, 0.f);

    float mreg = -1e30f, lreg = 0.f;

    int kb0 = max(0, t0 - (WINDOW - 1)) >> 5;
    int kb1 = (t0 + AQT - 1) >> 5;

    for (int kb = kb0; kb <= kb1; kb++) {
        int s0 = kb * AQT;
        __syncthreads();

        for (int idx = tid; idx < AQT * HD; idx += 256) {
            int ki = idx >> 8, d = idx & 255;
            Ks[ki * QPAD + d] =
                g_k[((size_t)(b * Tt + s0 + ki)) * NKV + kvh * HD + d];
        }
        for (int idx = tid; idx < AQT * (HD / 4); idx += 256) {
            int ki = idx >> 6, dc = idx & 63;
            float4 vv = *(const float4*)(
                g_v + ((size_t)(b * Tt + s0 + ki)) * NKV + kvh * HD + dc * 4);
            *(float4*)(Vs + ki * VPAD + dc * 4) = vv;
        }
        __syncthreads();

        // scores: 2x2 micro-tile per thread
        int q2 = (tid >> 4) << 1;
        int k2 = (tid & 15) << 1;
        float s00 = 0.f, s01 = 0.f, s10 = 0.f, s11 = 0.f;
        const float* q0p = Qs + q2 * QPAD;
        const float* q1p = q0p + QPAD;
        const float* k0p = Ks + k2 * QPAD;
        const float* k1p = k0p + QPAD;
#pragma unroll 4
        for (int d = 0; d < HD; d++) {
            float q0v = q0p[d], q1v = q1p[d];
            float k0v = k0p[d], k1v = k1p[d];
            s00 += q0v * k0v; s01 += q0v * k1v;
            s10 += q1v * k0v; s11 += q1v * k1v;
        }
        {
            int tq0 = t0 + q2, tq1 = tq0 + 1;
            int kk0 = s0 + k2, kk1 = kk0 + 1;
            Ss[q2 * SPAD + k2]           = (kk0 > tq0 || kk0 < tq0 - (WINDOW - 1)) ? -1e30f : s00;
            Ss[q2 * SPAD + k2 + 1]       = (kk1 > tq0 || kk1 < tq0 - (WINDOW - 1)) ? -1e30f : s01;
            Ss[(q2 + 1) * SPAD + k2]     = (kk0 > tq1 || kk0 < tq1 - (WINDOW - 1)) ? -1e30f : s10;
            Ss[(q2 + 1) * SPAD + k2 + 1] = (kk1 > tq1 || kk1 < tq1 - (WINDOW - 1)) ? -1e30f : s11;
        }
        __syncthreads();

        // online softmax (one thread per query row)
        if (tid < 32) {
            float* srow = Ss + tid * SPAD;
            float mnew = mreg;
#pragma unroll
            for (int j = 0; j < 32; j++) mnew = fmaxf(mnew, srow[j]);
            float alpha = __expf(mreg - mnew);
            float sum = 0.f;
#pragma unroll
            for (int j = 0; j < 32; j++) {
                float s = srow[j];
                float p = __expf(s - mnew);
                if (s < -1e29f) p = 0.f;
                srow[j] = p;
                sum += p;
            }
            lreg = lreg * alpha + sum;
            mreg = mnew;
            arow[tid] = alpha;
            lrow[tid] = lreg;
        }
        __syncthreads();

        // O = O*alpha + P @ V  (vectorized over d)
        float al = arow[qi_o];
#pragma unroll
        for (int j = 0; j < 8; j++) {
            o4[j].x *= al; o4[j].y *= al; o4[j].z *= al; o4[j].w *= al;
        }
        const float* prow = Ss + qi_o * SPAD;
#pragma unroll 4
        for (int k = 0; k < 32; k++) {
            float p = prow[k];
            const float4* vrow = (const float4*)(Vs + k * VPAD) + dseg;
#pragma unroll
            for (int j = 0; j < 8; j++) {
                float4 vv = vrow[j * 8];
                o4[j].x += p * vv.x; o4[j].y += p * vv.y;
                o4[j].z += p * vv.z; o4[j].w += p * vv.w;
            }
        }
    }
    __syncthreads();

    float invl = 1.f / lrow[qi_o];
    float* op = g_ao + ((size_t)(b * Tt + t0 + qi_o)) * NQ + h * HD + dseg * 4;
#pragma unroll
    for (int j = 0; j < 8; j++) {
        float4 v = make_float4(o4[j].x * invl, o4[j].y * invl,
                               o4[j].z * invl, o4[j].w * invl);
        *(float4*)(op + j * 32) = v;
    }
}

// ---------------- launch ----------------------------------------------------
extern "C" void kernel_launch(void* const* d_in, const int* in_sizes, int n_in,
                              void* d_out, int out_size)
{
    const float* x   = (const float*)d_in[0];
    const float* Wq  = (const float*)d_in[1];
    const float* Wk  = (const float*)d_in[2];
    const float* Wv  = (const float*)d_in[3];
    const float* Wo  = (const float*)d_in[4];
    const float* qsc = (const float*)d_in[5];
    const float* ksc = (const float*)d_in[6];
    float* out = (float*)d_out;

    void *pq, *pk, *pv, *pao, *pxh, *paoh;
    void *pwqh, *pwql, *pwkh, *pwkl, *pwvh, *pwvl, *pwoh, *pwol;
    cudaGetSymbolAddress(&pq, g_q);   cudaGetSymbolAddress(&pk, g_k);
    cudaGetSymbolAddress(&pv, g_v);   cudaGetSymbolAddress(&pao, g_ao);
    cudaGetSymbolAddress(&pxh, g_xh); cudaGetSymbolAddress(&paoh, g_aoh);
    cudaGetSymbolAddress(&pwqh, g_wqhi); cudaGetSymbolAddress(&pwql, g_wqlo);
    cudaGetSymbolAddress(&pwkh, g_wkhi); cudaGetSymbolAddress(&pwkl, g_wklo);
    cudaGetSymbolAddress(&pwvh, g_wvhi); cudaGetSymbolAddress(&pwvl, g_wvlo);
    cudaGetSymbolAddress(&pwoh, g_wohi); cudaGetSymbolAddress(&pwol, g_wolo);

    float* dq  = (float*)pq;  float* dk = (float*)pk;
    float* dv  = (float*)pv;  float* dao = (float*)pao;
    __half* xh  = (__half*)pxh;  __half* aoh = (__half*)paoh;
    __half* wqh = (__half*)pwqh; __half* wql = (__half*)pwql;
    __half* wkh = (__half*)pwkh; __half* wkl = (__half*)pwkl;
    __half* wvh = (__half*)pwvh; __half* wvl = (__half*)pwvl;
    __half* woh = (__half*)pwoh; __half* wol = (__half*)pwol;

    size_t gemm_smem = 2 * STAGEB;  // 61440
    cudaFuncSetAttribute(mma_gemm_kernel,
                         cudaFuncAttributeMaxDynamicSharedMemorySize, (int)gemm_smem);

    // ---- splits for Q/K/V projections ----
    {
        int n4 = (MROWS * Dd) / 4;
        tohalf_kernel<<<(n4 + 255) / 256, 256>>>((const float4*)x, xh, n4);
        split_transpose_kernel<<<dim3(NQ / 32, Dd / 32), 256>>>(Wq, wqh, wql, Dd, NQ);
        split_transpose_kernel<<<dim3(NKV / 32, Dd / 32), 256>>>(Wk, wkh, wkl, Dd, NKV);
        split_transpose_kernel<<<dim3(NKV / 32, Dd / 32), 256>>>(Wv, wvh, wvl, Dd, NKV);
    }

    // ---- projections (tensor cores, fp16 2-pass) ----
    {
        dim3 blk(256);
        mma_gemm_kernel<<<dim3(NQ / 128,  MROWS / 128), blk, gemm_smem>>>(
            xh, wqh, wql, dq, MROWS, NQ, Dd);
        mma_gemm_kernel<<<dim3(NKV / 128, MROWS / 128), blk, gemm_smem>>>(
            xh, wkh, wkl, dk, MROWS, NKV, Dd);
        mma_gemm_kernel<<<dim3(NKV / 128, MROWS / 128), blk, gemm_smem>>>(
            xh, wvh, wvl, dv, MROWS, NKV, Dd);
    }

    // ---- qk-norm ----
    rmsnorm_kernel<<<MROWS * Hh, 256>>>(dq, qsc);
    rmsnorm_kernel<<<MROWS * Gg, 256>>>(dk, ksc);

    // ---- attention ----
    {
        size_t smem = (size_t)(2 * AQT * QPAD + AQT * VPAD + AQT * SPAD + 2 * AQT)
                      * sizeof(float);
        cudaFuncSetAttribute(attn_kernel,
                             cudaFuncAttributeMaxDynamicSharedMemorySize, (int)smem);
        dim3 grid(Tt / AQT, Hh, Bb);
        attn_kernel<<<grid, 256, smem>>>();
    }

    // ---- output projection ----
    {
        int n4 = (MROWS * NQ) / 4;
        tohalf_kernel<<<(n4 + 255) / 256, 256>>>((const float4*)dao, aoh, n4);
        split_transpose_kernel<<<dim3(Dd / 32, NQ / 32), 256>>>(Wo, woh, wol, NQ, Dd);
        mma_gemm_kernel<<<dim3(Dd / 128, MROWS / 128), 256, gemm_smem>>>(
            aoh, woh, wol, out, MROWS, Dd, NQ);
    }
}

// round 7
// speedup vs baseline: 2.6232x; 2.2419x over previous
#include <cuda_runtime.h>
#include <cuda_fp16.h>
#include <math.h>
#include <cstdint>

// ---------------- problem constants ----------------
#define Bb 2
#define Tt 2048
#define Dd 2560
#define Hh 8
#define Gg 4
#define HD 256
#define NQ (Hh*HD)     // 2048
#define NKV (Gg*HD)    // 1024
#define MROWS (Bb*Tt)  // 4096
#define QK_SCALE 0.0625f
#define WINDOW 1024

// ---------------- scratch (static device globals; no allocation) -----------
__device__ float g_q[(size_t)MROWS * NQ];
__device__ float g_k[(size_t)MROWS * NKV];
__device__ float g_v[(size_t)MROWS * NKV];

// fp16 operands (16B-aligned for cp.async)
__device__ __align__(256) __half g_xh[(size_t)MROWS * Dd];      // A for QKV proj
__device__ __align__(256) __half g_aoh[(size_t)MROWS * NQ];     // A for O proj (attn writes)
__device__ __align__(256) __half g_wqhi[(size_t)NQ * Dd];       // [N,K] hi
__device__ __align__(256) __half g_wqlo[(size_t)NQ * Dd];       // [N,K] lo
__device__ __align__(256) __half g_wkhi[(size_t)NKV * Dd];
__device__ __align__(256) __half g_wklo[(size_t)NKV * Dd];
__device__ __align__(256) __half g_wvhi[(size_t)NKV * Dd];
__device__ __align__(256) __half g_wvlo[(size_t)NKV * Dd];
__device__ __align__(256) __half g_wohi[(size_t)Dd * NQ];
__device__ __align__(256) __half g_wolo[(size_t)Dd * NQ];

// ---------------- helpers ----------------------------------------------------
__device__ __forceinline__ uint32_t smem_u32(const void* p) {
    uint32_t a;
    asm("{ .reg .u64 t; cvta.to.shared.u64 t, %1; cvt.u32.u64 %0, t; }"
        : "=r"(a) : "l"(p));
    return a;
}
__device__ __forceinline__ void cp_async16(uint32_t saddr, const void* gaddr) {
    asm volatile("cp.async.cg.shared.global [%0], [%1], 16;"
                 :: "r"(saddr), "l"(gaddr) : "memory");
}
__device__ __forceinline__ void ldmat4(uint32_t* r, uint32_t addr) {
    asm volatile("ldmatrix.sync.aligned.m8n8.x4.shared.b16 {%0,%1,%2,%3}, [%4];"
                 : "=r"(r[0]), "=r"(r[1]), "=r"(r[2]), "=r"(r[3]) : "r"(addr));
}
__device__ __forceinline__ void ldmat4t(uint32_t* r, uint32_t addr) {
    asm volatile("ldmatrix.sync.aligned.m8n8.x4.trans.shared.b16 {%0,%1,%2,%3}, [%4];"
                 : "=r"(r[0]), "=r"(r[1]), "=r"(r[2]), "=r"(r[3]) : "r"(addr));
}
__device__ __forceinline__ void mma_f16(float* c, const uint32_t* a, const uint32_t* b) {
    asm volatile(
        "mma.sync.aligned.m16n8k16.row.col.f32.f16.f16.f32 "
        "{%0,%1,%2,%3}, {%4,%5,%6,%7}, {%8,%9}, {%0,%1,%2,%3};"
        : "+f"(c[0]), "+f"(c[1]), "+f"(c[2]), "+f"(c[3])
        : "r"(a[0]), "r"(a[1]), "r"(a[2]), "r"(a[3]), "r"(b[0]), "r"(b[1]));
}

// ---------------- split kernels ---------------------------------------------
__global__ __launch_bounds__(256) void tohalf_kernel(
    const float4* __restrict__ in, __half* __restrict__ out, int n4)
{
    int i = blockIdx.x * 256 + threadIdx.x;
    if (i >= n4) return;
    float4 v = in[i];
    __half2* op = (__half2*)(out + (size_t)i * 4);
    op[0] = __half2(__float2half_rn(v.x), __float2half_rn(v.y));
    op[1] = __half2(__float2half_rn(v.z), __float2half_rn(v.w));
}

// in [K,N] fp32 -> out hi/lo [N,K] fp16
__global__ __launch_bounds__(256) void split_transpose_kernel(
    const float* __restrict__ in, __half* __restrict__ hi,
    __half* __restrict__ lo, int K, int N)
{
    __shared__ float t[32][33];
    int n0 = blockIdx.x * 32, k0 = blockIdx.y * 32;
    int tx = threadIdx.x & 31, ty = threadIdx.x >> 5;  // 32 x 8
#pragma unroll
    for (int i = 0; i < 32; i += 8)
        t[ty + i][tx] = in[(size_t)(k0 + ty + i) * N + n0 + tx];
    __syncthreads();
#pragma unroll
    for (int i = 0; i < 32; i += 8) {
        float a = t[tx][ty + i];
        __half h = __float2half_rn(a);
        __half l = __float2half_rn(a - __half2float(h));
        size_t o = (size_t)(n0 + ty + i) * K + k0 + tx;
        hi[o] = h; lo[o] = l;
    }
}

// ---------------- mma.sync fp16 2-pass GEMM (unchanged from R6) --------------
#define GP 80
#define TILEB (128 * GP)
#define STAGEB (3 * TILEB)

__global__ __launch_bounds__(256, 2) void mma_gemm_kernel(
    const __half* __restrict__ A,
    const __half* __restrict__ Bhi, const __half* __restrict__ Blo,
    float* __restrict__ C, int M, int N, int K)
{
    extern __shared__ char smem[];
    uint32_t sb = smem_u32(smem);
    int tid = threadIdx.x, lane = tid & 31, wid = tid >> 5;
    int wm = wid & 3, wn = wid >> 2;
    int row0 = blockIdx.y * 128, col0 = blockIdx.x * 128;

    const __half* gsrc[3] = {
        A + (size_t)row0 * K,
        Bhi + (size_t)col0 * K, Blo + (size_t)col0 * K };

    const int NC = K >> 5;

    int r_ld0 = tid >> 2, c16_0 = tid & 3;
    int r_ld1 = (tid + 256) >> 2, c16_1 = (tid + 256) & 3;

    float acc[2][8][4];
#pragma unroll
    for (int mt = 0; mt < 2; mt++)
#pragma unroll
        for (int nt = 0; nt < 8; nt++)
#pragma unroll
            for (int i = 0; i < 4; i++) acc[mt][nt][i] = 0.f;

    int grp = lane >> 3, lr = lane & 7;
    uint32_t aoff = (uint32_t)(((grp & 1) * 8 + lr) * GP + (grp >> 1) * 16);
    uint32_t boff = (uint32_t)(((grp >> 1) * 8 + lr) * GP + (grp & 1) * 16);

    auto load_stage = [&](int c) {
        uint32_t st = sb + (uint32_t)(c & 1) * STAGEB;
        int kb = c * 32;
#pragma unroll
        for (int tile = 0; tile < 3; tile++) {
            const __half* g = gsrc[tile];
            uint32_t tb = st + (uint32_t)tile * TILEB;
            cp_async16(tb + (uint32_t)(r_ld0 * GP + c16_0 * 16),
                       g + (size_t)r_ld0 * K + kb + c16_0 * 8);
            cp_async16(tb + (uint32_t)(r_ld1 * GP + c16_1 * 16),
                       g + (size_t)r_ld1 * K + kb + c16_1 * 8);
        }
        asm volatile("cp.async.commit_group;" ::: "memory");
    };

    load_stage(0);

    for (int c = 0; c < NC; c++) {
        if (c + 1 < NC) {
            load_stage(c + 1);
            asm volatile("cp.async.wait_group 1;" ::: "memory");
        } else {
            asm volatile("cp.async.wait_group 0;" ::: "memory");
        }
        __syncthreads();

        uint32_t st = sb + (uint32_t)(c & 1) * STAGEB;
        uint32_t A0 = st, B0 = st + TILEB, B1 = st + 2 * TILEB;

#pragma unroll
        for (int kk = 0; kk < 2; kk++) {
            uint32_t kbyte = (uint32_t)kk * 32;
            uint32_t ah[2][4];
#pragma unroll
            for (int mt = 0; mt < 2; mt++) {
                uint32_t rb = (uint32_t)((wm * 32 + mt * 16) * GP) + aoff + kbyte;
                ldmat4(ah[mt], A0 + rb);
            }
#pragma unroll
            for (int nh = 0; nh < 2; nh++) {
                uint32_t bh[4][2], bl[4][2];
#pragma unroll
                for (int nt2 = 0; nt2 < 2; nt2++) {
                    uint32_t rb = (uint32_t)((wn * 64 + nh * 32 + nt2 * 16) * GP)
                                + boff + kbyte;
                    uint32_t r[4];
                    ldmat4(r, B0 + rb);
                    bh[nt2 * 2][0] = r[0]; bh[nt2 * 2][1] = r[1];
                    bh[nt2 * 2 + 1][0] = r[2]; bh[nt2 * 2 + 1][1] = r[3];
                    ldmat4(r, B1 + rb);
                    bl[nt2 * 2][0] = r[0]; bl[nt2 * 2][1] = r[1];
                    bl[nt2 * 2 + 1][0] = r[2]; bl[nt2 * 2 + 1][1] = r[3];
                }
#pragma unroll
                for (int mt = 0; mt < 2; mt++)
#pragma unroll
                    for (int nt = 0; nt < 4; nt++) {
                        float* a = acc[mt][nh * 4 + nt];
                        mma_f16(a, ah[mt], bh[nt]);
                        mma_f16(a, ah[mt], bl[nt]);
                    }
            }
        }
        __syncthreads();
    }

#pragma unroll
    for (int mt = 0; mt < 2; mt++) {
        int rg0 = row0 + wm * 32 + mt * 16 + (lane >> 2);
#pragma unroll
        for (int nt = 0; nt < 8; nt++) {
            int cg = col0 + wn * 64 + nt * 8 + (lane & 3) * 2;
            *(float2*)(C + (size_t)rg0 * N + cg) =
                make_float2(acc[mt][nt][0], acc[mt][nt][1]);
            *(float2*)(C + (size_t)(rg0 + 8) * N + cg) =
                make_float2(acc[mt][nt][2], acc[mt][nt][3]);
        }
    }
}

// ---------------- Gemma RMSNorm over contiguous 256-float rows -------------
__global__ __launch_bounds__(256) void rmsnorm_kernel(
    float* __restrict__ buf, const float* __restrict__ scale)
{
    int row = blockIdx.x;
    int d = threadIdx.x;
    float* p = buf + (size_t)row * HD;
    float x = p[d];
    float v = x * x;
#pragma unroll
    for (int o = 16; o > 0; o >>= 1) v += __shfl_xor_sync(0xffffffffu, v, o);
    __shared__ float ws[8];
    __shared__ float stot;
    if ((d & 31) == 0) ws[d >> 5] = v;
    __syncthreads();
    if (d == 0) {
        float s = 0.f;
#pragma unroll
        for (int i = 0; i < 8; i++) s += ws[i];
        stot = s;
    }
    __syncthreads();
    float r = rsqrtf(stot * (1.f / HD) + 1e-6f);
    p[d] = x * r * (1.f + scale[d]);
}

// ---------------- tensor-core flash attention -------------------------------
// 64 q x 64 k tiles, fp16 HMMA with fp32 accum, online softmax in fp32.
// Output written as fp16 directly into g_aoh (the O-proj A operand).
// smem layout (bytes):
#define AQP 528                       // half pitch 264 * 2
#define A_QB 0
#define A_KB (A_QB + 64 * AQP)        // 33792
#define A_VB (A_KB + 64 * AQP)        // 67584
#define A_SB (A_VB + 64 * AQP)        // 101376, fp32 scores pitch 66
#define A_PB (A_SB + 64 * 66 * 4)     // 118272, fp16 P pitch 72 (144 B)
#define A_MB (A_PB + 64 * 144)        // 127488 msm
#define A_LB (A_MB + 256)             // lsm
#define A_AB (A_LB + 256)             // arow
#define A_TOT (A_AB + 256)            // 128256

__global__ __launch_bounds__(256, 1) void attn_mma_kernel()
{
    extern __shared__ char sm[];
    uint32_t sb = smem_u32(sm);
    float* Sf   = (float*)(sm + A_SB);
    __half* Ph  = (__half*)(sm + A_PB);
    float* msm  = (float*)(sm + A_MB);
    float* lsm  = (float*)(sm + A_LB);
    float* arow = (float*)(sm + A_AB);

    int tid = threadIdx.x, lane = tid & 31, wid = tid >> 5;
    int wq = wid & 3, wn = wid >> 2;   // 4 m-warps x 2 n-warps
    int qt = blockIdx.x, h = blockIdx.y, b = blockIdx.z;
    int t0 = qt * 64;
    int kvh = h & (Gg - 1);

    // ---- load Q tile -> fp16 smem (scale folded) ----
    const float* qbase = g_q + ((size_t)(b * Tt + t0)) * NQ + h * HD;
    for (int idx = tid; idx < 64 * 64; idx += 256) {
        int r = idx >> 6, c = idx & 63;
        float4 v = *(const float4*)(qbase + (size_t)r * NQ + c * 4);
        __half2 h0 = __floats2half2_rn(v.x * QK_SCALE, v.y * QK_SCALE);
        __half2 h1 = __floats2half2_rn(v.z * QK_SCALE, v.w * QK_SCALE);
        *(uint2*)(sm + A_QB + r * AQP + c * 8) =
            make_uint2(*(uint32_t*)&h0, *(uint32_t*)&h1);
    }
    if (tid < 64) { msm[tid] = -1e30f; lsm[tid] = 0.f; }

    float o[16][4];
#pragma unroll
    for (int f = 0; f < 16; f++)
#pragma unroll
        for (int i = 0; i < 4; i++) o[f][i] = 0.f;

    int grp = lane >> 3, lr = lane & 7;
    uint32_t aoff = (uint32_t)(((grp & 1) * 8 + lr) * AQP + (grp >> 1) * 16);
    uint32_t boff = (uint32_t)(((grp >> 1) * 8 + lr) * AQP + (grp & 1) * 16);
    uint32_t poff = (uint32_t)(((grp & 1) * 8 + lr) * 144 + (grp >> 1) * 16);

    int row_m = wq * 16 + (lane >> 2);   // this thread's first m-row

    int kb0 = max(0, t0 - (WINDOW - 1)) >> 6;
    int kb1 = (t0 + 63) >> 6;

    for (int kb = kb0; kb <= kb1; kb++) {
        int s0 = kb * 64;
        __syncthreads();

        // ---- load K,V tiles -> fp16 smem ----
        const float* kbase = g_k + ((size_t)(b * Tt + s0)) * NKV + kvh * HD;
        const float* vbase = g_v + ((size_t)(b * Tt + s0)) * NKV + kvh * HD;
        for (int idx = tid; idx < 64 * 64; idx += 256) {
            int r = idx >> 6, c = idx & 63;
            float4 kv = *(const float4*)(kbase + (size_t)r * NKV + c * 4);
            __half2 k0 = __floats2half2_rn(kv.x, kv.y);
            __half2 k1 = __floats2half2_rn(kv.z, kv.w);
            *(uint2*)(sm + A_KB + r * AQP + c * 8) =
                make_uint2(*(uint32_t*)&k0, *(uint32_t*)&k1);
            float4 vv = *(const float4*)(vbase + (size_t)r * NKV + c * 4);
            __half2 v0 = __floats2half2_rn(vv.x, vv.y);
            __half2 v1 = __floats2half2_rn(vv.z, vv.w);
            *(uint2*)(sm + A_VB + r * AQP + c * 8) =
                make_uint2(*(uint32_t*)&v0, *(uint32_t*)&v1);
        }
        __syncthreads();

        // ---- QK: warp computes 16q x 32k ----
        {
            float sc[4][4];
#pragma unroll
            for (int j = 0; j < 4; j++)
#pragma unroll
                for (int i = 0; i < 4; i++) sc[j][i] = 0.f;
#pragma unroll 4
            for (int kd = 0; kd < 16; kd++) {
                uint32_t a[4];
                ldmat4(a, sb + A_QB + (uint32_t)(wq * 16) * AQP + kd * 32 + aoff);
                uint32_t bf0[4], bf1[4];
                ldmat4(bf0, sb + A_KB + (uint32_t)(wn * 32) * AQP + kd * 32 + boff);
                ldmat4(bf1, sb + A_KB + (uint32_t)(wn * 32 + 16) * AQP + kd * 32 + boff);
                mma_f16(sc[0], a, &bf0[0]);
                mma_f16(sc[1], a, &bf0[2]);
                mma_f16(sc[2], a, &bf1[0]);
                mma_f16(sc[3], a, &bf1[2]);
            }
            int cb = wn * 32 + (lane & 3) * 2;
#pragma unroll
            for (int j = 0; j < 4; j++) {
                *(float2*)(Sf + row_m * 66 + cb + 8 * j) =
                    make_float2(sc[j][0], sc[j][1]);
                *(float2*)(Sf + (row_m + 8) * 66 + cb + 8 * j) =
                    make_float2(sc[j][2], sc[j][3]);
            }
        }
        __syncthreads();

        // ---- softmax (one thread per q row) ----
        if (tid < 64) {
            int row = tid;
            int tq = t0 + row;
            int jlo = (tq - (WINDOW - 1)) - s0;
            int jhi = tq - s0;
            if (jhi > 63) jhi = 63;
            if (jlo < 0) jlo = 0;
            const float* srow = Sf + row * 66;
            float m0 = msm[row];
            float mnew = m0;
            for (int j = jlo; j <= jhi; j++) mnew = fmaxf(mnew, srow[j]);
            float alpha = __expf(m0 - mnew);
            float sum = 0.f;
            __half* prow = Ph + row * 72;
#pragma unroll 8
            for (int j = 0; j < 64; j += 2) {
                float p0 = 0.f, p1 = 0.f;
                if (j >= jlo && j <= jhi)     p0 = __expf(srow[j] - mnew);
                if (j + 1 >= jlo && j + 1 <= jhi) p1 = __expf(srow[j + 1] - mnew);
                *(__half2*)(prow + j) = __floats2half2_rn(p0, p1);
                sum += p0 + p1;
            }
            lsm[row] = lsm[row] * alpha + sum;
            msm[row] = mnew;
            arow[row] = alpha;
        }
        __syncthreads();

        // ---- rescale O, then PV: warp computes 16q x 128d ----
        {
            float a0 = arow[row_m], a1 = arow[row_m + 8];
#pragma unroll
            for (int f = 0; f < 16; f++) {
                o[f][0] *= a0; o[f][1] *= a0;
                o[f][2] *= a1; o[f][3] *= a1;
            }
#pragma unroll
            for (int kk = 0; kk < 4; kk++) {
                uint32_t pa[4];
                ldmat4(pa, sb + A_PB + (uint32_t)(wq * 16) * 144 + kk * 32 + poff);
#pragma unroll
                for (int nb = 0; nb < 8; nb++) {
                    uint32_t bv[4];
                    ldmat4t(bv, sb + A_VB + (uint32_t)(kk * 16) * AQP
                                + (uint32_t)(wn * 256 + nb * 32) + aoff);
                    mma_f16(o[nb * 2],     pa, &bv[0]);
                    mma_f16(o[nb * 2 + 1], pa, &bv[2]);
                }
            }
        }
    }

    __syncthreads();
    // ---- epilogue: O / l -> g_aoh (fp16) ----
    float il0 = 1.f / lsm[row_m];
    float il1 = 1.f / lsm[row_m + 8];
    __half* obase = g_aoh + ((size_t)(b * Tt + t0)) * NQ + h * HD;
#pragma unroll
    for (int f = 0; f < 16; f++) {
        int nb = f >> 1, t = f & 1;
        int col = wn * 128 + nb * 16 + t * 8 + (lane & 3) * 2;
        __half2 h0 = __floats2half2_rn(o[f][0] * il0, o[f][1] * il0);
        __half2 h1 = __floats2half2_rn(o[f][2] * il1, o[f][3] * il1);
        *(__half2*)(obase + (size_t)row_m * NQ + col) = h0;
        *(__half2*)(obase + (size_t)(row_m + 8) * NQ + col) = h1;
    }
}

// ---------------- launch ----------------------------------------------------
extern "C" void kernel_launch(void* const* d_in, const int* in_sizes, int n_in,
                              void* d_out, int out_size)
{
    const float* x   = (const float*)d_in[0];
    const float* Wq  = (const float*)d_in[1];
    const float* Wk  = (const float*)d_in[2];
    const float* Wv  = (const float*)d_in[3];
    const float* Wo  = (const float*)d_in[4];
    const float* qsc = (const float*)d_in[5];
    const float* ksc = (const float*)d_in[6];
    float* out = (float*)d_out;

    void *pq, *pk, *pv, *pxh, *paoh;
    void *pwqh, *pwql, *pwkh, *pwkl, *pwvh, *pwvl, *pwoh, *pwol;
    cudaGetSymbolAddress(&pq, g_q);   cudaGetSymbolAddress(&pk, g_k);
    cudaGetSymbolAddress(&pv, g_v);
    cudaGetSymbolAddress(&pxh, g_xh); cudaGetSymbolAddress(&paoh, g_aoh);
    cudaGetSymbolAddress(&pwqh, g_wqhi); cudaGetSymbolAddress(&pwql, g_wqlo);
    cudaGetSymbolAddress(&pwkh, g_wkhi); cudaGetSymbolAddress(&pwkl, g_wklo);
    cudaGetSymbolAddress(&pwvh, g_wvhi); cudaGetSymbolAddress(&pwvl, g_wvlo);
    cudaGetSymbolAddress(&pwoh, g_wohi); cudaGetSymbolAddress(&pwol, g_wolo);

    float* dq  = (float*)pq;  float* dk = (float*)pk;  float* dv = (float*)pv;
    __half* xh  = (__half*)pxh;  __half* aoh = (__half*)paoh;
    __half* wqh = (__half*)pwqh; __half* wql = (__half*)pwql;
    __half* wkh = (__half*)pwkh; __half* wkl = (__half*)pwkl;
    __half* wvh = (__half*)pwvh; __half* wvl = (__half*)pwvl;
    __half* woh = (__half*)pwoh; __half* wol = (__half*)pwol;

    size_t gemm_smem = 2 * STAGEB;  // 61440
    cudaFuncSetAttribute(mma_gemm_kernel,
                         cudaFuncAttributeMaxDynamicSharedMemorySize, (int)gemm_smem);
    cudaFuncSetAttribute(attn_mma_kernel,
                         cudaFuncAttributeMaxDynamicSharedMemorySize, A_TOT);

    // ---- splits for Q/K/V projections ----
    {
        int n4 = (MROWS * Dd) / 4;
        tohalf_kernel<<<(n4 + 255) / 256, 256>>>((const float4*)x, xh, n4);
        split_transpose_kernel<<<dim3(NQ / 32, Dd / 32), 256>>>(Wq, wqh, wql, Dd, NQ);
        split_transpose_kernel<<<dim3(NKV / 32, Dd / 32), 256>>>(Wk, wkh, wkl, Dd, NKV);
        split_transpose_kernel<<<dim3(NKV / 32, Dd / 32), 256>>>(Wv, wvh, wvl, Dd, NKV);
    }

    // ---- projections (tensor cores, fp16 2-pass) ----
    {
        dim3 blk(256);
        mma_gemm_kernel<<<dim3(NQ / 128,  MROWS / 128), blk, gemm_smem>>>(
            xh, wqh, wql, dq, MROWS, NQ, Dd);
        mma_gemm_kernel<<<dim3(NKV / 128, MROWS / 128), blk, gemm_smem>>>(
            xh, wkh, wkl, dk, MROWS, NKV, Dd);
        mma_gemm_kernel<<<dim3(NKV / 128, MROWS / 128), blk, gemm_smem>>>(
            xh, wvh, wvl, dv, MROWS, NKV, Dd);
    }

    // ---- qk-norm ----
    rmsnorm_kernel<<<MROWS * Hh, 256>>>(dq, qsc);
    rmsnorm_kernel<<<MROWS * Gg, 256>>>(dk, ksc);

    // ---- attention (tensor cores) ----
    {
        dim3 grid(Tt / 64, Hh, Bb);
        attn_mma_kernel<<<grid, 256, A_TOT>>>();
    }

    // ---- output projection (A = g_aoh written by attention) ----
    {
        split_transpose_kernel<<<dim3(Dd / 32, NQ / 32), 256>>>(Wo, woh, wol, NQ, Dd);
        mma_gemm_kernel<<<dim3(Dd / 128, MROWS / 128), 256, gemm_smem>>>(
            aoh, woh, wol, out, MROWS, Dd, NQ);
    }
}

// round 8
// speedup vs baseline: 2.8898x; 1.1016x over previous
#include <cuda_runtime.h>
#include <cuda_fp16.h>
#include <math.h>
#include <cstdint>

// ---------------- problem constants ----------------
#define Bb 2
#define Tt 2048
#define Dd 2560
#define Hh 8
#define Gg 4
#define HD 256
#define NQ (Hh*HD)     // 2048
#define NKV (Gg*HD)    // 1024
#define NQKV 4096      // 2048 q + 1024 k + 1024 v
#define MROWS (Bb*Tt)  // 4096
#define QK_SCALE 0.0625f
#define WINDOW 1024

// ---------------- scratch (static device globals; no allocation) -----------
__device__ float g_qkv[(size_t)MROWS * NQKV];                    // merged proj out
__device__ __align__(256) __half g_xh[(size_t)MROWS * Dd];       // A for QKV proj
__device__ __align__(256) __half g_qh[(size_t)MROWS * NQ];       // normed q (fp16, scaled)
__device__ __align__(256) __half g_kh[(size_t)MROWS * NKV];      // normed k (fp16)
__device__ __align__(256) __half g_vh[(size_t)MROWS * NKV];      // v (fp16)
__device__ __align__(256) __half g_aoh[(size_t)MROWS * NQ];      // attn out (fp16)
__device__ __align__(256) __half g_wfhi[(size_t)NQKV * Dd];      // [N,K] hi (Wq|Wk|Wv)
__device__ __align__(256) __half g_wflo[(size_t)NQKV * Dd];
__device__ __align__(256) __half g_wohi[(size_t)Dd * NQ];
__device__ __align__(256) __half g_wolo[(size_t)Dd * NQ];

// ---------------- helpers ----------------------------------------------------
__device__ __forceinline__ uint32_t smem_u32(const void* p) {
    uint32_t a;
    asm("{ .reg .u64 t; cvta.to.shared.u64 t, %1; cvt.u32.u64 %0, t; }"
        : "=r"(a) : "l"(p));
    return a;
}
__device__ __forceinline__ void cp_async16(uint32_t saddr, const void* gaddr) {
    asm volatile("cp.async.cg.shared.global [%0], [%1], 16;"
                 :: "r"(saddr), "l"(gaddr) : "memory");
}
__device__ __forceinline__ void ldmat4(uint32_t* r, uint32_t addr) {
    asm volatile("ldmatrix.sync.aligned.m8n8.x4.shared.b16 {%0,%1,%2,%3}, [%4];"
                 : "=r"(r[0]), "=r"(r[1]), "=r"(r[2]), "=r"(r[3]) : "r"(addr));
}
__device__ __forceinline__ void ldmat4t(uint32_t* r, uint32_t addr) {
    asm volatile("ldmatrix.sync.aligned.m8n8.x4.trans.shared.b16 {%0,%1,%2,%3}, [%4];"
                 : "=r"(r[0]), "=r"(r[1]), "=r"(r[2]), "=r"(r[3]) : "r"(addr));
}
__device__ __forceinline__ void mma_f16(float* c, const uint32_t* a, const uint32_t* b) {
    asm volatile(
        "mma.sync.aligned.m16n8k16.row.col.f32.f16.f16.f32 "
        "{%0,%1,%2,%3}, {%4,%5,%6,%7}, {%8,%9}, {%0,%1,%2,%3};"
        : "+f"(c[0]), "+f"(c[1]), "+f"(c[2]), "+f"(c[3])
        : "r"(a[0]), "r"(a[1]), "r"(a[2]), "r"(a[3]), "r"(b[0]), "r"(b[1]));
}

// ---------------- split kernels ---------------------------------------------
__global__ __launch_bounds__(256) void tohalf_kernel(
    const float4* __restrict__ in, __half* __restrict__ out, int n4)
{
    int i = blockIdx.x * 256 + threadIdx.x;
    if (i >= n4) return;
    float4 v = in[i];
    __half2* op = (__half2*)(out + (size_t)i * 4);
    op[0] = __half2(__float2half_rn(v.x), __float2half_rn(v.y));
    op[1] = __half2(__float2half_rn(v.z), __float2half_rn(v.w));
}

// in [K,N] fp32 -> out hi/lo [N,K] fp16
__global__ __launch_bounds__(256) void split_transpose_kernel(
    const float* __restrict__ in, __half* __restrict__ hi,
    __half* __restrict__ lo, int K, int N)
{
    __shared__ float t[32][33];
    int n0 = blockIdx.x * 32, k0 = blockIdx.y * 32;
    int tx = threadIdx.x & 31, ty = threadIdx.x >> 5;
#pragma unroll
    for (int i = 0; i < 32; i += 8)
        t[ty + i][tx] = in[(size_t)(k0 + ty + i) * N + n0 + tx];
    __syncthreads();
#pragma unroll
    for (int i = 0; i < 32; i += 8) {
        float a = t[tx][ty + i];
        __half h = __float2half_rn(a);
        __half l = __float2half_rn(a - __half2float(h));
        size_t o = (size_t)(n0 + ty + i) * K + k0 + tx;
        hi[o] = h; lo[o] = l;
    }
}

// ---------------- mma.sync fp16 2-pass GEMM ----------------------------------
#define GP 80
#define TILEB (128 * GP)
#define STAGEB (3 * TILEB)

__global__ __launch_bounds__(256, 2) void mma_gemm_kernel(
    const __half* __restrict__ A,
    const __half* __restrict__ Bhi, const __half* __restrict__ Blo,
    float* __restrict__ C, int M, int N, int K)
{
    extern __shared__ char smem[];
    uint32_t sb = smem_u32(smem);
    int tid = threadIdx.x, lane = tid & 31, wid = tid >> 5;
    int wm = wid & 3, wn = wid >> 2;
    int row0 = blockIdx.y * 128, col0 = blockIdx.x * 128;

    const __half* gsrc[3] = {
        A + (size_t)row0 * K,
        Bhi + (size_t)col0 * K, Blo + (size_t)col0 * K };

    const int NC = K >> 5;

    int r_ld0 = tid >> 2, c16_0 = tid & 3;
    int r_ld1 = (tid + 256) >> 2, c16_1 = (tid + 256) & 3;

    float acc[2][8][4];
#pragma unroll
    for (int mt = 0; mt < 2; mt++)
#pragma unroll
        for (int nt = 0; nt < 8; nt++)
#pragma unroll
            for (int i = 0; i < 4; i++) acc[mt][nt][i] = 0.f;

    int grp = lane >> 3, lr = lane & 7;
    uint32_t aoff = (uint32_t)(((grp & 1) * 8 + lr) * GP + (grp >> 1) * 16);
    uint32_t boff = (uint32_t)(((grp >> 1) * 8 + lr) * GP + (grp & 1) * 16);

    auto load_stage = [&](int c) {
        uint32_t st = sb + (uint32_t)(c & 1) * STAGEB;
        int kb = c * 32;
#pragma unroll
        for (int tile = 0; tile < 3; tile++) {
            const __half* g = gsrc[tile];
            uint32_t tb = st + (uint32_t)tile * TILEB;
            cp_async16(tb + (uint32_t)(r_ld0 * GP + c16_0 * 16),
                       g + (size_t)r_ld0 * K + kb + c16_0 * 8);
            cp_async16(tb + (uint32_t)(r_ld1 * GP + c16_1 * 16),
                       g + (size_t)r_ld1 * K + kb + c16_1 * 8);
        }
        asm volatile("cp.async.commit_group;" ::: "memory");
    };

    load_stage(0);

    for (int c = 0; c < NC; c++) {
        if (c + 1 < NC) {
            load_stage(c + 1);
            asm volatile("cp.async.wait_group 1;" ::: "memory");
        } else {
            asm volatile("cp.async.wait_group 0;" ::: "memory");
        }
        __syncthreads();

        uint32_t st = sb + (uint32_t)(c & 1) * STAGEB;
        uint32_t A0 = st, B0 = st + TILEB, B1 = st + 2 * TILEB;

#pragma unroll
        for (int kk = 0; kk < 2; kk++) {
            uint32_t kbyte = (uint32_t)kk * 32;
            uint32_t ah[2][4];
#pragma unroll
            for (int mt = 0; mt < 2; mt++) {
                uint32_t rb = (uint32_t)((wm * 32 + mt * 16) * GP) + aoff + kbyte;
                ldmat4(ah[mt], A0 + rb);
            }
#pragma unroll
            for (int nh = 0; nh < 2; nh++) {
                uint32_t bh[4][2], bl[4][2];
#pragma unroll
                for (int nt2 = 0; nt2 < 2; nt2++) {
                    uint32_t rb = (uint32_t)((wn * 64 + nh * 32 + nt2 * 16) * GP)
                                + boff + kbyte;
                    uint32_t r[4];
                    ldmat4(r, B0 + rb);
                    bh[nt2 * 2][0] = r[0]; bh[nt2 * 2][1] = r[1];
                    bh[nt2 * 2 + 1][0] = r[2]; bh[nt2 * 2 + 1][1] = r[3];
                    ldmat4(r, B1 + rb);
                    bl[nt2 * 2][0] = r[0]; bl[nt2 * 2][1] = r[1];
                    bl[nt2 * 2 + 1][0] = r[2]; bl[nt2 * 2 + 1][1] = r[3];
                }
#pragma unroll
                for (int mt = 0; mt < 2; mt++)
#pragma unroll
                    for (int nt = 0; nt < 4; nt++) {
                        float* a = acc[mt][nh * 4 + nt];
                        mma_f16(a, ah[mt], bh[nt]);
                        mma_f16(a, ah[mt], bl[nt]);
                    }
            }
        }
        __syncthreads();
    }

#pragma unroll
    for (int mt = 0; mt < 2; mt++) {
        int rg0 = row0 + wm * 32 + mt * 16 + (lane >> 2);
#pragma unroll
        for (int nt = 0; nt < 8; nt++) {
            int cg = col0 + wn * 64 + nt * 8 + (lane & 3) * 2;
            *(float2*)(C + (size_t)rg0 * N + cg) =
                make_float2(acc[mt][nt][0], acc[mt][nt][1]);
            *(float2*)(C + (size_t)(rg0 + 8) * N + cg) =
                make_float2(acc[mt][nt][2], acc[mt][nt][3]);
        }
    }
}

// ---------------- Gemma RMSNorm: g_qkv -> fp16 q (scaled) / k ---------------
// grid = MROWS * 12: blocks 0..7 = q heads, 8..11 = k heads per row
__global__ __launch_bounds__(256) void rmsnorm_qk_kernel(
    const float* __restrict__ qkv, const float* __restrict__ qsc,
    const float* __restrict__ ksc, __half* __restrict__ qh,
    __half* __restrict__ kh)
{
    int blk = blockIdx.x;
    int row = blk / 12, hh = blk % 12;
    int d = threadIdx.x;
    const float* p;
    const float* sc;
    __half* o;
    float osc;
    if (hh < 8) {
        p = qkv + (size_t)row * NQKV + hh * HD;
        o = qh + (size_t)row * NQ + hh * HD;
        sc = qsc; osc = QK_SCALE;
    } else {
        int g = hh - 8;
        p = qkv + (size_t)row * NQKV + NQ + g * HD;
        o = kh + (size_t)row * NKV + g * HD;
        sc = ksc; osc = 1.f;
    }
    float x = p[d];
    float v = x * x;
#pragma unroll
    for (int of = 16; of > 0; of >>= 1) v += __shfl_xor_sync(0xffffffffu, v, of);
    __shared__ float ws[8];
    __shared__ float stot;
    if ((d & 31) == 0) ws[d >> 5] = v;
    __syncthreads();
    if (d == 0) {
        float s = 0.f;
#pragma unroll
        for (int i = 0; i < 8; i++) s += ws[i];
        stot = s;
    }
    __syncthreads();
    float r = rsqrtf(stot * (1.f / HD) + 1e-6f);
    o[d] = __float2half_rn(x * r * (1.f + sc[d]) * osc);
}

// ---------------- extract V slice -> fp16 ------------------------------------
__global__ __launch_bounds__(256) void extract_v_kernel(
    const float* __restrict__ qkv, __half* __restrict__ vh)
{
    int row = blockIdx.x;
    int t = threadIdx.x;   // 256 threads * 4 floats = 1024
    float4 v = *(const float4*)(qkv + (size_t)row * NQKV + NQ + NKV + t * 4);
    __half2 h0 = __floats2half2_rn(v.x, v.y);
    __half2 h1 = __floats2half2_rn(v.z, v.w);
    *(uint2*)(vh + (size_t)row * NKV + t * 4) =
        make_uint2(*(uint32_t*)&h0, *(uint32_t*)&h1);
}

// ---------------- tensor-core flash attention -------------------------------
#define AQP 528
#define A_QB 0
#define A_KB (A_QB + 64 * AQP)
#define A_VB (A_KB + 64 * AQP)
#define A_SB (A_VB + 64 * AQP)
#define A_PB (A_SB + 64 * 66 * 4)
#define A_MB (A_PB + 64 * 144)
#define A_LB (A_MB + 256)
#define A_AB (A_LB + 256)
#define A_TOT (A_AB + 256)

__global__ __launch_bounds__(256, 1) void attn_mma_kernel()
{
    extern __shared__ char sm[];
    uint32_t sb = smem_u32(sm);
    float* Sf   = (float*)(sm + A_SB);
    __half* Ph  = (__half*)(sm + A_PB);
    float* msm  = (float*)(sm + A_MB);
    float* lsm  = (float*)(sm + A_LB);
    float* arow = (float*)(sm + A_AB);

    int tid = threadIdx.x, lane = tid & 31, wid = tid >> 5;
    int wq = wid & 3, wn = wid >> 2;
    int qt = blockIdx.x, h = blockIdx.y, b = blockIdx.z;
    int t0 = qt * 64;
    int kvh = h & (Gg - 1);

    // ---- load Q tile (fp16, already scaled) ----
    const __half* qbase = g_qh + ((size_t)(b * Tt + t0)) * NQ + h * HD;
    for (int idx = tid; idx < 64 * 32; idx += 256) {
        int r = idx >> 5, c = idx & 31;
        *(uint4*)(sm + A_QB + r * AQP + c * 16) =
            *(const uint4*)(qbase + (size_t)r * NQ + c * 8);
    }
    if (tid < 64) { msm[tid] = -1e30f; lsm[tid] = 0.f; }

    float o[16][4];
#pragma unroll
    for (int f = 0; f < 16; f++)
#pragma unroll
        for (int i = 0; i < 4; i++) o[f][i] = 0.f;

    int grp = lane >> 3, lr = lane & 7;
    uint32_t aoff = (uint32_t)(((grp & 1) * 8 + lr) * AQP + (grp >> 1) * 16);
    uint32_t boff = (uint32_t)(((grp >> 1) * 8 + lr) * AQP + (grp & 1) * 16);
    uint32_t poff = (uint32_t)(((grp & 1) * 8 + lr) * 144 + (grp >> 1) * 16);

    int row_m = wq * 16 + (lane >> 2);

    int kb0 = max(0, t0 - (WINDOW - 1)) >> 6;
    int kb1 = (t0 + 63) >> 6;

    for (int kb = kb0; kb <= kb1; kb++) {
        int s0 = kb * 64;
        __syncthreads();

        // ---- load K,V tiles (fp16 direct copy) ----
        const __half* kbase = g_kh + ((size_t)(b * Tt + s0)) * NKV + kvh * HD;
        const __half* vbase = g_vh + ((size_t)(b * Tt + s0)) * NKV + kvh * HD;
        for (int idx = tid; idx < 64 * 32; idx += 256) {
            int r = idx >> 5, c = idx & 31;
            *(uint4*)(sm + A_KB + r * AQP + c * 16) =
                *(const uint4*)(kbase + (size_t)r * NKV + c * 8);
            *(uint4*)(sm + A_VB + r * AQP + c * 16) =
                *(const uint4*)(vbase + (size_t)r * NKV + c * 8);
        }
        __syncthreads();

        // ---- QK: warp computes 16q x 32k ----
        {
            float sc[4][4];
#pragma unroll
            for (int j = 0; j < 4; j++)
#pragma unroll
                for (int i = 0; i < 4; i++) sc[j][i] = 0.f;
#pragma unroll 4
            for (int kd = 0; kd < 16; kd++) {
                uint32_t a[4];
                ldmat4(a, sb + A_QB + (uint32_t)(wq * 16) * AQP + kd * 32 + aoff);
                uint32_t bf0[4], bf1[4];
                ldmat4(bf0, sb + A_KB + (uint32_t)(wn * 32) * AQP + kd * 32 + boff);
                ldmat4(bf1, sb + A_KB + (uint32_t)(wn * 32 + 16) * AQP + kd * 32 + boff);
                mma_f16(sc[0], a, &bf0[0]);
                mma_f16(sc[1], a, &bf0[2]);
                mma_f16(sc[2], a, &bf1[0]);
                mma_f16(sc[3], a, &bf1[2]);
            }
            int cb = wn * 32 + (lane & 3) * 2;
#pragma unroll
            for (int j = 0; j < 4; j++) {
                *(float2*)(Sf + row_m * 66 + cb + 8 * j) =
                    make_float2(sc[j][0], sc[j][1]);
                *(float2*)(Sf + (row_m + 8) * 66 + cb + 8 * j) =
                    make_float2(sc[j][2], sc[j][3]);
            }
        }
        __syncthreads();

        // ---- softmax (one thread per q row) ----
        if (tid < 64) {
            int row = tid;
            int tq = t0 + row;
            int jlo = (tq - (WINDOW - 1)) - s0;
            int jhi = tq - s0;
            if (jhi > 63) jhi = 63;
            if (jlo < 0) jlo = 0;
            const float* srow = Sf + row * 66;
            float m0 = msm[row];
            float mnew = m0;
            for (int j = jlo; j <= jhi; j++) mnew = fmaxf(mnew, srow[j]);
            float alpha = __expf(m0 - mnew);
            float sum = 0.f;
            __half* prow = Ph + row * 72;
#pragma unroll 8
            for (int j = 0; j < 64; j += 2) {
                float p0 = 0.f, p1 = 0.f;
                if (j >= jlo && j <= jhi)         p0 = __expf(srow[j] - mnew);
                if (j + 1 >= jlo && j + 1 <= jhi) p1 = __expf(srow[j + 1] - mnew);
                *(__half2*)(prow + j) = __floats2half2_rn(p0, p1);
                sum += p0 + p1;
            }
            lsm[row] = lsm[row] * alpha + sum;
            msm[row] = mnew;
            arow[row] = alpha;
        }
        __syncthreads();

        // ---- rescale O, then PV ----
        {
            float a0 = arow[row_m], a1 = arow[row_m + 8];
#pragma unroll
            for (int f = 0; f < 16; f++) {
                o[f][0] *= a0; o[f][1] *= a0;
                o[f][2] *= a1; o[f][3] *= a1;
            }
#pragma unroll
            for (int kk = 0; kk < 4; kk++) {
                uint32_t pa[4];
                ldmat4(pa, sb + A_PB + (uint32_t)(wq * 16) * 144 + kk * 32 + poff);
#pragma unroll
                for (int nb = 0; nb < 8; nb++) {
                    uint32_t bv[4];
                    ldmat4t(bv, sb + A_VB + (uint32_t)(kk * 16) * AQP
                                + (uint32_t)(wn * 256 + nb * 32) + aoff);
                    mma_f16(o[nb * 2],     pa, &bv[0]);
                    mma_f16(o[nb * 2 + 1], pa, &bv[2]);
                }
            }
        }
    }

    __syncthreads();
    float il0 = 1.f / lsm[row_m];
    float il1 = 1.f / lsm[row_m + 8];
    __half* obase = g_aoh + ((size_t)(b * Tt + t0)) * NQ + h * HD;
#pragma unroll
    for (int f = 0; f < 16; f++) {
        int nb = f >> 1, t = f & 1;
        int col = wn * 128 + nb * 16 + t * 8 + (lane & 3) * 2;
        __half2 h0 = __floats2half2_rn(o[f][0] * il0, o[f][1] * il0);
        __half2 h1 = __floats2half2_rn(o[f][2] * il1, o[f][3] * il1);
        *(__half2*)(obase + (size_t)row_m * NQ + col) = h0;
        *(__half2*)(obase + (size_t)(row_m + 8) * NQ + col) = h1;
    }
}

// ---------------- launch ----------------------------------------------------
extern "C" void kernel_launch(void* const* d_in, const int* in_sizes, int n_in,
                              void* d_out, int out_size)
{
    const float* x   = (const float*)d_in[0];
    const float* Wq  = (const float*)d_in[1];
    const float* Wk  = (const float*)d_in[2];
    const float* Wv  = (const float*)d_in[3];
    const float* Wo  = (const float*)d_in[4];
    const float* qsc = (const float*)d_in[5];
    const float* ksc = (const float*)d_in[6];
    float* out = (float*)d_out;

    void *pqkv, *pxh, *pqh, *pkh, *pvh, *paoh;
    void *pwfh, *pwfl, *pwoh, *pwol;
    cudaGetSymbolAddress(&pqkv, g_qkv);
    cudaGetSymbolAddress(&pxh, g_xh);
    cudaGetSymbolAddress(&pqh, g_qh);
    cudaGetSymbolAddress(&pkh, g_kh);
    cudaGetSymbolAddress(&pvh, g_vh);
    cudaGetSymbolAddress(&paoh, g_aoh);
    cudaGetSymbolAddress(&pwfh, g_wfhi);
    cudaGetSymbolAddress(&pwfl, g_wflo);
    cudaGetSymbolAddress(&pwoh, g_wohi);
    cudaGetSymbolAddress(&pwol, g_wolo);

    float* dqkv = (float*)pqkv;
    __half* xh  = (__half*)pxh;
    __half* qh  = (__half*)pqh;
    __half* kh  = (__half*)pkh;
    __half* vh  = (__half*)pvh;
    __half* aoh = (__half*)paoh;
    __half* wfh = (__half*)pwfh; __half* wfl = (__half*)pwfl;
    __half* woh = (__half*)pwoh; __half* wol = (__half*)pwol;

    size_t gemm_smem = 2 * STAGEB;  // 61440
    cudaFuncSetAttribute(mma_gemm_kernel,
                         cudaFuncAttributeMaxDynamicSharedMemorySize, (int)gemm_smem);
    cudaFuncSetAttribute(attn_mma_kernel,
                         cudaFuncAttributeMaxDynamicSharedMemorySize, A_TOT);

    // ---- operand prep ----
    {
        int n4 = (MROWS * Dd) / 4;
        tohalf_kernel<<<(n4 + 255) / 256, 256>>>((const float4*)x, xh, n4);
        // concat Wq|Wk|Wv rows into wf
        split_transpose_kernel<<<dim3(NQ / 32, Dd / 32), 256>>>(
            Wq, wfh, wfl, Dd, NQ);
        split_transpose_kernel<<<dim3(NKV / 32, Dd / 32), 256>>>(
            Wk, wfh + (size_t)NQ * Dd, wfl + (size_t)NQ * Dd, Dd, NKV);
        split_transpose_kernel<<<dim3(NKV / 32, Dd / 32), 256>>>(
            Wv, wfh + (size_t)(NQ + NKV) * Dd, wfl + (size_t)(NQ + NKV) * Dd, Dd, NKV);
        split_transpose_kernel<<<dim3(Dd / 32, NQ / 32), 256>>>(Wo, woh, wol, NQ, Dd);
    }

    // ---- merged QKV projection ----
    mma_gemm_kernel<<<dim3(NQKV / 128, MROWS / 128), 256, gemm_smem>>>(
        xh, wfh, wfl, dqkv, MROWS, NQKV, Dd);

    // ---- qk-norm -> fp16, V extract -> fp16 ----
    rmsnorm_qk_kernel<<<MROWS * 12, 256>>>(dqkv, qsc, ksc, qh, kh);
    extract_v_kernel<<<MROWS, 256>>>(dqkv, vh);

    // ---- attention (tensor cores) ----
    {
        dim3 grid(Tt / 64, Hh, Bb);
        attn_mma_kernel<<<grid, 256, A_TOT>>>();
    }

    // ---- output projection ----
    mma_gemm_kernel<<<dim3(Dd / 128, MROWS / 128), 256, gemm_smem>>>(
        aoh, woh, wol, out, MROWS, Dd, NQ);
}

// round 9
// speedup vs baseline: 3.4238x; 1.1848x over previous
#include <cuda_runtime.h>
#include <cuda_fp16.h>
#include <math.h>
#include <cstdint>

// ---------------- problem constants ----------------
#define Bb 2
#define Tt 2048
#define Dd 2560
#define Hh 8
#define Gg 4
#define HD 256
#define NQ (Hh*HD)     // 2048
#define NKV (Gg*HD)    // 1024
#define NQKV 4096
#define MROWS (Bb*Tt)  // 4096
#define QK_SCALE 0.0625f
#define WINDOW 1024

// ---------------- scratch ----------------------------------------------------
__device__ float g_qkv[(size_t)MROWS * NQKV];
__device__ __align__(256) __half g_xh[(size_t)MROWS * Dd];
__device__ __align__(256) __half g_qh[(size_t)MROWS * NQ];
__device__ __align__(256) __half g_kh[(size_t)MROWS * NKV];
__device__ __align__(256) __half g_vh[(size_t)MROWS * NKV];
__device__ __align__(256) __half g_aoh[(size_t)MROWS * NQ];
__device__ __align__(256) __half g_wfhi[(size_t)NQKV * Dd];
__device__ __align__(256) __half g_wflo[(size_t)NQKV * Dd];
__device__ __align__(256) __half g_wohi[(size_t)Dd * NQ];

// ---------------- helpers ----------------------------------------------------
__device__ __forceinline__ uint32_t smem_u32(const void* p) {
    uint32_t a;
    asm("{ .reg .u64 t; cvta.to.shared.u64 t, %1; cvt.u32.u64 %0, t; }"
        : "=r"(a) : "l"(p));
    return a;
}
__device__ __forceinline__ void cp_async16(uint32_t saddr, const void* gaddr) {
    asm volatile("cp.async.cg.shared.global [%0], [%1], 16;"
                 :: "r"(saddr), "l"(gaddr) : "memory");
}
__device__ __forceinline__ void ldmat4(uint32_t* r, uint32_t addr) {
    asm volatile("ldmatrix.sync.aligned.m8n8.x4.shared.b16 {%0,%1,%2,%3}, [%4];"
                 : "=r"(r[0]), "=r"(r[1]), "=r"(r[2]), "=r"(r[3]) : "r"(addr));
}
__device__ __forceinline__ void ldmat4t(uint32_t* r, uint32_t addr) {
    asm volatile("ldmatrix.sync.aligned.m8n8.x4.trans.shared.b16 {%0,%1,%2,%3}, [%4];"
                 : "=r"(r[0]), "=r"(r[1]), "=r"(r[2]), "=r"(r[3]) : "r"(addr));
}
__device__ __forceinline__ void mma_f16(float* c, const uint32_t* a, const uint32_t* b) {
    asm volatile(
        "mma.sync.aligned.m16n8k16.row.col.f32.f16.f16.f32 "
        "{%0,%1,%2,%3}, {%4,%5,%6,%7}, {%8,%9}, {%0,%1,%2,%3};"
        : "+f"(c[0]), "+f"(c[1]), "+f"(c[2]), "+f"(c[3])
        : "r"(a[0]), "r"(a[1]), "r"(a[2]), "r"(a[3]), "r"(b[0]), "r"(b[1]));
}

// ---------------- prep kernels ------------------------------------------------
__global__ __launch_bounds__(256) void tohalf_kernel(
    const float4* __restrict__ in, __half* __restrict__ out, int n4)
{
    int i = blockIdx.x * 256 + threadIdx.x;
    if (i >= n4) return;
    float4 v = in[i];
    __half2* op = (__half2*)(out + (size_t)i * 4);
    op[0] = __half2(__float2half_rn(v.x), __float2half_rn(v.y));
    op[1] = __half2(__float2half_rn(v.z), __float2half_rn(v.w));
}

// in [K,N] fp32 -> out hi/lo [N,K] fp16
__global__ __launch_bounds__(256) void split_transpose_kernel(
    const float* __restrict__ in, __half* __restrict__ hi,
    __half* __restrict__ lo, int K, int N)
{
    __shared__ float t[32][33];
    int n0 = blockIdx.x * 32, k0 = blockIdx.y * 32;
    int tx = threadIdx.x & 31, ty = threadIdx.x >> 5;
#pragma unroll
    for (int i = 0; i < 32; i += 8)
        t[ty + i][tx] = in[(size_t)(k0 + ty + i) * N + n0 + tx];
    __syncthreads();
#pragma unroll
    for (int i = 0; i < 32; i += 8) {
        float a = t[tx][ty + i];
        __half h = __float2half_rn(a);
        __half l = __float2half_rn(a - __half2float(h));
        size_t o = (size_t)(n0 + ty + i) * K + k0 + tx;
        hi[o] = h; lo[o] = l;
    }
}

// in [K,N] fp32 -> out [N,K] fp16 (hi only)
__global__ __launch_bounds__(256) void transpose_half_kernel(
    const float* __restrict__ in, __half* __restrict__ hi, int K, int N)
{
    __shared__ float t[32][33];
    int n0 = blockIdx.x * 32, k0 = blockIdx.y * 32;
    int tx = threadIdx.x & 31, ty = threadIdx.x >> 5;
#pragma unroll
    for (int i = 0; i < 32; i += 8)
        t[ty + i][tx] = in[(size_t)(k0 + ty + i) * N + n0 + tx];
    __syncthreads();
#pragma unroll
    for (int i = 0; i < 32; i += 8)
        hi[(size_t)(n0 + ty + i) * K + k0 + tx] = __float2half_rn(t[tx][ty + i]);
}

// ---------------- mma.sync fp16 2-pass GEMM (QKV) -----------------------------
#define GP 80
#define TILEB (128 * GP)
#define STAGEB (3 * TILEB)

__global__ __launch_bounds__(256, 2) void mma_gemm_kernel(
    const __half* __restrict__ A,
    const __half* __restrict__ Bhi, const __half* __restrict__ Blo,
    float* __restrict__ C, int M, int N, int K)
{
    extern __shared__ char smem[];
    uint32_t sb = smem_u32(smem);
    int tid = threadIdx.x, lane = tid & 31, wid = tid >> 5;
    int wm = wid & 3, wn = wid >> 2;
    int row0 = blockIdx.y * 128, col0 = blockIdx.x * 128;

    const __half* gsrc[3] = {
        A + (size_t)row0 * K,
        Bhi + (size_t)col0 * K, Blo + (size_t)col0 * K };

    const int NC = K >> 5;

    int r_ld0 = tid >> 2, c16_0 = tid & 3;
    int r_ld1 = (tid + 256) >> 2, c16_1 = (tid + 256) & 3;

    float acc[2][8][4];
#pragma unroll
    for (int mt = 0; mt < 2; mt++)
#pragma unroll
        for (int nt = 0; nt < 8; nt++)
#pragma unroll
            for (int i = 0; i < 4; i++) acc[mt][nt][i] = 0.f;

    int grp = lane >> 3, lr = lane & 7;
    uint32_t aoff = (uint32_t)(((grp & 1) * 8 + lr) * GP + (grp >> 1) * 16);
    uint32_t boff = (uint32_t)(((grp >> 1) * 8 + lr) * GP + (grp & 1) * 16);

    auto load_stage = [&](int c) {
        uint32_t st = sb + (uint32_t)(c & 1) * STAGEB;
        int kb = c * 32;
#pragma unroll
        for (int tile = 0; tile < 3; tile++) {
            const __half* g = gsrc[tile];
            uint32_t tb = st + (uint32_t)tile * TILEB;
            cp_async16(tb + (uint32_t)(r_ld0 * GP + c16_0 * 16),
                       g + (size_t)r_ld0 * K + kb + c16_0 * 8);
            cp_async16(tb + (uint32_t)(r_ld1 * GP + c16_1 * 16),
                       g + (size_t)r_ld1 * K + kb + c16_1 * 8);
        }
        asm volatile("cp.async.commit_group;" ::: "memory");
    };

    load_stage(0);

    for (int c = 0; c < NC; c++) {
        if (c + 1 < NC) {
            load_stage(c + 1);
            asm volatile("cp.async.wait_group 1;" ::: "memory");
        } else {
            asm volatile("cp.async.wait_group 0;" ::: "memory");
        }
        __syncthreads();

        uint32_t st = sb + (uint32_t)(c & 1) * STAGEB;
        uint32_t A0 = st, B0 = st + TILEB, B1 = st + 2 * TILEB;

#pragma unroll
        for (int kk = 0; kk < 2; kk++) {
            uint32_t kbyte = (uint32_t)kk * 32;
            uint32_t ah[2][4];
#pragma unroll
            for (int mt = 0; mt < 2; mt++) {
                uint32_t rb = (uint32_t)((wm * 32 + mt * 16) * GP) + aoff + kbyte;
                ldmat4(ah[mt], A0 + rb);
            }
#pragma unroll
            for (int nh = 0; nh < 2; nh++) {
                uint32_t bh[4][2], bl[4][2];
#pragma unroll
                for (int nt2 = 0; nt2 < 2; nt2++) {
                    uint32_t rb = (uint32_t)((wn * 64 + nh * 32 + nt2 * 16) * GP)
                                + boff + kbyte;
                    uint32_t r[4];
                    ldmat4(r, B0 + rb);
                    bh[nt2 * 2][0] = r[0]; bh[nt2 * 2][1] = r[1];
                    bh[nt2 * 2 + 1][0] = r[2]; bh[nt2 * 2 + 1][1] = r[3];
                    ldmat4(r, B1 + rb);
                    bl[nt2 * 2][0] = r[0]; bl[nt2 * 2][1] = r[1];
                    bl[nt2 * 2 + 1][0] = r[2]; bl[nt2 * 2 + 1][1] = r[3];
                }
#pragma unroll
                for (int mt = 0; mt < 2; mt++)
#pragma unroll
                    for (int nt = 0; nt < 4; nt++) {
                        float* a = acc[mt][nh * 4 + nt];
                        mma_f16(a, ah[mt], bh[nt]);
                        mma_f16(a, ah[mt], bl[nt]);
                    }
            }
        }
        __syncthreads();
    }

#pragma unroll
    for (int mt = 0; mt < 2; mt++) {
        int rg0 = row0 + wm * 32 + mt * 16 + (lane >> 2);
#pragma unroll
        for (int nt = 0; nt < 8; nt++) {
            int cg = col0 + wn * 64 + nt * 8 + (lane & 3) * 2;
            *(float2*)(C + (size_t)rg0 * N + cg) =
                make_float2(acc[mt][nt][0], acc[mt][nt][1]);
            *(float2*)(C + (size_t)(rg0 + 8) * N + cg) =
                make_float2(acc[mt][nt][2], acc[mt][nt][3]);
        }
    }
}

// ---------------- mma.sync fp16 single-pass GEMM (O-proj) ---------------------
#define STAGEB2 (2 * TILEB)

__global__ __launch_bounds__(256, 2) void mma_gemm1_kernel(
    const __half* __restrict__ A, const __half* __restrict__ B,
    float* __restrict__ C, int M, int N, int K)
{
    extern __shared__ char smem[];
    uint32_t sb = smem_u32(smem);
    int tid = threadIdx.x, lane = tid & 31, wid = tid >> 5;
    int wm = wid & 3, wn = wid >> 2;
    int row0 = blockIdx.y * 128, col0 = blockIdx.x * 128;

    const __half* gsrc[2] = { A + (size_t)row0 * K, B + (size_t)col0 * K };

    const int NC = K >> 5;

    int r_ld0 = tid >> 2, c16_0 = tid & 3;
    int r_ld1 = (tid + 256) >> 2, c16_1 = (tid + 256) & 3;

    float acc[2][8][4];
#pragma unroll
    for (int mt = 0; mt < 2; mt++)
#pragma unroll
        for (int nt = 0; nt < 8; nt++)
#pragma unroll
            for (int i = 0; i < 4; i++) acc[mt][nt][i] = 0.f;

    int grp = lane >> 3, lr = lane & 7;
    uint32_t aoff = (uint32_t)(((grp & 1) * 8 + lr) * GP + (grp >> 1) * 16);
    uint32_t boff = (uint32_t)(((grp >> 1) * 8 + lr) * GP + (grp & 1) * 16);

    auto load_stage = [&](int c) {
        uint32_t st = sb + (uint32_t)(c & 1) * STAGEB2;
        int kb = c * 32;
#pragma unroll
        for (int tile = 0; tile < 2; tile++) {
            const __half* g = gsrc[tile];
            uint32_t tb = st + (uint32_t)tile * TILEB;
            cp_async16(tb + (uint32_t)(r_ld0 * GP + c16_0 * 16),
                       g + (size_t)r_ld0 * K + kb + c16_0 * 8);
            cp_async16(tb + (uint32_t)(r_ld1 * GP + c16_1 * 16),
                       g + (size_t)r_ld1 * K + kb + c16_1 * 8);
        }
        asm volatile("cp.async.commit_group;" ::: "memory");
    };

    load_stage(0);

    for (int c = 0; c < NC; c++) {
        if (c + 1 < NC) {
            load_stage(c + 1);
            asm volatile("cp.async.wait_group 1;" ::: "memory");
        } else {
            asm volatile("cp.async.wait_group 0;" ::: "memory");
        }
        __syncthreads();

        uint32_t st = sb + (uint32_t)(c & 1) * STAGEB2;
        uint32_t A0 = st, B0 = st + TILEB;

#pragma unroll
        for (int kk = 0; kk < 2; kk++) {
            uint32_t kbyte = (uint32_t)kk * 32;
            uint32_t ah[2][4], bh[8][2];
#pragma unroll
            for (int mt = 0; mt < 2; mt++) {
                uint32_t rb = (uint32_t)((wm * 32 + mt * 16) * GP) + aoff + kbyte;
                ldmat4(ah[mt], A0 + rb);
            }
#pragma unroll
            for (int nt2 = 0; nt2 < 4; nt2++) {
                uint32_t rb = (uint32_t)((wn * 64 + nt2 * 16) * GP) + boff + kbyte;
                uint32_t r[4];
                ldmat4(r, B0 + rb);
                bh[nt2 * 2][0] = r[0]; bh[nt2 * 2][1] = r[1];
                bh[nt2 * 2 + 1][0] = r[2]; bh[nt2 * 2 + 1][1] = r[3];
            }
#pragma unroll
            for (int mt = 0; mt < 2; mt++)
#pragma unroll
                for (int nt = 0; nt < 8; nt++)
                    mma_f16(acc[mt][nt], ah[mt], bh[nt]);
        }
        __syncthreads();
    }

#pragma unroll
    for (int mt = 0; mt < 2; mt++) {
        int rg0 = row0 + wm * 32 + mt * 16 + (lane >> 2);
#pragma unroll
        for (int nt = 0; nt < 8; nt++) {
            int cg = col0 + wn * 64 + nt * 8 + (lane & 3) * 2;
            *(float2*)(C + (size_t)rg0 * N + cg) =
                make_float2(acc[mt][nt][0], acc[mt][nt][1]);
            *(float2*)(C + (size_t)(rg0 + 8) * N + cg) =
                make_float2(acc[mt][nt][2], acc[mt][nt][3]);
        }
    }
}

// ---------------- Gemma RMSNorm: g_qkv -> fp16 q (scaled) / k -----------------
__global__ __launch_bounds__(256) void rmsnorm_qk_kernel(
    const float* __restrict__ qkv, const float* __restrict__ qsc,
    const float* __restrict__ ksc, __half* __restrict__ qh,
    __half* __restrict__ kh)
{
    int blk = blockIdx.x;
    int row = blk / 12, hh = blk % 12;
    int d = threadIdx.x;
    const float* p;
    const float* sc;
    __half* o;
    float osc;
    if (hh < 8) {
        p = qkv + (size_t)row * NQKV + hh * HD;
        o = qh + (size_t)row * NQ + hh * HD;
        sc = qsc; osc = QK_SCALE;
    } else {
        int g = hh - 8;
        p = qkv + (size_t)row * NQKV + NQ + g * HD;
        o = kh + (size_t)row * NKV + g * HD;
        sc = ksc; osc = 1.f;
    }
    float x = p[d];
    float v = x * x;
#pragma unroll
    for (int of = 16; of > 0; of >>= 1) v += __shfl_xor_sync(0xffffffffu, v, of);
    __shared__ float ws[8];
    __shared__ float stot;
    if ((d & 31) == 0) ws[d >> 5] = v;
    __syncthreads();
    if (d == 0) {
        float s = 0.f;
#pragma unroll
        for (int i = 0; i < 8; i++) s += ws[i];
        stot = s;
    }
    __syncthreads();
    float r = rsqrtf(stot * (1.f / HD) + 1e-6f);
    o[d] = __float2half_rn(x * r * (1.f + sc[d]) * osc);
}

__global__ __launch_bounds__(256) void extract_v_kernel(
    const float* __restrict__ qkv, __half* __restrict__ vh)
{
    int row = blockIdx.x;
    int t = threadIdx.x;
    float4 v = *(const float4*)(qkv + (size_t)row * NQKV + NQ + NKV + t * 4);
    __half2 h0 = __floats2half2_rn(v.x, v.y);
    __half2 h1 = __floats2half2_rn(v.z, v.w);
    *(uint2*)(vh + (size_t)row * NKV + t * 4) =
        make_uint2(*(uint32_t*)&h0, *(uint32_t*)&h1);
}

// ---------------- tensor-core flash attention ---------------------------------
#define AQP 528
#define A_QB 0
#define A_KB (A_QB + 64 * AQP)
#define A_VB (A_KB + 64 * AQP)
#define A_SB (A_VB + 64 * AQP)
#define A_PB (A_SB + 64 * 66 * 4)
#define A_MB (A_PB + 64 * 144)
#define A_LB (A_MB + 256)
#define A_AB (A_LB + 256)
#define A_TOT (A_AB + 256)

__global__ __launch_bounds__(256, 1) void attn_mma_kernel()
{
    extern __shared__ char sm[];
    uint32_t sb = smem_u32(sm);
    float* Sf   = (float*)(sm + A_SB);
    __half* Ph  = (__half*)(sm + A_PB);
    float* msm  = (float*)(sm + A_MB);
    float* lsm  = (float*)(sm + A_LB);
    float* arow = (float*)(sm + A_AB);

    int tid = threadIdx.x, lane = tid & 31, wid = tid >> 5;
    int wq = wid & 3, wn = wid >> 2;
    int qt = blockIdx.x, h = blockIdx.y, b = blockIdx.z;
    int t0 = qt * 64;
    int kvh = h & (Gg - 1);

    const __half* qbase = g_qh + ((size_t)(b * Tt + t0)) * NQ + h * HD;
    for (int idx = tid; idx < 64 * 32; idx += 256) {
        int r = idx >> 5, c = idx & 31;
        *(uint4*)(sm + A_QB + r * AQP + c * 16) =
            *(const uint4*)(qbase + (size_t)r * NQ + c * 8);
    }
    if (tid < 64) { msm[tid] = -1e30f; lsm[tid] = 0.f; }

    float o[16][4];
#pragma unroll
    for (int f = 0; f < 16; f++)
#pragma unroll
        for (int i = 0; i < 4; i++) o[f][i] = 0.f;

    int grp = lane >> 3, lr = lane & 7;
    uint32_t aoff = (uint32_t)(((grp & 1) * 8 + lr) * AQP + (grp >> 1) * 16);
    uint32_t boff = (uint32_t)(((grp >> 1) * 8 + lr) * AQP + (grp & 1) * 16);
    uint32_t poff = (uint32_t)(((grp & 1) * 8 + lr) * 144 + (grp >> 1) * 16);

    int row_m = wq * 16 + (lane >> 2);

    // softmax mapping: 4 threads per row, 16 cols each
    int sm_row = tid >> 2, sm_q = tid & 3;
    int sm_base = sm_q * 16;

    int kb0 = max(0, t0 - (WINDOW - 1)) >> 6;
    int kb1 = (t0 + 63) >> 6;

    for (int kb = kb0; kb <= kb1; kb++) {
        int s0 = kb * 64;
        __syncthreads();

        const __half* kbase = g_kh + ((size_t)(b * Tt + s0)) * NKV + kvh * HD;
        const __half* vbase = g_vh + ((size_t)(b * Tt + s0)) * NKV + kvh * HD;
        for (int idx = tid; idx < 64 * 32; idx += 256) {
            int r = idx >> 5, c = idx & 31;
            *(uint4*)(sm + A_KB + r * AQP + c * 16) =
                *(const uint4*)(kbase + (size_t)r * NKV + c * 8);
            *(uint4*)(sm + A_VB + r * AQP + c * 16) =
                *(const uint4*)(vbase + (size_t)r * NKV + c * 8);
        }
        __syncthreads();

        // ---- QK ----
        {
            float sc[4][4];
#pragma unroll
            for (int j = 0; j < 4; j++)
#pragma unroll
                for (int i = 0; i < 4; i++) sc[j][i] = 0.f;
#pragma unroll 4
            for (int kd = 0; kd < 16; kd++) {
                uint32_t a[4];
                ldmat4(a, sb + A_QB + (uint32_t)(wq * 16) * AQP + kd * 32 + aoff);
                uint32_t bf0[4], bf1[4];
                ldmat4(bf0, sb + A_KB + (uint32_t)(wn * 32) * AQP + kd * 32 + boff);
                ldmat4(bf1, sb + A_KB + (uint32_t)(wn * 32 + 16) * AQP + kd * 32 + boff);
                mma_f16(sc[0], a, &bf0[0]);
                mma_f16(sc[1], a, &bf0[2]);
                mma_f16(sc[2], a, &bf1[0]);
                mma_f16(sc[3], a, &bf1[2]);
            }
            int cb = wn * 32 + (lane & 3) * 2;
#pragma unroll
            for (int j = 0; j < 4; j++) {
                *(float2*)(Sf + row_m * 66 + cb + 8 * j) =
                    make_float2(sc[j][0], sc[j][1]);
                *(float2*)(Sf + (row_m + 8) * 66 + cb + 8 * j) =
                    make_float2(sc[j][2], sc[j][3]);
            }
        }
        __syncthreads();

        // ---- softmax: 4 threads per row ----
        {
            int tq = t0 + sm_row;
            int jlo = tq - (WINDOW - 1) - s0;
            int jhi = tq - s0;
            if (jhi > 63) jhi = 63;
            if (jlo < 0) jlo = 0;
            const float* srow = Sf + sm_row * 66;
            float mloc = -1e30f;
#pragma unroll
            for (int j = 0; j < 16; j++) {
                int jj = sm_base + j;
                if (jj >= jlo && jj <= jhi) mloc = fmaxf(mloc, srow[jj]);
            }
            mloc = fmaxf(mloc, __shfl_xor_sync(0xffffffffu, mloc, 1));
            mloc = fmaxf(mloc, __shfl_xor_sync(0xffffffffu, mloc, 2));
            float m0 = msm[sm_row];
            float mnew = fmaxf(m0, mloc);
            float sum = 0.f;
            __half* prow = Ph + sm_row * 72;
#pragma unroll
            for (int j = 0; j < 16; j += 2) {
                int j0 = sm_base + j, j1 = j0 + 1;
                float p0 = (j0 >= jlo && j0 <= jhi) ? __expf(srow[j0] - mnew) : 0.f;
                float p1 = (j1 >= jlo && j1 <= jhi) ? __expf(srow[j1] - mnew) : 0.f;
                *(__half2*)(prow + j0) = __floats2half2_rn(p0, p1);
                sum += p0 + p1;
            }
            sum += __shfl_xor_sync(0xffffffffu, sum, 1);
            sum += __shfl_xor_sync(0xffffffffu, sum, 2);
            if (sm_q == 0) {
                float alpha = __expf(m0 - mnew);
                lsm[sm_row] = lsm[sm_row] * alpha + sum;
                msm[sm_row] = mnew;
                arow[sm_row] = alpha;
            }
        }
        __syncthreads();

        // ---- rescale O, then PV ----
        {
            float a0 = arow[row_m], a1 = arow[row_m + 8];
#pragma unroll
            for (int f = 0; f < 16; f++) {
                o[f][0] *= a0; o[f][1] *= a0;
                o[f][2] *= a1; o[f][3] *= a1;
            }
#pragma unroll
            for (int kk = 0; kk < 4; kk++) {
                uint32_t pa[4];
                ldmat4(pa, sb + A_PB + (uint32_t)(wq * 16) * 144 + kk * 32 + poff);
#pragma unroll
                for (int nb = 0; nb < 8; nb++) {
                    uint32_t bv[4];
                    ldmat4t(bv, sb + A_VB + (uint32_t)(kk * 16) * AQP
                                + (uint32_t)(wn * 256 + nb * 32) + aoff);
                    mma_f16(o[nb * 2],     pa, &bv[0]);
                    mma_f16(o[nb * 2 + 1], pa, &bv[2]);
                }
            }
        }
    }

    __syncthreads();
    float il0 = 1.f / lsm[row_m];
    float il1 = 1.f / lsm[row_m + 8];
    __half* obase = g_aoh + ((size_t)(b * Tt + t0)) * NQ + h * HD;
#pragma unroll
    for (int f = 0; f < 16; f++) {
        int nb = f >> 1, t = f & 1;
        int col = wn * 128 + nb * 16 + t * 8 + (lane & 3) * 2;
        __half2 h0 = __floats2half2_rn(o[f][0] * il0, o[f][1] * il0);
        __half2 h1 = __floats2half2_rn(o[f][2] * il1, o[f][3] * il1);
        *(__half2*)(obase + (size_t)row_m * NQ + col) = h0;
        *(__half2*)(obase + (size_t)(row_m + 8) * NQ + col) = h1;
    }
}

// ---------------- launch -------------------------------------------------------
extern "C" void kernel_launch(void* const* d_in, const int* in_sizes, int n_in,
                              void* d_out, int out_size)
{
    const float* x   = (const float*)d_in[0];
    const float* Wq  = (const float*)d_in[1];
    const float* Wk  = (const float*)d_in[2];
    const float* Wv  = (const float*)d_in[3];
    const float* Wo  = (const float*)d_in[4];
    const float* qsc = (const float*)d_in[5];
    const float* ksc = (const float*)d_in[6];
    float* out = (float*)d_out;

    void *pqkv, *pxh, *pqh, *pkh, *pvh, *paoh, *pwfh, *pwfl, *pwoh;
    cudaGetSymbolAddress(&pqkv, g_qkv);
    cudaGetSymbolAddress(&pxh, g_xh);
    cudaGetSymbolAddress(&pqh, g_qh);
    cudaGetSymbolAddress(&pkh, g_kh);
    cudaGetSymbolAddress(&pvh, g_vh);
    cudaGetSymbolAddress(&paoh, g_aoh);
    cudaGetSymbolAddress(&pwfh, g_wfhi);
    cudaGetSymbolAddress(&pwfl, g_wflo);
    cudaGetSymbolAddress(&pwoh, g_wohi);

    float* dqkv = (float*)pqkv;
    __half* xh  = (__half*)pxh;
    __half* qh  = (__half*)pqh;
    __half* kh  = (__half*)pkh;
    __half* vh  = (__half*)pvh;
    __half* aoh = (__half*)paoh;
    __half* wfh = (__half*)pwfh; __half* wfl = (__half*)pwfl;
    __half* woh = (__half*)pwoh;

    size_t gemm_smem  = 2 * STAGEB;   // 61440
    size_t gemm1_smem = 2 * STAGEB2;  // 40960
    cudaFuncSetAttribute(mma_gemm_kernel,
                         cudaFuncAttributeMaxDynamicSharedMemorySize, (int)gemm_smem);
    cudaFuncSetAttribute(mma_gemm1_kernel,
                         cudaFuncAttributeMaxDynamicSharedMemorySize, (int)gemm1_smem);
    cudaFuncSetAttribute(attn_mma_kernel,
                         cudaFuncAttributeMaxDynamicSharedMemorySize, A_TOT);

    // ---- operand prep ----
    {
        int n4 = (MROWS * Dd) / 4;
        tohalf_kernel<<<(n4 + 255) / 256, 256>>>((const float4*)x, xh, n4);
        split_transpose_kernel<<<dim3(NQ / 32, Dd / 32), 256>>>(
            Wq, wfh, wfl, Dd, NQ);
        split_transpose_kernel<<<dim3(NKV / 32, Dd / 32), 256>>>(
            Wk, wfh + (size_t)NQ * Dd, wfl + (size_t)NQ * Dd, Dd, NKV);
        split_transpose_kernel<<<dim3(NKV / 32, Dd / 32), 256>>>(
            Wv, wfh + (size_t)(NQ + NKV) * Dd, wfl + (size_t)(NQ + NKV) * Dd, Dd, NKV);
        transpose_half_kernel<<<dim3(Dd / 32, NQ / 32), 256>>>(Wo, woh, NQ, Dd);
    }

    // ---- merged QKV projection (2-pass) ----
    mma_gemm_kernel<<<dim3(NQKV / 128, MROWS / 128), 256, gemm_smem>>>(
        xh, wfh, wfl, dqkv, MROWS, NQKV, Dd);

    // ---- qk-norm -> fp16, V extract -> fp16 ----
    rmsnorm_qk_kernel<<<MROWS * 12, 256>>>(dqkv, qsc, ksc, qh, kh);
    extract_v_kernel<<<MROWS, 256>>>(dqkv, vh);

    // ---- attention (tensor cores) ----
    {
        dim3 grid(Tt / 64, Hh, Bb);
        attn_mma_kernel<<<grid, 256, A_TOT>>>();
    }

    // ---- output projection (single-pass fp16) ----
    mma_gemm1_kernel<<<dim3(Dd / 128, MROWS / 128), 256, gemm1_smem>>>(
        aoh, woh, out, MROWS, Dd, NQ);
}

// round 10
// speedup vs baseline: 4.3193x; 1.2616x over previous
#include <cuda_runtime.h>
#include <cuda_fp16.h>
#include <math.h>
#include <cstdint>

// ---------------- problem constants ----------------
#define Bb 2
#define Tt 2048
#define Dd 2560
#define Hh 8
#define Gg 4
#define HD 256
#define NQ (Hh*HD)     // 2048
#define NKV (Gg*HD)    // 1024
#define NQKV 4096
#define MROWS (Bb*Tt)  // 4096
#define QK_SCALE 0.0625f
#define WINDOW 1024

// ---------------- scratch ----------------------------------------------------
__device__ float g_qkv[(size_t)MROWS * NQKV];
__device__ __align__(256) __half g_xh[(size_t)MROWS * Dd];
__device__ __align__(256) __half g_qh[(size_t)MROWS * NQ];
__device__ __align__(256) __half g_kh[(size_t)MROWS * NKV];
__device__ __align__(256) __half g_vh[(size_t)MROWS * NKV];
__device__ __align__(256) __half g_aoh[(size_t)MROWS * NQ];
__device__ __align__(256) __half g_wfhi[(size_t)NQKV * Dd];   // Wq|Wk|Wv [N,K]
__device__ __align__(256) __half g_wohi[(size_t)Dd * NQ];

// ---------------- helpers ----------------------------------------------------
__device__ __forceinline__ uint32_t smem_u32(const void* p) {
    uint32_t a;
    asm("{ .reg .u64 t; cvta.to.shared.u64 t, %1; cvt.u32.u64 %0, t; }"
        : "=r"(a) : "l"(p));
    return a;
}
__device__ __forceinline__ void cp_async16(uint32_t saddr, const void* gaddr) {
    asm volatile("cp.async.cg.shared.global [%0], [%1], 16;"
                 :: "r"(saddr), "l"(gaddr) : "memory");
}
__device__ __forceinline__ void ldmat4(uint32_t* r, uint32_t addr) {
    asm volatile("ldmatrix.sync.aligned.m8n8.x4.shared.b16 {%0,%1,%2,%3}, [%4];"
                 : "=r"(r[0]), "=r"(r[1]), "=r"(r[2]), "=r"(r[3]) : "r"(addr));
}
__device__ __forceinline__ void ldmat4t(uint32_t* r, uint32_t addr) {
    asm volatile("ldmatrix.sync.aligned.m8n8.x4.trans.shared.b16 {%0,%1,%2,%3}, [%4];"
                 : "=r"(r[0]), "=r"(r[1]), "=r"(r[2]), "=r"(r[3]) : "r"(addr));
}
__device__ __forceinline__ void mma_f16(float* c, const uint32_t* a, const uint32_t* b) {
    asm volatile(
        "mma.sync.aligned.m16n8k16.row.col.f32.f16.f16.f32 "
        "{%0,%1,%2,%3}, {%4,%5,%6,%7}, {%8,%9}, {%0,%1,%2,%3};"
        : "+f"(c[0]), "+f"(c[1]), "+f"(c[2]), "+f"(c[3])
        : "r"(a[0]), "r"(a[1]), "r"(a[2]), "r"(a[3]), "r"(b[0]), "r"(b[1]));
}

// ---------------- prep kernels ------------------------------------------------
__global__ __launch_bounds__(256) void tohalf_kernel(
    const float4* __restrict__ in, __half* __restrict__ out, int n4)
{
    int i = blockIdx.x * 256 + threadIdx.x;
    if (i >= n4) return;
    float4 v = in[i];
    __half2* op = (__half2*)(out + (size_t)i * 4);
    op[0] = __half2(__float2half_rn(v.x), __float2half_rn(v.y));
    op[1] = __half2(__float2half_rn(v.z), __float2half_rn(v.w));
}

// in [K,N] fp32 -> out [N,K] fp16
__global__ __launch_bounds__(256) void transpose_half_kernel(
    const float* __restrict__ in, __half* __restrict__ hi, int K, int N)
{
    __shared__ float t[32][33];
    int n0 = blockIdx.x * 32, k0 = blockIdx.y * 32;
    int tx = threadIdx.x & 31, ty = threadIdx.x >> 5;
#pragma unroll
    for (int i = 0; i < 32; i += 8)
        t[ty + i][tx] = in[(size_t)(k0 + ty + i) * N + n0 + tx];
    __syncthreads();
#pragma unroll
    for (int i = 0; i < 32; i += 8)
        hi[(size_t)(n0 + ty + i) * K + k0 + tx] = __float2half_rn(t[tx][ty + i]);
}

// ---------------- mma.sync fp16 single-pass GEMM ------------------------------
#define GP 80
#define TILEB (128 * GP)
#define STAGEB2 (2 * TILEB)

__global__ __launch_bounds__(256, 2) void mma_gemm1_kernel(
    const __half* __restrict__ A, const __half* __restrict__ B,
    float* __restrict__ C, int M, int N, int K)
{
    extern __shared__ char smem[];
    uint32_t sb = smem_u32(smem);
    int tid = threadIdx.x, lane = tid & 31, wid = tid >> 5;
    int wm = wid & 3, wn = wid >> 2;
    int row0 = blockIdx.y * 128, col0 = blockIdx.x * 128;

    const __half* gsrc[2] = { A + (size_t)row0 * K, B + (size_t)col0 * K };

    const int NC = K >> 5;

    int r_ld0 = tid >> 2, c16_0 = tid & 3;
    int r_ld1 = (tid + 256) >> 2, c16_1 = (tid + 256) & 3;

    float acc[2][8][4];
#pragma unroll
    for (int mt = 0; mt < 2; mt++)
#pragma unroll
        for (int nt = 0; nt < 8; nt++)
#pragma unroll
            for (int i = 0; i < 4; i++) acc[mt][nt][i] = 0.f;

    int grp = lane >> 3, lr = lane & 7;
    uint32_t aoff = (uint32_t)(((grp & 1) * 8 + lr) * GP + (grp >> 1) * 16);
    uint32_t boff = (uint32_t)(((grp >> 1) * 8 + lr) * GP + (grp & 1) * 16);

    auto load_stage = [&](int c) {
        uint32_t st = sb + (uint32_t)(c & 1) * STAGEB2;
        int kb = c * 32;
#pragma unroll
        for (int tile = 0; tile < 2; tile++) {
            const __half* g = gsrc[tile];
            uint32_t tb = st + (uint32_t)tile * TILEB;
            cp_async16(tb + (uint32_t)(r_ld0 * GP + c16_0 * 16),
                       g + (size_t)r_ld0 * K + kb + c16_0 * 8);
            cp_async16(tb + (uint32_t)(r_ld1 * GP + c16_1 * 16),
                       g + (size_t)r_ld1 * K + kb + c16_1 * 8);
        }
        asm volatile("cp.async.commit_group;" ::: "memory");
    };

    load_stage(0);

    for (int c = 0; c < NC; c++) {
        if (c + 1 < NC) {
            load_stage(c + 1);
            asm volatile("cp.async.wait_group 1;" ::: "memory");
        } else {
            asm volatile("cp.async.wait_group 0;" ::: "memory");
        }
        __syncthreads();

        uint32_t st = sb + (uint32_t)(c & 1) * STAGEB2;
        uint32_t A0 = st, B0 = st + TILEB;

#pragma unroll
        for (int kk = 0; kk < 2; kk++) {
            uint32_t kbyte = (uint32_t)kk * 32;
            uint32_t ah[2][4], bh[8][2];
#pragma unroll
            for (int mt = 0; mt < 2; mt++) {
                uint32_t rb = (uint32_t)((wm * 32 + mt * 16) * GP) + aoff + kbyte;
                ldmat4(ah[mt], A0 + rb);
            }
#pragma unroll
            for (int nt2 = 0; nt2 < 4; nt2++) {
                uint32_t rb = (uint32_t)((wn * 64 + nt2 * 16) * GP) + boff + kbyte;
                uint32_t r[4];
                ldmat4(r, B0 + rb);
                bh[nt2 * 2][0] = r[0]; bh[nt2 * 2][1] = r[1];
                bh[nt2 * 2 + 1][0] = r[2]; bh[nt2 * 2 + 1][1] = r[3];
            }
#pragma unroll
            for (int mt = 0; mt < 2; mt++)
#pragma unroll
                for (int nt = 0; nt < 8; nt++)
                    mma_f16(acc[mt][nt], ah[mt], bh[nt]);
        }
        __syncthreads();
    }

#pragma unroll
    for (int mt = 0; mt < 2; mt++) {
        int rg0 = row0 + wm * 32 + mt * 16 + (lane >> 2);
#pragma unroll
        for (int nt = 0; nt < 8; nt++) {
            int cg = col0 + wn * 64 + nt * 8 + (lane & 3) * 2;
            *(float2*)(C + (size_t)rg0 * N + cg) =
                make_float2(acc[mt][nt][0], acc[mt][nt][1]);
            *(float2*)(C + (size_t)(rg0 + 8) * N + cg) =
                make_float2(acc[mt][nt][2], acc[mt][nt][3]);
        }
    }
}

// ---------------- Gemma RMSNorm: g_qkv -> fp16 q (scaled) / k -----------------
__global__ __launch_bounds__(256) void rmsnorm_qk_kernel(
    const float* __restrict__ qkv, const float* __restrict__ qsc,
    const float* __restrict__ ksc, __half* __restrict__ qh,
    __half* __restrict__ kh)
{
    int blk = blockIdx.x;
    int row = blk / 12, hh = blk % 12;
    int d = threadIdx.x;
    const float* p;
    const float* sc;
    __half* o;
    float osc;
    if (hh < 8) {
        p = qkv + (size_t)row * NQKV + hh * HD;
        o = qh + (size_t)row * NQ + hh * HD;
        sc = qsc; osc = QK_SCALE;
    } else {
        int g = hh - 8;
        p = qkv + (size_t)row * NQKV + NQ + g * HD;
        o = kh + (size_t)row * NKV + g * HD;
        sc = ksc; osc = 1.f;
    }
    float x = p[d];
    float v = x * x;
#pragma unroll
    for (int of = 16; of > 0; of >>= 1) v += __shfl_xor_sync(0xffffffffu, v, of);
    __shared__ float ws[8];
    __shared__ float stot;
    if ((d & 31) == 0) ws[d >> 5] = v;
    __syncthreads();
    if (d == 0) {
        float s = 0.f;
#pragma unroll
        for (int i = 0; i < 8; i++) s += ws[i];
        stot = s;
    }
    __syncthreads();
    float r = rsqrtf(stot * (1.f / HD) + 1e-6f);
    o[d] = __float2half_rn(x * r * (1.f + sc[d]) * osc);
}

__global__ __launch_bounds__(256) void extract_v_kernel(
    const float* __restrict__ qkv, __half* __restrict__ vh)
{
    int row = blockIdx.x;
    int t = threadIdx.x;
    float4 v = *(const float4*)(qkv + (size_t)row * NQKV + NQ + NKV + t * 4);
    __half2 h0 = __floats2half2_rn(v.x, v.y);
    __half2 h1 = __floats2half2_rn(v.z, v.w);
    *(uint2*)(vh + (size_t)row * NKV + t * 4) =
        make_uint2(*(uint32_t*)&h0, *(uint32_t*)&h1);
}

// ---------------- tensor-core flash attention ---------------------------------
#define AQP 528
#define A_QB 0
#define A_KB (A_QB + 64 * AQP)
#define A_VB (A_KB + 64 * AQP)
#define A_SB (A_VB + 64 * AQP)
#define A_PB (A_SB + 64 * 66 * 4)
#define A_MB (A_PB + 64 * 144)
#define A_LB (A_MB + 256)
#define A_AB (A_LB + 256)
#define A_TOT (A_AB + 256)

__global__ __launch_bounds__(256, 1) void attn_mma_kernel()
{
    extern __shared__ char sm[];
    uint32_t sb = smem_u32(sm);
    float* Sf   = (float*)(sm + A_SB);
    __half* Ph  = (__half*)(sm + A_PB);
    float* msm  = (float*)(sm + A_MB);
    float* lsm  = (float*)(sm + A_LB);
    float* arow = (float*)(sm + A_AB);

    int tid = threadIdx.x, lane = tid & 31, wid = tid >> 5;
    int wq = wid & 3, wn = wid >> 2;
    int qt = blockIdx.x, h = blockIdx.y, b = blockIdx.z;
    int t0 = qt * 64;
    int kvh = h & (Gg - 1);

    const __half* qbase = g_qh + ((size_t)(b * Tt + t0)) * NQ + h * HD;
    for (int idx = tid; idx < 64 * 32; idx += 256) {
        int r = idx >> 5, c = idx & 31;
        *(uint4*)(sm + A_QB + r * AQP + c * 16) =
            *(const uint4*)(qbase + (size_t)r * NQ + c * 8);
    }
    if (tid < 64) { msm[tid] = -1e30f; lsm[tid] = 0.f; }

    float o[16][4];
#pragma unroll
    for (int f = 0; f < 16; f++)
#pragma unroll
        for (int i = 0; i < 4; i++) o[f][i] = 0.f;

    int grp = lane >> 3, lr = lane & 7;
    uint32_t aoff = (uint32_t)(((grp & 1) * 8 + lr) * AQP + (grp >> 1) * 16);
    uint32_t boff = (uint32_t)(((grp >> 1) * 8 + lr) * AQP + (grp & 1) * 16);
    uint32_t poff = (uint32_t)(((grp & 1) * 8 + lr) * 144 + (grp >> 1) * 16);

    int row_m = wq * 16 + (lane >> 2);

    int sm_row = tid >> 2, sm_q = tid & 3;
    int sm_base = sm_q * 16;

    int kb0 = max(0, t0 - (WINDOW - 1)) >> 6;
    int kb1 = (t0 + 63) >> 6;

    for (int kb = kb0; kb <= kb1; kb++) {
        int s0 = kb * 64;
        __syncthreads();

        const __half* kbase = g_kh + ((size_t)(b * Tt + s0)) * NKV + kvh * HD;
        const __half* vbase = g_vh + ((size_t)(b * Tt + s0)) * NKV + kvh * HD;
        for (int idx = tid; idx < 64 * 32; idx += 256) {
            int r = idx >> 5, c = idx & 31;
            *(uint4*)(sm + A_KB + r * AQP + c * 16) =
                *(const uint4*)(kbase + (size_t)r * NKV + c * 8);
            *(uint4*)(sm + A_VB + r * AQP + c * 16) =
                *(const uint4*)(vbase + (size_t)r * NKV + c * 8);
        }
        __syncthreads();

        // ---- QK ----
        {
            float sc[4][4];
#pragma unroll
            for (int j = 0; j < 4; j++)
#pragma unroll
                for (int i = 0; i < 4; i++) sc[j][i] = 0.f;
#pragma unroll 4
            for (int kd = 0; kd < 16; kd++) {
                uint32_t a[4];
                ldmat4(a, sb + A_QB + (uint32_t)(wq * 16) * AQP + kd * 32 + aoff);
                uint32_t bf0[4], bf1[4];
                ldmat4(bf0, sb + A_KB + (uint32_t)(wn * 32) * AQP + kd * 32 + boff);
                ldmat4(bf1, sb + A_KB + (uint32_t)(wn * 32 + 16) * AQP + kd * 32 + boff);
                mma_f16(sc[0], a, &bf0[0]);
                mma_f16(sc[1], a, &bf0[2]);
                mma_f16(sc[2], a, &bf1[0]);
                mma_f16(sc[3], a, &bf1[2]);
            }
            int cb = wn * 32 + (lane & 3) * 2;
#pragma unroll
            for (int j = 0; j < 4; j++) {
                *(float2*)(Sf + row_m * 66 + cb + 8 * j) =
                    make_float2(sc[j][0], sc[j][1]);
                *(float2*)(Sf + (row_m + 8) * 66 + cb + 8 * j) =
                    make_float2(sc[j][2], sc[j][3]);
            }
        }
        __syncthreads();

        // ---- softmax: 4 threads per row ----
        {
            int tq = t0 + sm_row;
            int jlo = tq - (WINDOW - 1) - s0;
            int jhi = tq - s0;
            if (jhi > 63) jhi = 63;
            if (jlo < 0) jlo = 0;
            const float* srow = Sf + sm_row * 66;
            float mloc = -1e30f;
#pragma unroll
            for (int j = 0; j < 16; j++) {
                int jj = sm_base + j;
                if (jj >= jlo && jj <= jhi) mloc = fmaxf(mloc, srow[jj]);
            }
            mloc = fmaxf(mloc, __shfl_xor_sync(0xffffffffu, mloc, 1));
            mloc = fmaxf(mloc, __shfl_xor_sync(0xffffffffu, mloc, 2));
            float m0 = msm[sm_row];
            float mnew = fmaxf(m0, mloc);
            float sum = 0.f;
            __half* prow = Ph + sm_row * 72;
#pragma unroll
            for (int j = 0; j < 16; j += 2) {
                int j0 = sm_base + j, j1 = j0 + 1;
                float p0 = (j0 >= jlo && j0 <= jhi) ? __expf(srow[j0] - mnew) : 0.f;
                float p1 = (j1 >= jlo && j1 <= jhi) ? __expf(srow[j1] - mnew) : 0.f;
                *(__half2*)(prow + j0) = __floats2half2_rn(p0, p1);
                sum += p0 + p1;
            }
            sum += __shfl_xor_sync(0xffffffffu, sum, 1);
            sum += __shfl_xor_sync(0xffffffffu, sum, 2);
            if (sm_q == 0) {
                float alpha = __expf(m0 - mnew);
                lsm[sm_row] = lsm[sm_row] * alpha + sum;
                msm[sm_row] = mnew;
                arow[sm_row] = alpha;
            }
        }
        __syncthreads();

        // ---- rescale O, then PV ----
        {
            float a0 = arow[row_m], a1 = arow[row_m + 8];
#pragma unroll
            for (int f = 0; f < 16; f++) {
                o[f][0] *= a0; o[f][1] *= a0;
                o[f][2] *= a1; o[f][3] *= a1;
            }
#pragma unroll
            for (int kk = 0; kk < 4; kk++) {
                uint32_t pa[4];
                ldmat4(pa, sb + A_PB + (uint32_t)(wq * 16) * 144 + kk * 32 + poff);
#pragma unroll
                for (int nb = 0; nb < 8; nb++) {
                    uint32_t bv[4];
                    ldmat4t(bv, sb + A_VB + (uint32_t)(kk * 16) * AQP
                                + (uint32_t)(wn * 256 + nb * 32) + aoff);
                    mma_f16(o[nb * 2],     pa, &bv[0]);
                    mma_f16(o[nb * 2 + 1], pa, &bv[2]);
                }
            }
        }
    }

    __syncthreads();
    float il0 = 1.f / lsm[row_m];
    float il1 = 1.f / lsm[row_m + 8];
    __half* obase = g_aoh + ((size_t)(b * Tt + t0)) * NQ + h * HD;
#pragma unroll
    for (int f = 0; f < 16; f++) {
        int nb = f >> 1, t = f & 1;
        int col = wn * 128 + nb * 16 + t * 8 + (lane & 3) * 2;
        __half2 h0 = __floats2half2_rn(o[f][0] * il0, o[f][1] * il0);
        __half2 h1 = __floats2half2_rn(o[f][2] * il1, o[f][3] * il1);
        *(__half2*)(obase + (size_t)row_m * NQ + col) = h0;
        *(__half2*)(obase + (size_t)(row_m + 8) * NQ + col) = h1;
    }
}

// ---------------- launch -------------------------------------------------------
extern "C" void kernel_launch(void* const* d_in, const int* in_sizes, int n_in,
                              void* d_out, int out_size)
{
    const float* x   = (const float*)d_in[0];
    const float* Wq  = (const float*)d_in[1];
    const float* Wk  = (const float*)d_in[2];
    const float* Wv  = (const float*)d_in[3];
    const float* Wo  = (const float*)d_in[4];
    const float* qsc = (const float*)d_in[5];
    const float* ksc = (const float*)d_in[6];
    float* out = (float*)d_out;

    void *pqkv, *pxh, *pqh, *pkh, *pvh, *paoh, *pwfh, *pwoh;
    cudaGetSymbolAddress(&pqkv, g_qkv);
    cudaGetSymbolAddress(&pxh, g_xh);
    cudaGetSymbolAddress(&pqh, g_qh);
    cudaGetSymbolAddress(&pkh, g_kh);
    cudaGetSymbolAddress(&pvh, g_vh);
    cudaGetSymbolAddress(&paoh, g_aoh);
    cudaGetSymbolAddress(&pwfh, g_wfhi);
    cudaGetSymbolAddress(&pwoh, g_wohi);

    float* dqkv = (float*)pqkv;
    __half* xh  = (__half*)pxh;
    __half* qh  = (__half*)pqh;
    __half* kh  = (__half*)pkh;
    __half* vh  = (__half*)pvh;
    __half* aoh = (__half*)paoh;
    __half* wfh = (__half*)pwfh;
    __half* woh = (__half*)pwoh;

    size_t gemm1_smem = 2 * STAGEB2;  // 40960
    cudaFuncSetAttribute(mma_gemm1_kernel,
                         cudaFuncAttributeMaxDynamicSharedMemorySize, (int)gemm1_smem);
    cudaFuncSetAttribute(attn_mma_kernel,
                         cudaFuncAttributeMaxDynamicSharedMemorySize, A_TOT);

    // ---- operand prep (all fp16 single-precision) ----
    {
        int n4 = (MROWS * Dd) / 4;
        tohalf_kernel<<<(n4 + 255) / 256, 256>>>((const float4*)x, xh, n4);
        transpose_half_kernel<<<dim3(NQ / 32, Dd / 32), 256>>>(Wq, wfh, Dd, NQ);
        transpose_half_kernel<<<dim3(NKV / 32, Dd / 32), 256>>>(
            Wk, wfh + (size_t)NQ * Dd, Dd, NKV);
        transpose_half_kernel<<<dim3(NKV / 32, Dd / 32), 256>>>(
            Wv, wfh + (size_t)(NQ + NKV) * Dd, Dd, NKV);
        transpose_half_kernel<<<dim3(Dd / 32, NQ / 32), 256>>>(Wo, woh, NQ, Dd);
    }

    // ---- merged QKV projection (single-pass fp16) ----
    mma_gemm1_kernel<<<dim3(NQKV / 128, MROWS / 128), 256, gemm1_smem>>>(
        xh, wfh, dqkv, MROWS, NQKV, Dd);

    // ---- qk-norm -> fp16, V extract -> fp16 ----
    rmsnorm_qk_kernel<<<MROWS * 12, 256>>>(dqkv, qsc, ksc, qh, kh);
    extract_v_kernel<<<MROWS, 256>>>(dqkv, vh);

    // ---- attention (tensor cores) ----
    {
        dim3 grid(Tt / 64, Hh, Bb);
        attn_mma_kernel<<<grid, 256, A_TOT>>>();
    }

    // ---- output projection (single-pass fp16) ----
    mma_gemm1_kernel<<<dim3(Dd / 128, MROWS / 128), 256, gemm1_smem>>>(
        aoh, woh, out, MROWS, Dd, NQ);
}

// round 11
// speedup vs baseline: 4.6305x; 1.0720x over previous
#include <cuda_runtime.h>
#include <cuda_fp16.h>
#include <math.h>
#include <cstdint>

// ---------------- problem constants ----------------
#define Bb 2
#define Tt 2048
#define Dd 2560
#define Hh 8
#define Gg 4
#define HD 256
#define NQ (Hh*HD)     // 2048
#define NKV (Gg*HD)    // 1024
#define NQKV 4096
#define MROWS (Bb*Tt)  // 4096
#define QK_SCALE 0.0625f
#define WINDOW 1024

// ---------------- scratch ----------------------------------------------------
__device__ float g_qkv[(size_t)MROWS * NQKV];
__device__ __align__(256) __half g_xh[(size_t)MROWS * Dd];
__device__ __align__(256) __half g_qh[(size_t)MROWS * NQ];
__device__ __align__(256) __half g_kh[(size_t)MROWS * NKV];
__device__ __align__(256) __half g_vh[(size_t)MROWS * NKV];
__device__ __align__(256) __half g_aoh[(size_t)MROWS * NQ];
__device__ __align__(256) __half g_wfhi[(size_t)NQKV * Dd];   // Wq|Wk|Wv [N,K]
__device__ __align__(256) __half g_wohi[(size_t)Dd * NQ];

// ---------------- helpers ----------------------------------------------------
__device__ __forceinline__ uint32_t smem_u32(const void* p) {
    uint32_t a;
    asm("{ .reg .u64 t; cvta.to.shared.u64 t, %1; cvt.u32.u64 %0, t; }"
        : "=r"(a) : "l"(p));
    return a;
}
__device__ __forceinline__ void cp_async16(uint32_t saddr, const void* gaddr) {
    asm volatile("cp.async.cg.shared.global [%0], [%1], 16;"
                 :: "r"(saddr), "l"(gaddr) : "memory");
}
__device__ __forceinline__ void ldmat4(uint32_t* r, uint32_t addr) {
    asm volatile("ldmatrix.sync.aligned.m8n8.x4.shared.b16 {%0,%1,%2,%3}, [%4];"
                 : "=r"(r[0]), "=r"(r[1]), "=r"(r[2]), "=r"(r[3]) : "r"(addr));
}
__device__ __forceinline__ void ldmat4t(uint32_t* r, uint32_t addr) {
    asm volatile("ldmatrix.sync.aligned.m8n8.x4.trans.shared.b16 {%0,%1,%2,%3}, [%4];"
                 : "=r"(r[0]), "=r"(r[1]), "=r"(r[2]), "=r"(r[3]) : "r"(addr));
}
__device__ __forceinline__ void mma_f16(float* c, const uint32_t* a, const uint32_t* b) {
    asm volatile(
        "mma.sync.aligned.m16n8k16.row.col.f32.f16.f16.f32 "
        "{%0,%1,%2,%3}, {%4,%5,%6,%7}, {%8,%9}, {%0,%1,%2,%3};"
        : "+f"(c[0]), "+f"(c[1]), "+f"(c[2]), "+f"(c[3])
        : "r"(a[0]), "r"(a[1]), "r"(a[2]), "r"(a[3]), "r"(b[0]), "r"(b[1]));
}

// ---------------- prep kernels ------------------------------------------------
__global__ __launch_bounds__(256) void tohalf_kernel(
    const float4* __restrict__ in, __half* __restrict__ out, int n4)
{
    int i = blockIdx.x * 256 + threadIdx.x;
    if (i >= n4) return;
    float4 v = in[i];
    __half2* op = (__half2*)(out + (size_t)i * 4);
    op[0] = __half2(__float2half_rn(v.x), __float2half_rn(v.y));
    op[1] = __half2(__float2half_rn(v.z), __float2half_rn(v.w));
}

// in [K,N] fp32 -> out [N,K] fp16
__global__ __launch_bounds__(256) void transpose_half_kernel(
    const float* __restrict__ in, __half* __restrict__ hi, int K, int N)
{
    __shared__ float t[32][33];
    int n0 = blockIdx.x * 32, k0 = blockIdx.y * 32;
    int tx = threadIdx.x & 31, ty = threadIdx.x >> 5;
#pragma unroll
    for (int i = 0; i < 32; i += 8)
        t[ty + i][tx] = in[(size_t)(k0 + ty + i) * N + n0 + tx];
    __syncthreads();
#pragma unroll
    for (int i = 0; i < 32; i += 8)
        hi[(size_t)(n0 + ty + i) * K + k0 + tx] = __float2half_rn(t[tx][ty + i]);
}

// ---------------- mma.sync fp16 single-pass GEMM ------------------------------
#define GP 80
#define TILEB (128 * GP)
#define STAGEB2 (2 * TILEB)

__global__ __launch_bounds__(256, 2) void mma_gemm1_kernel(
    const __half* __restrict__ A, const __half* __restrict__ B,
    float* __restrict__ C, int M, int N, int K)
{
    extern __shared__ char smem[];
    uint32_t sb = smem_u32(smem);
    int tid = threadIdx.x, lane = tid & 31, wid = tid >> 5;
    int wm = wid & 3, wn = wid >> 2;
    int row0 = blockIdx.y * 128, col0 = blockIdx.x * 128;

    const __half* gsrc[2] = { A + (size_t)row0 * K, B + (size_t)col0 * K };

    const int NC = K >> 5;

    int r_ld0 = tid >> 2, c16_0 = tid & 3;
    int r_ld1 = (tid + 256) >> 2, c16_1 = (tid + 256) & 3;

    float acc[2][8][4];
#pragma unroll
    for (int mt = 0; mt < 2; mt++)
#pragma unroll
        for (int nt = 0; nt < 8; nt++)
#pragma unroll
            for (int i = 0; i < 4; i++) acc[mt][nt][i] = 0.f;

    int grp = lane >> 3, lr = lane & 7;
    uint32_t aoff = (uint32_t)(((grp & 1) * 8 + lr) * GP + (grp >> 1) * 16);
    uint32_t boff = (uint32_t)(((grp >> 1) * 8 + lr) * GP + (grp & 1) * 16);

    auto load_stage = [&](int c) {
        uint32_t st = sb + (uint32_t)(c & 1) * STAGEB2;
        int kb = c * 32;
#pragma unroll
        for (int tile = 0; tile < 2; tile++) {
            const __half* g = gsrc[tile];
            uint32_t tb = st + (uint32_t)tile * TILEB;
            cp_async16(tb + (uint32_t)(r_ld0 * GP + c16_0 * 16),
                       g + (size_t)r_ld0 * K + kb + c16_0 * 8);
            cp_async16(tb + (uint32_t)(r_ld1 * GP + c16_1 * 16),
                       g + (size_t)r_ld1 * K + kb + c16_1 * 8);
        }
        asm volatile("cp.async.commit_group;" ::: "memory");
    };

    load_stage(0);

    for (int c = 0; c < NC; c++) {
        if (c + 1 < NC) {
            load_stage(c + 1);
            asm volatile("cp.async.wait_group 1;" ::: "memory");
        } else {
            asm volatile("cp.async.wait_group 0;" ::: "memory");
        }
        __syncthreads();

        uint32_t st = sb + (uint32_t)(c & 1) * STAGEB2;
        uint32_t A0 = st, B0 = st + TILEB;

#pragma unroll
        for (int kk = 0; kk < 2; kk++) {
            uint32_t kbyte = (uint32_t)kk * 32;
            uint32_t ah[2][4], bh[8][2];
#pragma unroll
            for (int mt = 0; mt < 2; mt++) {
                uint32_t rb = (uint32_t)((wm * 32 + mt * 16) * GP) + aoff + kbyte;
                ldmat4(ah[mt], A0 + rb);
            }
#pragma unroll
            for (int nt2 = 0; nt2 < 4; nt2++) {
                uint32_t rb = (uint32_t)((wn * 64 + nt2 * 16) * GP) + boff + kbyte;
                uint32_t r[4];
                ldmat4(r, B0 + rb);
                bh[nt2 * 2][0] = r[0]; bh[nt2 * 2][1] = r[1];
                bh[nt2 * 2 + 1][0] = r[2]; bh[nt2 * 2 + 1][1] = r[3];
            }
#pragma unroll
            for (int mt = 0; mt < 2; mt++)
#pragma unroll
                for (int nt = 0; nt < 8; nt++)
                    mma_f16(acc[mt][nt], ah[mt], bh[nt]);
        }
        __syncthreads();
    }

#pragma unroll
    for (int mt = 0; mt < 2; mt++) {
        int rg0 = row0 + wm * 32 + mt * 16 + (lane >> 2);
#pragma unroll
        for (int nt = 0; nt < 8; nt++) {
            int cg = col0 + wn * 64 + nt * 8 + (lane & 3) * 2;
            *(float2*)(C + (size_t)rg0 * N + cg) =
                make_float2(acc[mt][nt][0], acc[mt][nt][1]);
            *(float2*)(C + (size_t)(rg0 + 8) * N + cg) =
                make_float2(acc[mt][nt][2], acc[mt][nt][3]);
        }
    }
}

// ---------------- Gemma RMSNorm: g_qkv -> fp16 q (scaled) / k -----------------
__global__ __launch_bounds__(256) void rmsnorm_qk_kernel(
    const float* __restrict__ qkv, const float* __restrict__ qsc,
    const float* __restrict__ ksc, __half* __restrict__ qh,
    __half* __restrict__ kh)
{
    int blk = blockIdx.x;
    int row = blk / 12, hh = blk % 12;
    int d = threadIdx.x;
    const float* p;
    const float* sc;
    __half* o;
    float osc;
    if (hh < 8) {
        p = qkv + (size_t)row * NQKV + hh * HD;
        o = qh + (size_t)row * NQ + hh * HD;
        sc = qsc; osc = QK_SCALE;
    } else {
        int g = hh - 8;
        p = qkv + (size_t)row * NQKV + NQ + g * HD;
        o = kh + (size_t)row * NKV + g * HD;
        sc = ksc; osc = 1.f;
    }
    float x = p[d];
    float v = x * x;
#pragma unroll
    for (int of = 16; of > 0; of >>= 1) v += __shfl_xor_sync(0xffffffffu, v, of);
    __shared__ float ws[8];
    __shared__ float stot;
    if ((d & 31) == 0) ws[d >> 5] = v;
    __syncthreads();
    if (d == 0) {
        float s = 0.f;
#pragma unroll
        for (int i = 0; i < 8; i++) s += ws[i];
        stot = s;
    }
    __syncthreads();
    float r = rsqrtf(stot * (1.f / HD) + 1e-6f);
    o[d] = __float2half_rn(x * r * (1.f + sc[d]) * osc);
}

__global__ __launch_bounds__(256) void extract_v_kernel(
    const float* __restrict__ qkv, __half* __restrict__ vh)
{
    int row = blockIdx.x;
    int t = threadIdx.x;
    float4 v = *(const float4*)(qkv + (size_t)row * NQKV + NQ + NKV + t * 4);
    __half2 h0 = __floats2half2_rn(v.x, v.y);
    __half2 h1 = __floats2half2_rn(v.z, v.w);
    *(uint2*)(vh + (size_t)row * NKV + t * 4) =
        make_uint2(*(uint32_t*)&h0, *(uint32_t*)&h1);
}

// ---------------- FA2-style register-resident attention ----------------------
// 8 warps, each owns 16 q-rows x all 64 k-cols. Q-tile 128, K-tile 64.
// S/P stay in registers; softmax via quad shfl; K/V double-buffered cp.async.
#define NAQP 528
#define N_QB 0
#define N_KB (N_QB + 128 * NAQP)          // 67584
#define N_VB (N_KB + 2 * 64 * NAQP)       // +67584
#define N_TOT (N_VB + 2 * 64 * NAQP)      // 202752

__global__ __launch_bounds__(256, 1) void attn_fa2_kernel()
{
    extern __shared__ char sm[];
    uint32_t sb = smem_u32(sm);

    int tid = threadIdx.x, lane = tid & 31, wid = tid >> 5;
    int qt = (int)gridDim.x - 1 - (int)blockIdx.x;   // heavy tiles first
    int h = blockIdx.y, b = blockIdx.z;
    int t0 = qt * 128;
    int kvh = h & (Gg - 1);

    int grp = lane >> 3, lr = lane & 7;
    uint32_t aoff = (uint32_t)(((grp & 1) * 8 + lr) * NAQP + (grp >> 1) * 16);
    uint32_t boff = (uint32_t)(((grp >> 1) * 8 + lr) * NAQP + (grp & 1) * 16);

    int q4 = lane & 3;            // quad lane
    int row_m = wid * 16 + (lane >> 2);

    // ---- prologue: Q tile + first K/V tile, one cp.async group ----
    const __half* qbase = g_qh + ((size_t)(b * Tt + t0)) * NQ + h * HD;
    for (int idx = tid; idx < 128 * 32; idx += 256) {
        int r = idx >> 5, c = idx & 31;
        cp_async16(sb + N_QB + (uint32_t)(r * NAQP + c * 16),
                   qbase + (size_t)r * NQ + c * 8);
    }

    int kb0 = max(0, t0 - (WINDOW - 1)) >> 6;
    int kb1 = (t0 + 127) >> 6;

    auto load_kv = [&](int kb, int buf) {
        const __half* kbase = g_kh + ((size_t)(b * Tt + kb * 64)) * NKV + kvh * HD;
        const __half* vbase = g_vh + ((size_t)(b * Tt + kb * 64)) * NKV + kvh * HD;
        uint32_t kdst = sb + N_KB + (uint32_t)buf * (64 * NAQP);
        uint32_t vdst = sb + N_VB + (uint32_t)buf * (64 * NAQP);
        for (int idx = tid; idx < 64 * 32; idx += 256) {
            int r = idx >> 5, c = idx & 31;
            uint32_t so = (uint32_t)(r * NAQP + c * 16);
            cp_async16(kdst + so, kbase + (size_t)r * NKV + c * 8);
            cp_async16(vdst + so, vbase + (size_t)r * NKV + c * 8);
        }
        asm volatile("cp.async.commit_group;" ::: "memory");
    };

    load_kv(kb0, 0);   // commits Q + first K/V together

    float o[32][4];
#pragma unroll
    for (int f = 0; f < 32; f++)
#pragma unroll
        for (int i = 0; i < 4; i++) o[f][i] = 0.f;

    float m0r = -1e30f, m1r = -1e30f;   // running max, rows row_m / row_m+8
    float l0r = 0.f,    l1r = 0.f;      // running sum

    int gr0 = t0 + row_m;       // global q row (thread row 0)
    int gr1 = gr0 + 8;

    for (int kb = kb0; kb <= kb1; kb++) {
        int buf = (kb - kb0) & 1;
        asm volatile("cp.async.wait_group 0;" ::: "memory");
        __syncthreads();
        if (kb < kb1) load_kv(kb + 1, buf ^ 1);

        uint32_t Kb = sb + N_KB + (uint32_t)buf * (64 * NAQP);
        uint32_t Vb = sb + N_VB + (uint32_t)buf * (64 * NAQP);
        int s0 = kb * 64;

        // ---- QK: 16q x 64k in registers ----
        float sc[8][4];
#pragma unroll
        for (int j = 0; j < 8; j++)
#pragma unroll
            for (int i = 0; i < 4; i++) sc[j][i] = 0.f;
#pragma unroll 4
        for (int kd = 0; kd < 16; kd++) {
            uint32_t a[4];
            ldmat4(a, sb + N_QB + (uint32_t)(wid * 16) * NAQP + kd * 32 + aoff);
#pragma unroll
            for (int nt2 = 0; nt2 < 4; nt2++) {
                uint32_t bf[4];
                ldmat4(bf, Kb + (uint32_t)(nt2 * 16) * NAQP + kd * 32 + boff);
                mma_f16(sc[nt2 * 2], a, &bf[0]);
                mma_f16(sc[nt2 * 2 + 1], a, &bf[2]);
            }
        }

        // ---- register softmax ----
        float mx0 = -1e30f, mx1 = -1e30f;
#pragma unroll
        for (int j = 0; j < 8; j++) {
            int c0 = s0 + j * 8 + q4 * 2, c1 = c0 + 1;
            bool a00 = (c0 <= gr0) && (c0 > gr0 - WINDOW);
            bool a01 = (c1 <= gr0) && (c1 > gr0 - WINDOW);
            bool a10 = (c0 <= gr1) && (c0 > gr1 - WINDOW);
            bool a11 = (c1 <= gr1) && (c1 > gr1 - WINDOW);
            if (a00) mx0 = fmaxf(mx0, sc[j][0]);
            if (a01) mx0 = fmaxf(mx0, sc[j][1]);
            if (a10) mx1 = fmaxf(mx1, sc[j][2]);
            if (a11) mx1 = fmaxf(mx1, sc[j][3]);
            // encode mask by setting disallowed to -inf sentinel
            if (!a00) sc[j][0] = -1e30f;
            if (!a01) sc[j][1] = -1e30f;
            if (!a10) sc[j][2] = -1e30f;
            if (!a11) sc[j][3] = -1e30f;
        }
        mx0 = fmaxf(mx0, __shfl_xor_sync(0xffffffffu, mx0, 1));
        mx0 = fmaxf(mx0, __shfl_xor_sync(0xffffffffu, mx0, 2));
        mx1 = fmaxf(mx1, __shfl_xor_sync(0xffffffffu, mx1, 1));
        mx1 = fmaxf(mx1, __shfl_xor_sync(0xffffffffu, mx1, 2));

        float mn0 = fmaxf(m0r, mx0), mn1 = fmaxf(m1r, mx1);
        float al0 = __expf(m0r - mn0), al1 = __expf(m1r - mn1);

        float s0sum = 0.f, s1sum = 0.f;
        uint32_t pfrag[8][2];   // per j: half2(row0 pair), half2(row1 pair)
#pragma unroll
        for (int j = 0; j < 8; j++) {
            float p00 = (sc[j][0] > -1e29f) ? __expf(sc[j][0] - mn0) : 0.f;
            float p01 = (sc[j][1] > -1e29f) ? __expf(sc[j][1] - mn0) : 0.f;
            float p10 = (sc[j][2] > -1e29f) ? __expf(sc[j][2] - mn1) : 0.f;
            float p11 = (sc[j][3] > -1e29f) ? __expf(sc[j][3] - mn1) : 0.f;
            s0sum += p00 + p01;
            s1sum += p10 + p11;
            __half2 h0 = __floats2half2_rn(p00, p01);
            __half2 h1 = __floats2half2_rn(p10, p11);
            pfrag[j][0] = *(uint32_t*)&h0;
            pfrag[j][1] = *(uint32_t*)&h1;
        }
        s0sum += __shfl_xor_sync(0xffffffffu, s0sum, 1);
        s0sum += __shfl_xor_sync(0xffffffffu, s0sum, 2);
        s1sum += __shfl_xor_sync(0xffffffffu, s1sum, 1);
        s1sum += __shfl_xor_sync(0xffffffffu, s1sum, 2);
        l0r = l0r * al0 + s0sum;
        l1r = l1r * al1 + s1sum;
        m0r = mn0; m1r = mn1;

        // ---- rescale O ----
#pragma unroll
        for (int f = 0; f < 32; f++) {
            o[f][0] *= al0; o[f][1] *= al0;
            o[f][2] *= al1; o[f][3] *= al1;
        }

        // ---- PV: A-frags directly from pfrag registers ----
#pragma unroll
        for (int kk = 0; kk < 4; kk++) {
            uint32_t pa[4];
            pa[0] = pfrag[kk * 2][0];
            pa[1] = pfrag[kk * 2][1];
            pa[2] = pfrag[kk * 2 + 1][0];
            pa[3] = pfrag[kk * 2 + 1][1];
#pragma unroll
            for (int nb = 0; nb < 16; nb++) {
                uint32_t bv[4];
                ldmat4t(bv, Vb + (uint32_t)(kk * 16) * NAQP
                            + (uint32_t)(nb * 32) + aoff);
                mma_f16(o[nb * 2],     pa, &bv[0]);
                mma_f16(o[nb * 2 + 1], pa, &bv[2]);
            }
        }
    }

    // ---- epilogue: O / l -> g_aoh (fp16) ----
    float il0 = 1.f / l0r, il1 = 1.f / l1r;
    __half* obase = g_aoh + ((size_t)(b * Tt + t0)) * NQ + h * HD;
#pragma unroll
    for (int f = 0; f < 32; f++) {
        int col = f * 8 + q4 * 2;
        __half2 h0 = __floats2half2_rn(o[f][0] * il0, o[f][1] * il0);
        __half2 h1 = __floats2half2_rn(o[f][2] * il1, o[f][3] * il1);
        *(__half2*)(obase + (size_t)row_m * NQ + col) = h0;
        *(__half2*)(obase + (size_t)(row_m + 8) * NQ + col) = h1;
    }
}

// ---------------- launch -------------------------------------------------------
extern "C" void kernel_launch(void* const* d_in, const int* in_sizes, int n_in,
                              void* d_out, int out_size)
{
    const float* x   = (const float*)d_in[0];
    const float* Wq  = (const float*)d_in[1];
    const float* Wk  = (const float*)d_in[2];
    const float* Wv  = (const float*)d_in[3];
    const float* Wo  = (const float*)d_in[4];
    const float* qsc = (const float*)d_in[5];
    const float* ksc = (const float*)d_in[6];
    float* out = (float*)d_out;

    void *pqkv, *pxh, *pqh, *pkh, *pvh, *paoh, *pwfh, *pwoh;
    cudaGetSymbolAddress(&pqkv, g_qkv);
    cudaGetSymbolAddress(&pxh, g_xh);
    cudaGetSymbolAddress(&pqh, g_qh);
    cudaGetSymbolAddress(&pkh, g_kh);
    cudaGetSymbolAddress(&pvh, g_vh);
    cudaGetSymbolAddress(&paoh, g_aoh);
    cudaGetSymbolAddress(&pwfh, g_wfhi);
    cudaGetSymbolAddress(&pwoh, g_wohi);

    float* dqkv = (float*)pqkv;
    __half* xh  = (__half*)pxh;
    __half* qh  = (__half*)pqh;
    __half* kh  = (__half*)pkh;
    __half* vh  = (__half*)pvh;
    __half* aoh = (__half*)paoh;
    __half* wfh = (__half*)pwfh;
    __half* woh = (__half*)pwoh;

    size_t gemm1_smem = 2 * STAGEB2;  // 40960
    cudaFuncSetAttribute(mma_gemm1_kernel,
                         cudaFuncAttributeMaxDynamicSharedMemorySize, (int)gemm1_smem);
    cudaFuncSetAttribute(attn_fa2_kernel,
                         cudaFuncAttributeMaxDynamicSharedMemorySize, N_TOT);

    // ---- operand prep ----
    {
        int n4 = (MROWS * Dd) / 4;
        tohalf_kernel<<<(n4 + 255) / 256, 256>>>((const float4*)x, xh, n4);
        transpose_half_kernel<<<dim3(NQ / 32, Dd / 32), 256>>>(Wq, wfh, Dd, NQ);
        transpose_half_kernel<<<dim3(NKV / 32, Dd / 32), 256>>>(
            Wk, wfh + (size_t)NQ * Dd, Dd, NKV);
        transpose_half_kernel<<<dim3(NKV / 32, Dd / 32), 256>>>(
            Wv, wfh + (size_t)(NQ + NKV) * Dd, Dd, NKV);
        transpose_half_kernel<<<dim3(Dd / 32, NQ / 32), 256>>>(Wo, woh, NQ, Dd);
    }

    // ---- merged QKV projection (single-pass fp16) ----
    mma_gemm1_kernel<<<dim3(NQKV / 128, MROWS / 128), 256, gemm1_smem>>>(
        xh, wfh, dqkv, MROWS, NQKV, Dd);

    // ---- qk-norm -> fp16, V extract -> fp16 ----
    rmsnorm_qk_kernel<<<MROWS * 12, 256>>>(dqkv, qsc, ksc, qh, kh);
    extract_v_kernel<<<MROWS, 256>>>(dqkv, vh);

    // ---- attention (FA2, register-resident) ----
    {
        dim3 grid(Tt / 128, Hh, Bb);
        attn_fa2_kernel<<<grid, 256, N_TOT>>>();
    }

    // ---- output projection (single-pass fp16) ----
    mma_gemm1_kernel<<<dim3(Dd / 128, MROWS / 128), 256, gemm1_smem>>>(
        aoh, woh, out, MROWS, Dd, NQ);
}

// round 12
// speedup vs baseline: 4.9409x; 1.0670x over previous
#include <cuda_runtime.h>
#include <cuda_fp16.h>
#include <math.h>
#include <cstdint>

// ---------------- problem constants ----------------
#define Bb 2
#define Tt 2048
#define Dd 2560
#define Hh 8
#define Gg 4
#define HD 256
#define NQ (Hh*HD)     // 2048
#define NKV (Gg*HD)    // 1024
#define NQKV 4096
#define MROWS (Bb*Tt)  // 4096
#define QK_SCALE 0.0625f
#define WINDOW 1024

// ---------------- scratch ----------------------------------------------------
__device__ __align__(256) __half g_qkvh[(size_t)MROWS * NQKV];  // fp16 qkv (v used in-place)
__device__ __align__(256) __half g_xh[(size_t)MROWS * Dd];
__device__ __align__(256) __half g_qh[(size_t)MROWS * NQ];
__device__ __align__(256) __half g_kh[(size_t)MROWS * NKV];
__device__ __align__(256) __half g_aoh[(size_t)MROWS * NQ];
__device__ __align__(256) __half g_wfhi[(size_t)NQKV * Dd];     // Wq|Wk|Wv [N,K]
__device__ __align__(256) __half g_wohi[(size_t)Dd * NQ];
__device__ int g_work_ctr;

// ---------------- helpers ----------------------------------------------------
__device__ __forceinline__ uint32_t smem_u32(const void* p) {
    uint32_t a;
    asm("{ .reg .u64 t; cvta.to.shared.u64 t, %1; cvt.u32.u64 %0, t; }"
        : "=r"(a) : "l"(p));
    return a;
}
__device__ __forceinline__ void cp_async16(uint32_t saddr, const void* gaddr) {
    asm volatile("cp.async.cg.shared.global [%0], [%1], 16;"
                 :: "r"(saddr), "l"(gaddr) : "memory");
}
__device__ __forceinline__ void ldmat4(uint32_t* r, uint32_t addr) {
    asm volatile("ldmatrix.sync.aligned.m8n8.x4.shared.b16 {%0,%1,%2,%3}, [%4];"
                 : "=r"(r[0]), "=r"(r[1]), "=r"(r[2]), "=r"(r[3]) : "r"(addr));
}
__device__ __forceinline__ void ldmat4t(uint32_t* r, uint32_t addr) {
    asm volatile("ldmatrix.sync.aligned.m8n8.x4.trans.shared.b16 {%0,%1,%2,%3}, [%4];"
                 : "=r"(r[0]), "=r"(r[1]), "=r"(r[2]), "=r"(r[3]) : "r"(addr));
}
__device__ __forceinline__ void mma_f16(float* c, const uint32_t* a, const uint32_t* b) {
    asm volatile(
        "mma.sync.aligned.m16n8k16.row.col.f32.f16.f16.f32 "
        "{%0,%1,%2,%3}, {%4,%5,%6,%7}, {%8,%9}, {%0,%1,%2,%3};"
        : "+f"(c[0]), "+f"(c[1]), "+f"(c[2]), "+f"(c[3])
        : "r"(a[0]), "r"(a[1]), "r"(a[2]), "r"(a[3]), "r"(b[0]), "r"(b[1]));
}

// ---------------- prep kernels ------------------------------------------------
__global__ __launch_bounds__(256) void tohalf_kernel(
    const float4* __restrict__ in, __half* __restrict__ out, int n4)
{
    int i = blockIdx.x * 256 + threadIdx.x;
    if (i >= n4) return;
    float4 v = in[i];
    __half2* op = (__half2*)(out + (size_t)i * 4);
    op[0] = __half2(__float2half_rn(v.x), __float2half_rn(v.y));
    op[1] = __half2(__float2half_rn(v.z), __float2half_rn(v.w));
}

// in [K,N] fp32 -> out [N,K] fp16
__global__ __launch_bounds__(256) void transpose_half_kernel(
    const float* __restrict__ in, __half* __restrict__ hi, int K, int N)
{
    __shared__ float t[32][33];
    int n0 = blockIdx.x * 32, k0 = blockIdx.y * 32;
    int tx = threadIdx.x & 31, ty = threadIdx.x >> 5;
#pragma unroll
    for (int i = 0; i < 32; i += 8)
        t[ty + i][tx] = in[(size_t)(k0 + ty + i) * N + n0 + tx];
    __syncthreads();
#pragma unroll
    for (int i = 0; i < 32; i += 8)
        hi[(size_t)(n0 + ty + i) * K + k0 + tx] = __float2half_rn(t[tx][ty + i]);
}

__global__ void zero_ctr_kernel() { g_work_ctr = 0; }

// ---------------- mma.sync fp16 single-pass GEMM (fp32 out) -------------------
#define GP 80
#define TILEB (128 * GP)
#define STAGEB2 (2 * TILEB)

__global__ __launch_bounds__(256, 2) void mma_gemm1_kernel(
    const __half* __restrict__ A, const __half* __restrict__ B,
    float* __restrict__ C, int M, int N, int K)
{
    extern __shared__ char smem[];
    uint32_t sb = smem_u32(smem);
    int tid = threadIdx.x, lane = tid & 31, wid = tid >> 5;
    int wm = wid & 3, wn = wid >> 2;
    int row0 = blockIdx.y * 128, col0 = blockIdx.x * 128;

    const __half* gsrc[2] = { A + (size_t)row0 * K, B + (size_t)col0 * K };
    const int NC = K >> 5;

    int r_ld0 = tid >> 2, c16_0 = tid & 3;
    int r_ld1 = (tid + 256) >> 2, c16_1 = (tid + 256) & 3;

    float acc[2][8][4];
#pragma unroll
    for (int mt = 0; mt < 2; mt++)
#pragma unroll
        for (int nt = 0; nt < 8; nt++)
#pragma unroll
            for (int i = 0; i < 4; i++) acc[mt][nt][i] = 0.f;

    int grp = lane >> 3, lr = lane & 7;
    uint32_t aoff = (uint32_t)(((grp & 1) * 8 + lr) * GP + (grp >> 1) * 16);
    uint32_t boff = (uint32_t)(((grp >> 1) * 8 + lr) * GP + (grp & 1) * 16);

    auto load_stage = [&](int c) {
        uint32_t st = sb + (uint32_t)(c & 1) * STAGEB2;
        int kb = c * 32;
#pragma unroll
        for (int tile = 0; tile < 2; tile++) {
            const __half* g = gsrc[tile];
            uint32_t tb = st + (uint32_t)tile * TILEB;
            cp_async16(tb + (uint32_t)(r_ld0 * GP + c16_0 * 16),
                       g + (size_t)r_ld0 * K + kb + c16_0 * 8);
            cp_async16(tb + (uint32_t)(r_ld1 * GP + c16_1 * 16),
                       g + (size_t)r_ld1 * K + kb + c16_1 * 8);
        }
        asm volatile("cp.async.commit_group;" ::: "memory");
    };

    load_stage(0);

    for (int c = 0; c < NC; c++) {
        if (c + 1 < NC) {
            load_stage(c + 1);
            asm volatile("cp.async.wait_group 1;" ::: "memory");
        } else {
            asm volatile("cp.async.wait_group 0;" ::: "memory");
        }
        __syncthreads();

        uint32_t st = sb + (uint32_t)(c & 1) * STAGEB2;
        uint32_t A0 = st, B0 = st + TILEB;

#pragma unroll
        for (int kk = 0; kk < 2; kk++) {
            uint32_t kbyte = (uint32_t)kk * 32;
            uint32_t ah[2][4], bh[8][2];
#pragma unroll
            for (int mt = 0; mt < 2; mt++) {
                uint32_t rb = (uint32_t)((wm * 32 + mt * 16) * GP) + aoff + kbyte;
                ldmat4(ah[mt], A0 + rb);
            }
#pragma unroll
            for (int nt2 = 0; nt2 < 4; nt2++) {
                uint32_t rb = (uint32_t)((wn * 64 + nt2 * 16) * GP) + boff + kbyte;
                uint32_t r[4];
                ldmat4(r, B0 + rb);
                bh[nt2 * 2][0] = r[0]; bh[nt2 * 2][1] = r[1];
                bh[nt2 * 2 + 1][0] = r[2]; bh[nt2 * 2 + 1][1] = r[3];
            }
#pragma unroll
            for (int mt = 0; mt < 2; mt++)
#pragma unroll
                for (int nt = 0; nt < 8; nt++)
                    mma_f16(acc[mt][nt], ah[mt], bh[nt]);
        }
        __syncthreads();
    }

#pragma unroll
    for (int mt = 0; mt < 2; mt++) {
        int rg0 = row0 + wm * 32 + mt * 16 + (lane >> 2);
#pragma unroll
        for (int nt = 0; nt < 8; nt++) {
            int cg = col0 + wn * 64 + nt * 8 + (lane & 3) * 2;
            *(float2*)(C + (size_t)rg0 * N + cg) =
                make_float2(acc[mt][nt][0], acc[mt][nt][1]);
            *(float2*)(C + (size_t)(rg0 + 8) * N + cg) =
                make_float2(acc[mt][nt][2], acc[mt][nt][3]);
        }
    }
}

// ---------------- mma.sync fp16 single-pass GEMM (fp16 out, QKV) --------------
__global__ __launch_bounds__(256, 2) void mma_gemm1h_kernel(
    const __half* __restrict__ A, const __half* __restrict__ B,
    __half* __restrict__ C, int M, int N, int K)
{
    extern __shared__ char smem[];
    uint32_t sb = smem_u32(smem);
    int tid = threadIdx.x, lane = tid & 31, wid = tid >> 5;
    int wm = wid & 3, wn = wid >> 2;
    int row0 = blockIdx.y * 128, col0 = blockIdx.x * 128;

    const __half* gsrc[2] = { A + (size_t)row0 * K, B + (size_t)col0 * K };
    const int NC = K >> 5;

    int r_ld0 = tid >> 2, c16_0 = tid & 3;
    int r_ld1 = (tid + 256) >> 2, c16_1 = (tid + 256) & 3;

    float acc[2][8][4];
#pragma unroll
    for (int mt = 0; mt < 2; mt++)
#pragma unroll
        for (int nt = 0; nt < 8; nt++)
#pragma unroll
            for (int i = 0; i < 4; i++) acc[mt][nt][i] = 0.f;

    int grp = lane >> 3, lr = lane & 7;
    uint32_t aoff = (uint32_t)(((grp & 1) * 8 + lr) * GP + (grp >> 1) * 16);
    uint32_t boff = (uint32_t)(((grp >> 1) * 8 + lr) * GP + (grp & 1) * 16);

    auto load_stage = [&](int c) {
        uint32_t st = sb + (uint32_t)(c & 1) * STAGEB2;
        int kb = c * 32;
#pragma unroll
        for (int tile = 0; tile < 2; tile++) {
            const __half* g = gsrc[tile];
            uint32_t tb = st + (uint32_t)tile * TILEB;
            cp_async16(tb + (uint32_t)(r_ld0 * GP + c16_0 * 16),
                       g + (size_t)r_ld0 * K + kb + c16_0 * 8);
            cp_async16(tb + (uint32_t)(r_ld1 * GP + c16_1 * 16),
                       g + (size_t)r_ld1 * K + kb + c16_1 * 8);
        }
        asm volatile("cp.async.commit_group;" ::: "memory");
    };

    load_stage(0);

    for (int c = 0; c < NC; c++) {
        if (c + 1 < NC) {
            load_stage(c + 1);
            asm volatile("cp.async.wait_group 1;" ::: "memory");
        } else {
            asm volatile("cp.async.wait_group 0;" ::: "memory");
        }
        __syncthreads();

        uint32_t st = sb + (uint32_t)(c & 1) * STAGEB2;
        uint32_t A0 = st, B0 = st + TILEB;

#pragma unroll
        for (int kk = 0; kk < 2; kk++) {
            uint32_t kbyte = (uint32_t)kk * 32;
            uint32_t ah[2][4], bh[8][2];
#pragma unroll
            for (int mt = 0; mt < 2; mt++) {
                uint32_t rb = (uint32_t)((wm * 32 + mt * 16) * GP) + aoff + kbyte;
                ldmat4(ah[mt], A0 + rb);
            }
#pragma unroll
            for (int nt2 = 0; nt2 < 4; nt2++) {
                uint32_t rb = (uint32_t)((wn * 64 + nt2 * 16) * GP) + boff + kbyte;
                uint32_t r[4];
                ldmat4(r, B0 + rb);
                bh[nt2 * 2][0] = r[0]; bh[nt2 * 2][1] = r[1];
                bh[nt2 * 2 + 1][0] = r[2]; bh[nt2 * 2 + 1][1] = r[3];
            }
#pragma unroll
            for (int mt = 0; mt < 2; mt++)
#pragma unroll
                for (int nt = 0; nt < 8; nt++)
                    mma_f16(acc[mt][nt], ah[mt], bh[nt]);
        }
        __syncthreads();
    }

#pragma unroll
    for (int mt = 0; mt < 2; mt++) {
        int rg0 = row0 + wm * 32 + mt * 16 + (lane >> 2);
#pragma unroll
        for (int nt = 0; nt < 8; nt++) {
            int cg = col0 + wn * 64 + nt * 8 + (lane & 3) * 2;
            __half2 h0 = __floats2half2_rn(acc[mt][nt][0], acc[mt][nt][1]);
            __half2 h1 = __floats2half2_rn(acc[mt][nt][2], acc[mt][nt][3]);
            *(__half2*)(C + (size_t)rg0 * N + cg) = h0;
            *(__half2*)(C + (size_t)(rg0 + 8) * N + cg) = h1;
        }
    }
}

// ---------------- Gemma RMSNorm: fp16 qkv -> fp16 q (scaled) / k --------------
__global__ __launch_bounds__(256) void rmsnorm_qk_kernel(
    const __half* __restrict__ qkv, const float* __restrict__ qsc,
    const float* __restrict__ ksc, __half* __restrict__ qh,
    __half* __restrict__ kh)
{
    int blk = blockIdx.x;
    int row = blk / 12, hh = blk % 12;
    int d = threadIdx.x;
    const __half* p;
    const float* sc;
    __half* o;
    float osc;
    if (hh < 8) {
        p = qkv + (size_t)row * NQKV + hh * HD;
        o = qh + (size_t)row * NQ + hh * HD;
        sc = qsc; osc = QK_SCALE;
    } else {
        int g = hh - 8;
        p = qkv + (size_t)row * NQKV + NQ + g * HD;
        o = kh + (size_t)row * NKV + g * HD;
        sc = ksc; osc = 1.f;
    }
    float x = __half2float(p[d]);
    float v = x * x;
#pragma unroll
    for (int of = 16; of > 0; of >>= 1) v += __shfl_xor_sync(0xffffffffu, v, of);
    __shared__ float ws[8];
    __shared__ float stot;
    if ((d & 31) == 0) ws[d >> 5] = v;
    __syncthreads();
    if (d == 0) {
        float s = 0.f;
#pragma unroll
        for (int i = 0; i < 8; i++) s += ws[i];
        stot = s;
    }
    __syncthreads();
    float r = rsqrtf(stot * (1.f / HD) + 1e-6f);
    o[d] = __float2half_rn(x * r * (1.f + sc[d]) * osc);
}

// ---------------- persistent FA2 attention ------------------------------------
#define NAQP 528
#define N_QB 0
#define N_KB (N_QB + 128 * NAQP)
#define N_VB (N_KB + 2 * 64 * NAQP)
#define N_TOT (N_VB + 2 * 64 * NAQP + 128)
#define NTILES (16 * Hh * Bb)   // 256

__global__ __launch_bounds__(256, 1) void attn_fa2_kernel()
{
    extern __shared__ char sm[];
    uint32_t sb = smem_u32(sm);
    __shared__ int s_w;

    int tid = threadIdx.x, lane = tid & 31, wid = tid >> 5;

    int grp = lane >> 3, lr = lane & 7;
    uint32_t aoff = (uint32_t)(((grp & 1) * 8 + lr) * NAQP + (grp >> 1) * 16);
    uint32_t boff = (uint32_t)(((grp >> 1) * 8 + lr) * NAQP + (grp & 1) * 16);
    int q4 = lane & 3;
    int row_m = wid * 16 + (lane >> 2);

    for (;;) {
        if (tid == 0) s_w = atomicAdd(&g_work_ctr, 1);
        __syncthreads();
        int w = s_w;
        if (w >= NTILES) return;

        int qt = 15 - (w >> 4);     // heavy q-tiles first
        int hb = w & 15;
        int h = hb & 7, b = hb >> 3;
        int t0 = qt * 128;
        int kvh = h & (Gg - 1);

        // ---- prologue: Q tile + first K/V tile ----
        const __half* qbase = g_qh + ((size_t)(b * Tt + t0)) * NQ + h * HD;
        for (int idx = tid; idx < 128 * 32; idx += 256) {
            int r = idx >> 5, c = idx & 31;
            cp_async16(sb + N_QB + (uint32_t)(r * NAQP + c * 16),
                       qbase + (size_t)r * NQ + c * 8);
        }

        int kb0 = max(0, t0 - (WINDOW - 1)) >> 6;
        int kb1 = (t0 + 127) >> 6;

        auto load_kv = [&](int kb, int buf) {
            const __half* kbase = g_kh + ((size_t)(b * Tt + kb * 64)) * NKV + kvh * HD;
            const __half* vbase = g_qkvh + ((size_t)(b * Tt + kb * 64)) * NQKV
                                  + NQ + NKV + kvh * HD;   // V in-place
            uint32_t kdst = sb + N_KB + (uint32_t)buf * (64 * NAQP);
            uint32_t vdst = sb + N_VB + (uint32_t)buf * (64 * NAQP);
            for (int idx = tid; idx < 64 * 32; idx += 256) {
                int r = idx >> 5, c = idx & 31;
                uint32_t so = (uint32_t)(r * NAQP + c * 16);
                cp_async16(kdst + so, kbase + (size_t)r * NKV + c * 8);
                cp_async16(vdst + so, vbase + (size_t)r * NQKV + c * 8);
            }
            asm volatile("cp.async.commit_group;" ::: "memory");
        };

        load_kv(kb0, 0);

        float o[32][4];
#pragma unroll
        for (int f = 0; f < 32; f++)
#pragma unroll
            for (int i = 0; i < 4; i++) o[f][i] = 0.f;

        float m0r = -1e30f, m1r = -1e30f;
        float l0r = 0.f, l1r = 0.f;

        int gr0 = t0 + row_m;
        int gr1 = gr0 + 8;

        for (int kb = kb0; kb <= kb1; kb++) {
            int buf = (kb - kb0) & 1;
            asm volatile("cp.async.wait_group 0;" ::: "memory");
            __syncthreads();
            if (kb < kb1) load_kv(kb + 1, buf ^ 1);

            uint32_t Kb = sb + N_KB + (uint32_t)buf * (64 * NAQP);
            uint32_t Vb = sb + N_VB + (uint32_t)buf * (64 * NAQP);
            int s0 = kb * 64;

            float sc[8][4];
#pragma unroll
            for (int j = 0; j < 8; j++)
#pragma unroll
                for (int i = 0; i < 4; i++) sc[j][i] = 0.f;
#pragma unroll 4
            for (int kd = 0; kd < 16; kd++) {
                uint32_t a[4];
                ldmat4(a, sb + N_QB + (uint32_t)(wid * 16) * NAQP + kd * 32 + aoff);
#pragma unroll
                for (int nt2 = 0; nt2 < 4; nt2++) {
                    uint32_t bf[4];
                    ldmat4(bf, Kb + (uint32_t)(nt2 * 16) * NAQP + kd * 32 + boff);
                    mma_f16(sc[nt2 * 2], a, &bf[0]);
                    mma_f16(sc[nt2 * 2 + 1], a, &bf[2]);
                }
            }

            float mx0 = -1e30f, mx1 = -1e30f;
#pragma unroll
            for (int j = 0; j < 8; j++) {
                int c0 = s0 + j * 8 + q4 * 2, c1 = c0 + 1;
                bool a00 = (c0 <= gr0) && (c0 > gr0 - WINDOW);
                bool a01 = (c1 <= gr0) && (c1 > gr0 - WINDOW);
                bool a10 = (c0 <= gr1) && (c0 > gr1 - WINDOW);
                bool a11 = (c1 <= gr1) && (c1 > gr1 - WINDOW);
                if (a00) mx0 = fmaxf(mx0, sc[j][0]);
                if (a01) mx0 = fmaxf(mx0, sc[j][1]);
                if (a10) mx1 = fmaxf(mx1, sc[j][2]);
                if (a11) mx1 = fmaxf(mx1, sc[j][3]);
                if (!a00) sc[j][0] = -1e30f;
                if (!a01) sc[j][1] = -1e30f;
                if (!a10) sc[j][2] = -1e30f;
                if (!a11) sc[j][3] = -1e30f;
            }
            mx0 = fmaxf(mx0, __shfl_xor_sync(0xffffffffu, mx0, 1));
            mx0 = fmaxf(mx0, __shfl_xor_sync(0xffffffffu, mx0, 2));
            mx1 = fmaxf(mx1, __shfl_xor_sync(0xffffffffu, mx1, 1));
            mx1 = fmaxf(mx1, __shfl_xor_sync(0xffffffffu, mx1, 2));

            float mn0 = fmaxf(m0r, mx0), mn1 = fmaxf(m1r, mx1);
            float al0 = __expf(m0r - mn0), al1 = __expf(m1r - mn1);

            float s0sum = 0.f, s1sum = 0.f;
            uint32_t pfrag[8][2];
#pragma unroll
            for (int j = 0; j < 8; j++) {
                float p00 = (sc[j][0] > -1e29f) ? __expf(sc[j][0] - mn0) : 0.f;
                float p01 = (sc[j][1] > -1e29f) ? __expf(sc[j][1] - mn0) : 0.f;
                float p10 = (sc[j][2] > -1e29f) ? __expf(sc[j][2] - mn1) : 0.f;
                float p11 = (sc[j][3] > -1e29f) ? __expf(sc[j][3] - mn1) : 0.f;
                s0sum += p00 + p01;
                s1sum += p10 + p11;
                __half2 h0 = __floats2half2_rn(p00, p01);
                __half2 h1 = __floats2half2_rn(p10, p11);
                pfrag[j][0] = *(uint32_t*)&h0;
                pfrag[j][1] = *(uint32_t*)&h1;
            }
            s0sum += __shfl_xor_sync(0xffffffffu, s0sum, 1);
            s0sum += __shfl_xor_sync(0xffffffffu, s0sum, 2);
            s1sum += __shfl_xor_sync(0xffffffffu, s1sum, 1);
            s1sum += __shfl_xor_sync(0xffffffffu, s1sum, 2);
            l0r = l0r * al0 + s0sum;
            l1r = l1r * al1 + s1sum;
            m0r = mn0; m1r = mn1;

#pragma unroll
            for (int f = 0; f < 32; f++) {
                o[f][0] *= al0; o[f][1] *= al0;
                o[f][2] *= al1; o[f][3] *= al1;
            }

#pragma unroll
            for (int kk = 0; kk < 4; kk++) {
                uint32_t pa[4];
                pa[0] = pfrag[kk * 2][0];
                pa[1] = pfrag[kk * 2][1];
                pa[2] = pfrag[kk * 2 + 1][0];
                pa[3] = pfrag[kk * 2 + 1][1];
#pragma unroll
                for (int nb = 0; nb < 16; nb++) {
                    uint32_t bv[4];
                    ldmat4t(bv, Vb + (uint32_t)(kk * 16) * NAQP
                                + (uint32_t)(nb * 32) + aoff);
                    mma_f16(o[nb * 2],     pa, &bv[0]);
                    mma_f16(o[nb * 2 + 1], pa, &bv[2]);
                }
            }
        }

        // ---- epilogue ----
        float il0 = 1.f / l0r, il1 = 1.f / l1r;
        __half* obase = g_aoh + ((size_t)(b * Tt + t0)) * NQ + h * HD;
#pragma unroll
        for (int f = 0; f < 32; f++) {
            int col = f * 8 + q4 * 2;
            __half2 h0 = __floats2half2_rn(o[f][0] * il0, o[f][1] * il0);
            __half2 h1 = __floats2half2_rn(o[f][2] * il1, o[f][3] * il1);
            *(__half2*)(obase + (size_t)row_m * NQ + col) = h0;
            *(__half2*)(obase + (size_t)(row_m + 8) * NQ + col) = h1;
        }
        __syncthreads();   // all warps done with smem before next tile
    }
}

// ---------------- launch -------------------------------------------------------
extern "C" void kernel_launch(void* const* d_in, const int* in_sizes, int n_in,
                              void* d_out, int out_size)
{
    const float* x   = (const float*)d_in[0];
    const float* Wq  = (const float*)d_in[1];
    const float* Wk  = (const float*)d_in[2];
    const float* Wv  = (const float*)d_in[3];
    const float* Wo  = (const float*)d_in[4];
    const float* qsc = (const float*)d_in[5];
    const float* ksc = (const float*)d_in[6];
    float* out = (float*)d_out;

    void *pqkv, *pxh, *pqh, *pkh, *paoh, *pwfh, *pwoh;
    cudaGetSymbolAddress(&pqkv, g_qkvh);
    cudaGetSymbolAddress(&pxh, g_xh);
    cudaGetSymbolAddress(&pqh, g_qh);
    cudaGetSymbolAddress(&pkh, g_kh);
    cudaGetSymbolAddress(&paoh, g_aoh);
    cudaGetSymbolAddress(&pwfh, g_wfhi);
    cudaGetSymbolAddress(&pwoh, g_wohi);

    __half* qkvh = (__half*)pqkv;
    __half* xh  = (__half*)pxh;
    __half* qh  = (__half*)pqh;
    __half* kh  = (__half*)pkh;
    __half* aoh = (__half*)paoh;
    __half* wfh = (__half*)pwfh;
    __half* woh = (__half*)pwoh;

    size_t gemm1_smem = 2 * STAGEB2;  // 40960
    cudaFuncSetAttribute(mma_gemm1_kernel,
                         cudaFuncAttributeMaxDynamicSharedMemorySize, (int)gemm1_smem);
    cudaFuncSetAttribute(mma_gemm1h_kernel,
                         cudaFuncAttributeMaxDynamicSharedMemorySize, (int)gemm1_smem);
    cudaFuncSetAttribute(attn_fa2_kernel,
                         cudaFuncAttributeMaxDynamicSharedMemorySize, N_TOT);

    // ---- operand prep ----
    {
        int n4 = (MROWS * Dd) / 4;
        tohalf_kernel<<<(n4 + 255) / 256, 256>>>((const float4*)x, xh, n4);
        transpose_half_kernel<<<dim3(NQ / 32, Dd / 32), 256>>>(Wq, wfh, Dd, NQ);
        transpose_half_kernel<<<dim3(NKV / 32, Dd / 32), 256>>>(
            Wk, wfh + (size_t)NQ * Dd, Dd, NKV);
        transpose_half_kernel<<<dim3(NKV / 32, Dd / 32), 256>>>(
            Wv, wfh + (size_t)(NQ + NKV) * Dd, Dd, NKV);
        transpose_half_kernel<<<dim3(Dd / 32, NQ / 32), 256>>>(Wo, woh, NQ, Dd);
    }

    // ---- merged QKV projection (fp16 out) ----
    mma_gemm1h_kernel<<<dim3(NQKV / 128, MROWS / 128), 256, gemm1_smem>>>(
        xh, wfh, qkvh, MROWS, NQKV, Dd);

    // ---- qk-norm -> fp16 (V stays in-place in qkvh) ----
    rmsnorm_qk_kernel<<<MROWS * 12, 256>>>(qkvh, qsc, ksc, qh, kh);

    // ---- attention (persistent FA2) ----
    zero_ctr_kernel<<<1, 1>>>();
    attn_fa2_kernel<<<152, 256, N_TOT>>>();

    // ---- output projection ----
    mma_gemm1_kernel<<<dim3(Dd / 128, MROWS / 128), 256, gemm1_smem>>>(
        aoh, woh, out, MROWS, Dd, NQ);
}

// round 13
// speedup vs baseline: 5.7751x; 1.1688x over previous
#include <cuda_runtime.h>
#include <cuda_fp16.h>
#include <math.h>
#include <cstdint>

// ---------------- problem constants ----------------
#define Bb 2
#define Tt 2048
#define Dd 2560
#define Hh 8
#define Gg 4
#define HD 256
#define NQ (Hh*HD)     // 2048
#define NKV (Gg*HD)    // 1024
#define NQKV 4096
#define MROWS (Bb*Tt)  // 4096
#define QK_SCALE 0.0625f
#define WINDOW 1024

// ---------------- scratch ----------------------------------------------------
__device__ __align__(256) __half g_qkvh[(size_t)MROWS * NQKV];  // fp16 qkv (v in-place)
__device__ __align__(256) __half g_xh[(size_t)MROWS * Dd];
__device__ __align__(256) __half g_qh[(size_t)MROWS * NQ];
__device__ __align__(256) __half g_kh[(size_t)MROWS * NKV];
__device__ __align__(256) __half g_aoh[(size_t)MROWS * NQ];
__device__ __align__(256) __half g_wfhi[(size_t)NQKV * Dd];     // Wq|Wk|Wv [N,K]
__device__ __align__(256) __half g_wohi[(size_t)Dd * NQ];
__device__ int g_work_ctr;

// ---------------- helpers ----------------------------------------------------
__device__ __forceinline__ uint32_t smem_u32(const void* p) {
    uint32_t a;
    asm("{ .reg .u64 t; cvta.to.shared.u64 t, %1; cvt.u32.u64 %0, t; }"
        : "=r"(a) : "l"(p));
    return a;
}
__device__ __forceinline__ void cp_async16(uint32_t saddr, const void* gaddr) {
    asm volatile("cp.async.cg.shared.global [%0], [%1], 16;"
                 :: "r"(saddr), "l"(gaddr) : "memory");
}
__device__ __forceinline__ void ldmat4(uint32_t* r, uint32_t addr) {
    asm volatile("ldmatrix.sync.aligned.m8n8.x4.shared.b16 {%0,%1,%2,%3}, [%4];"
                 : "=r"(r[0]), "=r"(r[1]), "=r"(r[2]), "=r"(r[3]) : "r"(addr));
}
__device__ __forceinline__ void ldmat4t(uint32_t* r, uint32_t addr) {
    asm volatile("ldmatrix.sync.aligned.m8n8.x4.trans.shared.b16 {%0,%1,%2,%3}, [%4];"
                 : "=r"(r[0]), "=r"(r[1]), "=r"(r[2]), "=r"(r[3]) : "r"(addr));
}
__device__ __forceinline__ void mma_f16(float* c, const uint32_t* a, const uint32_t* b) {
    asm volatile(
        "mma.sync.aligned.m16n8k16.row.col.f32.f16.f16.f32 "
        "{%0,%1,%2,%3}, {%4,%5,%6,%7}, {%8,%9}, {%0,%1,%2,%3};"
        : "+f"(c[0]), "+f"(c[1]), "+f"(c[2]), "+f"(c[3])
        : "r"(a[0]), "r"(a[1]), "r"(a[2]), "r"(a[3]), "r"(b[0]), "r"(b[1]));
}

// ---------------- prep kernels ------------------------------------------------
__global__ __launch_bounds__(256) void tohalf_kernel(
    const float4* __restrict__ in, __half* __restrict__ out, int n4)
{
    int i = blockIdx.x * 256 + threadIdx.x;
    if (i >= n4) return;
    float4 v = in[i];
    __half2* op = (__half2*)(out + (size_t)i * 4);
    op[0] = __half2(__float2half_rn(v.x), __float2half_rn(v.y));
    op[1] = __half2(__float2half_rn(v.z), __float2half_rn(v.w));
}

// in [K,N] fp32 -> out [N,K] fp16
__global__ __launch_bounds__(256) void transpose_half_kernel(
    const float* __restrict__ in, __half* __restrict__ hi, int K, int N)
{
    __shared__ float t[32][33];
    int n0 = blockIdx.x * 32, k0 = blockIdx.y * 32;
    int tx = threadIdx.x & 31, ty = threadIdx.x >> 5;
#pragma unroll
    for (int i = 0; i < 32; i += 8)
        t[ty + i][tx] = in[(size_t)(k0 + ty + i) * N + n0 + tx];
    __syncthreads();
#pragma unroll
    for (int i = 0; i < 32; i += 8)
        hi[(size_t)(n0 + ty + i) * K + k0 + tx] = __float2half_rn(t[tx][ty + i]);
}

__global__ void zero_ctr_kernel() { g_work_ctr = 0; }

// ---------------- BK=64 fp16 single-pass GEMM ---------------------------------
// smem tile 128 x 64 halves, pitch 144 B (conflict-free: 144 mod 128 = 16).
#define GPK 144
#define TILEK (128 * GPK)       // 18432
#define STAGEK (2 * TILEK)      // 36864 (A + B)

template <typename OutT>
__global__ __launch_bounds__(256, 2) void mma_gemm64_kernel(
    const __half* __restrict__ A, const __half* __restrict__ B,
    OutT* __restrict__ C, int M, int N, int K)
{
    extern __shared__ char smem[];
    uint32_t sb = smem_u32(smem);
    int tid = threadIdx.x, lane = tid & 31, wid = tid >> 5;
    int wm = wid & 3, wn = wid >> 2;
    int row0 = blockIdx.y * 128, col0 = blockIdx.x * 128;

    const __half* gA = A + (size_t)row0 * K;
    const __half* gB = B + (size_t)col0 * K;
    const int NC = K >> 6;

    float acc[2][8][4];
#pragma unroll
    for (int mt = 0; mt < 2; mt++)
#pragma unroll
        for (int nt = 0; nt < 8; nt++)
#pragma unroll
            for (int i = 0; i < 4; i++) acc[mt][nt][i] = 0.f;

    int grp = lane >> 3, lr = lane & 7;
    uint32_t aoff = (uint32_t)(((grp & 1) * 8 + lr) * GPK + (grp >> 1) * 16);
    uint32_t boff = (uint32_t)(((grp >> 1) * 8 + lr) * GPK + (grp & 1) * 16);

    // copy coords: per tile 128 rows x 8 16B-chunks = 1024 chunks, 4 iters
    int rr = tid >> 3, cc = tid & 7;

    auto load_stage = [&](int c) {
        uint32_t st = sb + (uint32_t)(c & 1) * STAGEK;
        int kb = c * 64;
#pragma unroll
        for (int i = 0; i < 4; i++) {
            int r = rr + i * 32;
            uint32_t so = (uint32_t)(r * GPK + cc * 16);
            cp_async16(st + so, gA + (size_t)r * K + kb + cc * 8);
            cp_async16(st + TILEK + so, gB + (size_t)r * K + kb + cc * 8);
        }
        asm volatile("cp.async.commit_group;" ::: "memory");
    };

    load_stage(0);

    for (int c = 0; c < NC; c++) {
        if (c + 1 < NC) {
            load_stage(c + 1);
            asm volatile("cp.async.wait_group 1;" ::: "memory");
        } else {
            asm volatile("cp.async.wait_group 0;" ::: "memory");
        }
        __syncthreads();

        uint32_t st = sb + (uint32_t)(c & 1) * STAGEK;
        uint32_t A0 = st, B0 = st + TILEK;

#pragma unroll
        for (int kk = 0; kk < 4; kk++) {
            uint32_t kbyte = (uint32_t)kk * 32;
            uint32_t ah[2][4], bh[8][2];
#pragma unroll
            for (int mt = 0; mt < 2; mt++) {
                uint32_t rb = (uint32_t)((wm * 32 + mt * 16) * GPK) + aoff + kbyte;
                ldmat4(ah[mt], A0 + rb);
            }
#pragma unroll
            for (int nt2 = 0; nt2 < 4; nt2++) {
                uint32_t rb = (uint32_t)((wn * 64 + nt2 * 16) * GPK) + boff + kbyte;
                uint32_t r[4];
                ldmat4(r, B0 + rb);
                bh[nt2 * 2][0] = r[0]; bh[nt2 * 2][1] = r[1];
                bh[nt2 * 2 + 1][0] = r[2]; bh[nt2 * 2 + 1][1] = r[3];
            }
#pragma unroll
            for (int mt = 0; mt < 2; mt++)
#pragma unroll
                for (int nt = 0; nt < 8; nt++)
                    mma_f16(acc[mt][nt], ah[mt], bh[nt]);
        }
        __syncthreads();
    }

#pragma unroll
    for (int mt = 0; mt < 2; mt++) {
        int rg0 = row0 + wm * 32 + mt * 16 + (lane >> 2);
#pragma unroll
        for (int nt = 0; nt < 8; nt++) {
            int cg = col0 + wn * 64 + nt * 8 + (lane & 3) * 2;
            if (sizeof(OutT) == 4) {
                *(float2*)((float*)C + (size_t)rg0 * N + cg) =
                    make_float2(acc[mt][nt][0], acc[mt][nt][1]);
                *(float2*)((float*)C + (size_t)(rg0 + 8) * N + cg) =
                    make_float2(acc[mt][nt][2], acc[mt][nt][3]);
            } else {
                __half2 h0 = __floats2half2_rn(acc[mt][nt][0], acc[mt][nt][1]);
                __half2 h1 = __floats2half2_rn(acc[mt][nt][2], acc[mt][nt][3]);
                *(__half2*)((__half*)C + (size_t)rg0 * N + cg) = h0;
                *(__half2*)((__half*)C + (size_t)(rg0 + 8) * N + cg) = h1;
            }
        }
    }
}

// ---------------- warp-per-row Gemma RMSNorm -----------------------------------
// 8 warps/block, each warp = one (row, head) job; lane owns 8 contiguous elems.
__global__ __launch_bounds__(256) void rmsnorm_qk_kernel(
    const __half* __restrict__ qkv, const float* __restrict__ qsc,
    const float* __restrict__ ksc, __half* __restrict__ qh,
    __half* __restrict__ kh)
{
    int job = blockIdx.x * 8 + (threadIdx.x >> 5);
    int lane = threadIdx.x & 31;
    int row = job / 12, hh = job % 12;

    const __half* p;
    const float* sc;
    __half* o;
    float osc;
    if (hh < 8) {
        p = qkv + (size_t)row * NQKV + hh * HD;
        o = qh + (size_t)row * NQ + hh * HD;
        sc = qsc; osc = QK_SCALE;
    } else {
        int g = hh - 8;
        p = qkv + (size_t)row * NQKV + NQ + g * HD;
        o = kh + (size_t)row * NKV + g * HD;
        sc = ksc; osc = 1.f;
    }

    // load 8 halves (16 B)
    uint4 raw = *(const uint4*)(p + lane * 8);
    __half2 hv[4];
    hv[0] = *(__half2*)&raw.x; hv[1] = *(__half2*)&raw.y;
    hv[2] = *(__half2*)&raw.z; hv[3] = *(__half2*)&raw.w;
    float xv[8];
#pragma unroll
    for (int i = 0; i < 4; i++) {
        float2 f = __half22float2(hv[i]);
        xv[i * 2] = f.x; xv[i * 2 + 1] = f.y;
    }
    float v = 0.f;
#pragma unroll
    for (int i = 0; i < 8; i++) v += xv[i] * xv[i];
#pragma unroll
    for (int of = 16; of > 0; of >>= 1) v += __shfl_xor_sync(0xffffffffu, v, of);

    float r = rsqrtf(v * (1.f / HD) + 1e-6f) * osc;

    float4 s0 = *(const float4*)(sc + lane * 8);
    float4 s1 = *(const float4*)(sc + lane * 8 + 4);
    float sv[8] = { s0.x, s0.y, s0.z, s0.w, s1.x, s1.y, s1.z, s1.w };

    __half2 ov[4];
#pragma unroll
    for (int i = 0; i < 4; i++)
        ov[i] = __floats2half2_rn(xv[i * 2] * r * (1.f + sv[i * 2]),
                                  xv[i * 2 + 1] * r * (1.f + sv[i * 2 + 1]));
    uint4 out;
    out.x = *(uint32_t*)&ov[0]; out.y = *(uint32_t*)&ov[1];
    out.z = *(uint32_t*)&ov[2]; out.w = *(uint32_t*)&ov[3];
    *(uint4*)(o + lane * 8) = out;
}

// ---------------- persistent FA2 attention ------------------------------------
#define NAQP 528
#define N_QB 0
#define N_KB (N_QB + 128 * NAQP)
#define N_VB (N_KB + 2 * 64 * NAQP)
#define N_TOT (N_VB + 2 * 64 * NAQP + 128)
#define NTILES (16 * Hh * Bb)   // 256

__global__ __launch_bounds__(256, 1) void attn_fa2_kernel()
{
    extern __shared__ char sm[];
    uint32_t sb = smem_u32(sm);
    __shared__ int s_w;

    int tid = threadIdx.x, lane = tid & 31, wid = tid >> 5;

    int grp = lane >> 3, lr = lane & 7;
    uint32_t aoff = (uint32_t)(((grp & 1) * 8 + lr) * NAQP + (grp >> 1) * 16);
    uint32_t boff = (uint32_t)(((grp >> 1) * 8 + lr) * NAQP + (grp & 1) * 16);
    int q4 = lane & 3;
    int row_m = wid * 16 + (lane >> 2);

    for (;;) {
        if (tid == 0) s_w = atomicAdd(&g_work_ctr, 1);
        __syncthreads();
        int w = s_w;
        if (w >= NTILES) return;

        int qt = 15 - (w >> 4);     // heavy q-tiles first
        int hb = w & 15;
        int h = hb & 7, b = hb >> 3;
        int t0 = qt * 128;
        int kvh = h & (Gg - 1);

        const __half* qbase = g_qh + ((size_t)(b * Tt + t0)) * NQ + h * HD;
        for (int idx = tid; idx < 128 * 32; idx += 256) {
            int r = idx >> 5, c = idx & 31;
            cp_async16(sb + N_QB + (uint32_t)(r * NAQP + c * 16),
                       qbase + (size_t)r * NQ + c * 8);
        }

        int kb0 = max(0, t0 - (WINDOW - 1)) >> 6;
        int kb1 = (t0 + 127) >> 6;

        auto load_kv = [&](int kb, int buf) {
            const __half* kbase = g_kh + ((size_t)(b * Tt + kb * 64)) * NKV + kvh * HD;
            const __half* vbase = g_qkvh + ((size_t)(b * Tt + kb * 64)) * NQKV
                                  + NQ + NKV + kvh * HD;
            uint32_t kdst = sb + N_KB + (uint32_t)buf * (64 * NAQP);
            uint32_t vdst = sb + N_VB + (uint32_t)buf * (64 * NAQP);
            for (int idx = tid; idx < 64 * 32; idx += 256) {
                int r = idx >> 5, c = idx & 31;
                uint32_t so = (uint32_t)(r * NAQP + c * 16);
                cp_async16(kdst + so, kbase + (size_t)r * NKV + c * 8);
                cp_async16(vdst + so, vbase + (size_t)r * NQKV + c * 8);
            }
            asm volatile("cp.async.commit_group;" ::: "memory");
        };

        load_kv(kb0, 0);

        float o[32][4];
#pragma unroll
        for (int f = 0; f < 32; f++)
#pragma unroll
            for (int i = 0; i < 4; i++) o[f][i] = 0.f;

        float m0r = -1e30f, m1r = -1e30f;
        float l0r = 0.f, l1r = 0.f;

        int gr0 = t0 + row_m;
        int gr1 = gr0 + 8;

        for (int kb = kb0; kb <= kb1; kb++) {
            int buf = (kb - kb0) & 1;
            asm volatile("cp.async.wait_group 0;" ::: "memory");
            __syncthreads();
            if (kb < kb1) load_kv(kb + 1, buf ^ 1);

            uint32_t Kb = sb + N_KB + (uint32_t)buf * (64 * NAQP);
            uint32_t Vb = sb + N_VB + (uint32_t)buf * (64 * NAQP);
            int s0 = kb * 64;

            float sc[8][4];
#pragma unroll
            for (int j = 0; j < 8; j++)
#pragma unroll
                for (int i = 0; i < 4; i++) sc[j][i] = 0.f;
#pragma unroll 4
            for (int kd = 0; kd < 16; kd++) {
                uint32_t a[4];
                ldmat4(a, sb + N_QB + (uint32_t)(wid * 16) * NAQP + kd * 32 + aoff);
#pragma unroll
                for (int nt2 = 0; nt2 < 4; nt2++) {
                    uint32_t bf[4];
                    ldmat4(bf, Kb + (uint32_t)(nt2 * 16) * NAQP + kd * 32 + boff);
                    mma_f16(sc[nt2 * 2], a, &bf[0]);
                    mma_f16(sc[nt2 * 2 + 1], a, &bf[2]);
                }
            }

            float mx0 = -1e30f, mx1 = -1e30f;
#pragma unroll
            for (int j = 0; j < 8; j++) {
                int c0 = s0 + j * 8 + q4 * 2, c1 = c0 + 1;
                bool a00 = (c0 <= gr0) && (c0 > gr0 - WINDOW);
                bool a01 = (c1 <= gr0) && (c1 > gr0 - WINDOW);
                bool a10 = (c0 <= gr1) && (c0 > gr1 - WINDOW);
                bool a11 = (c1 <= gr1) && (c1 > gr1 - WINDOW);
                if (a00) mx0 = fmaxf(mx0, sc[j][0]);
                if (a01) mx0 = fmaxf(mx0, sc[j][1]);
                if (a10) mx1 = fmaxf(mx1, sc[j][2]);
                if (a11) mx1 = fmaxf(mx1, sc[j][3]);
                if (!a00) sc[j][0] = -1e30f;
                if (!a01) sc[j][1] = -1e30f;
                if (!a10) sc[j][2] = -1e30f;
                if (!a11) sc[j][3] = -1e30f;
            }
            mx0 = fmaxf(mx0, __shfl_xor_sync(0xffffffffu, mx0, 1));
            mx0 = fmaxf(mx0, __shfl_xor_sync(0xffffffffu, mx0, 2));
            mx1 = fmaxf(mx1, __shfl_xor_sync(0xffffffffu, mx1, 1));
            mx1 = fmaxf(mx1, __shfl_xor_sync(0xffffffffu, mx1, 2));

            float mn0 = fmaxf(m0r, mx0), mn1 = fmaxf(m1r, mx1);
            float al0 = __expf(m0r - mn0), al1 = __expf(m1r - mn1);

            float s0sum = 0.f, s1sum = 0.f;
            uint32_t pfrag[8][2];
#pragma unroll
            for (int j = 0; j < 8; j++) {
                float p00 = (sc[j][0] > -1e29f) ? __expf(sc[j][0] - mn0) : 0.f;
                float p01 = (sc[j][1] > -1e29f) ? __expf(sc[j][1] - mn0) : 0.f;
                float p10 = (sc[j][2] > -1e29f) ? __expf(sc[j][2] - mn1) : 0.f;
                float p11 = (sc[j][3] > -1e29f) ? __expf(sc[j][3] - mn1) : 0.f;
                s0sum += p00 + p01;
                s1sum += p10 + p11;
                __half2 h0 = __floats2half2_rn(p00, p01);
                __half2 h1 = __floats2half2_rn(p10, p11);
                pfrag[j][0] = *(uint32_t*)&h0;
                pfrag[j][1] = *(uint32_t*)&h1;
            }
            s0sum += __shfl_xor_sync(0xffffffffu, s0sum, 1);
            s0sum += __shfl_xor_sync(0xffffffffu, s0sum, 2);
            s1sum += __shfl_xor_sync(0xffffffffu, s1sum, 1);
            s1sum += __shfl_xor_sync(0xffffffffu, s1sum, 2);
            l0r = l0r * al0 + s0sum;
            l1r = l1r * al1 + s1sum;
            m0r = mn0; m1r = mn1;

#pragma unroll
            for (int f = 0; f < 32; f++) {
                o[f][0] *= al0; o[f][1] *= al0;
                o[f][2] *= al1; o[f][3] *= al1;
            }

#pragma unroll
            for (int kk = 0; kk < 4; kk++) {
                uint32_t pa[4];
                pa[0] = pfrag[kk * 2][0];
                pa[1] = pfrag[kk * 2][1];
                pa[2] = pfrag[kk * 2 + 1][0];
                pa[3] = pfrag[kk * 2 + 1][1];
#pragma unroll
                for (int nb = 0; nb < 16; nb++) {
                    uint32_t bv[4];
                    ldmat4t(bv, Vb + (uint32_t)(kk * 16) * NAQP
                                + (uint32_t)(nb * 32) + aoff);
                    mma_f16(o[nb * 2],     pa, &bv[0]);
                    mma_f16(o[nb * 2 + 1], pa, &bv[2]);
                }
            }
        }

        float il0 = 1.f / l0r, il1 = 1.f / l1r;
        __half* obase = g_aoh + ((size_t)(b * Tt + t0)) * NQ + h * HD;
#pragma unroll
        for (int f = 0; f < 32; f++) {
            int col = f * 8 + q4 * 2;
            __half2 h0 = __floats2half2_rn(o[f][0] * il0, o[f][1] * il0);
            __half2 h1 = __floats2half2_rn(o[f][2] * il1, o[f][3] * il1);
            *(__half2*)(obase + (size_t)row_m * NQ + col) = h0;
            *(__half2*)(obase + (size_t)(row_m + 8) * NQ + col) = h1;
        }
        __syncthreads();
    }
}

// ---------------- launch -------------------------------------------------------
extern "C" void kernel_launch(void* const* d_in, const int* in_sizes, int n_in,
                              void* d_out, int out_size)
{
    const float* x   = (const float*)d_in[0];
    const float* Wq  = (const float*)d_in[1];
    const float* Wk  = (const float*)d_in[2];
    const float* Wv  = (const float*)d_in[3];
    const float* Wo  = (const float*)d_in[4];
    const float* qsc = (const float*)d_in[5];
    const float* ksc = (const float*)d_in[6];
    float* out = (float*)d_out;

    void *pqkv, *pxh, *pqh, *pkh, *paoh, *pwfh, *pwoh;
    cudaGetSymbolAddress(&pqkv, g_qkvh);
    cudaGetSymbolAddress(&pxh, g_xh);
    cudaGetSymbolAddress(&pqh, g_qh);
    cudaGetSymbolAddress(&pkh, g_kh);
    cudaGetSymbolAddress(&paoh, g_aoh);
    cudaGetSymbolAddress(&pwfh, g_wfhi);
    cudaGetSymbolAddress(&pwoh, g_wohi);

    __half* qkvh = (__half*)pqkv;
    __half* xh  = (__half*)pxh;
    __half* qh  = (__half*)pqh;
    __half* kh  = (__half*)pkh;
    __half* aoh = (__half*)paoh;
    __half* wfh = (__half*)pwfh;
    __half* woh = (__half*)pwoh;

    size_t gemm_smem = 2 * STAGEK;  // 73728
    cudaFuncSetAttribute(mma_gemm64_kernel<float>,
                         cudaFuncAttributeMaxDynamicSharedMemorySize, (int)gemm_smem);
    cudaFuncSetAttribute(mma_gemm64_kernel<__half>,
                         cudaFuncAttributeMaxDynamicSharedMemorySize, (int)gemm_smem);
    cudaFuncSetAttribute(attn_fa2_kernel,
                         cudaFuncAttributeMaxDynamicSharedMemorySize, N_TOT);

    // ---- operand prep ----
    {
        int n4 = (MROWS * Dd) / 4;
        tohalf_kernel<<<(n4 + 255) / 256, 256>>>((const float4*)x, xh, n4);
        transpose_half_kernel<<<dim3(NQ / 32, Dd / 32), 256>>>(Wq, wfh, Dd, NQ);
        transpose_half_kernel<<<dim3(NKV / 32, Dd / 32), 256>>>(
            Wk, wfh + (size_t)NQ * Dd, Dd, NKV);
        transpose_half_kernel<<<dim3(NKV / 32, Dd / 32), 256>>>(
            Wv, wfh + (size_t)(NQ + NKV) * Dd, Dd, NKV);
        transpose_half_kernel<<<dim3(Dd / 32, NQ / 32), 256>>>(Wo, woh, NQ, Dd);
    }

    // ---- merged QKV projection (fp16 out, BK=64) ----
    mma_gemm64_kernel<__half><<<dim3(NQKV / 128, MROWS / 128), 256, gemm_smem>>>(
        xh, wfh, qkvh, MROWS, NQKV, Dd);

    // ---- qk-norm -> fp16 (warp-per-row; V stays in-place) ----
    rmsnorm_qk_kernel<<<MROWS * 12 / 8, 256>>>(qkvh, qsc, ksc, qh, kh);

    // ---- attention (persistent FA2) ----
    zero_ctr_kernel<<<1, 1>>>();
    attn_fa2_kernel<<<152, 256, N_TOT>>>();

    // ---- output projection (fp32 out, BK=64) ----
    mma_gemm64_kernel<float><<<dim3(Dd / 128, MROWS / 128), 256, gemm_smem>>>(
        aoh, woh, out, MROWS, Dd, NQ);
}